// round 1
// baseline (speedup 1.0000x reference)
#include <cuda_runtime.h>
#include <math.h>

#define T_LEN 2048
#define H_HEADS 16
#define KHN 2
#define GQ 8
#define DDIM 128
#define NCMP 127
#define NBLK 32
#define SCALE_F 0.08838834765f
#define NEG_INF (-INFINITY)

// ---------------- scratch (static device memory; no allocation) ----------------
__device__ float g_cmp_k[KHN][NCMP][DDIM];
__device__ float g_cmp_v[KHN][NCMP][DDIM];
__device__ float g_ocmp[T_LEN][H_HEADS][DDIM];
__device__ unsigned g_sel[T_LEN][KHN];

// ---------------- K1: compressed K/V (windowed means) ----------------
__global__ void k1_compress(const float* __restrict__ k, const float* __restrict__ v) {
    int j  = blockIdx.x;      // 0..126
    int kh = blockIdx.y;      // 0..1
    int d  = threadIdx.x;     // 0..127
    int s  = j * 16;
    float sk = 0.f, sv = 0.f;
#pragma unroll 8
    for (int i = 0; i < 32; i++) {
        sk += k[((size_t)(s + i) * KHN + kh) * DDIM + d];
        sv += v[((size_t)(s + i) * KHN + kh) * DDIM + d];
    }
    g_cmp_k[kh][j][d] = sk * (1.f / 32.f);
    g_cmp_v[kh][j][d] = sv * (1.f / 32.f);
}

// ---------------- K2: compressed attention + block scores + top-16 selection ----------------
__global__ __launch_bounds__(128) void k2_cmp_attn(const float* __restrict__ q) {
    int t   = blockIdx.x;
    int kh  = blockIdx.y;
    int tid = threadIdx.x;
    int lane = tid & 31, wrp = tid >> 5;

    __shared__ float4 q_sh[GQ * 32];
    __shared__ float  lg[GQ][NCMP];
    __shared__ float  psum[NCMP];
    __shared__ float  l_sh[GQ];
    __shared__ float  blk[NBLK];

    for (int i = tid; i < GQ * 32; i += 128)
        q_sh[i] = reinterpret_cast<const float4*>(q)[(size_t)(t * H_HEADS + kh * GQ) * 32 + i];
    if (tid < NCMP) psum[tid] = 0.f;

    int n_valid = (t >= 31) ? ((t - 31) / 16 + 1) : 0;
    if (n_valid > NCMP) n_valid = NCMP;
    __syncthreads();

    if (n_valid > 0) {
        // logits: warp-cooperative dots, coalesced cmp_k reads (L1-resident)
        for (int g = 0; g < GQ; g++) {
            for (int j = wrp; j < n_valid; j += 4) {
                const float4* kr = reinterpret_cast<const float4*>(g_cmp_k[kh][j]);
                float4 a = q_sh[g * 32 + lane];
                float4 b = kr[lane];
                float s = a.x * b.x + a.y * b.y + a.z * b.z + a.w * b.w;
                for (int o = 16; o; o >>= 1) s += __shfl_xor_sync(0xffffffffu, s, o);
                if (lane == 0) lg[g][j] = s * SCALE_F;
            }
        }
        __syncthreads();
        // per-g softmax (accurate expf: selection is tie-sensitive)
        for (int g = wrp; g < GQ; g += 4) {
            float m = NEG_INF;
            for (int j = lane; j < n_valid; j += 32) m = fmaxf(m, lg[g][j]);
            for (int o = 16; o; o >>= 1) m = fmaxf(m, __shfl_xor_sync(0xffffffffu, m, o));
            float sum = 0.f;
            for (int j = lane; j < n_valid; j += 32) {
                float e = expf(lg[g][j] - m);
                lg[g][j] = e;
                sum += e;
            }
            for (int o = 16; o; o >>= 1) sum += __shfl_xor_sync(0xffffffffu, sum, o);
            if (lane == 0) l_sh[g] = sum;
        }
        __syncthreads();
        // group-summed probabilities for block scores
        if (tid < n_valid) {
            float s = 0.f;
#pragma unroll
            for (int g = 0; g < GQ; g++) s += lg[g][tid] / l_sh[g];
            psum[tid] = s;
        }
        // o_cmp: thread = d; v row loaded once, used for all 8 heads
        {
            float acc[GQ];
#pragma unroll
            for (int g = 0; g < GQ; g++) acc[g] = 0.f;
            for (int j = 0; j < n_valid; j++) {
                float vv = g_cmp_v[kh][j][tid];
#pragma unroll
                for (int g = 0; g < GQ; g++) acc[g] += lg[g][j] * vv;
            }
#pragma unroll
            for (int g = 0; g < GQ; g++)
                g_ocmp[t][kh * GQ + g][tid] = acc[g] / l_sh[g];
        }
    } else {
#pragma unroll
        for (int g = 0; g < GQ; g++) g_ocmp[t][kh * GQ + g][tid] = 0.f;
    }
    __syncthreads();

    // blk_score[b] = sum of psum over windows j in [4b-1, 4b+3]
    if (tid < NBLK) {
        int b = tid;
        int jlo = 4 * b - 1; if (jlo < 0) jlo = 0;
        int jhi = 4 * b + 3; if (jhi > n_valid - 1) jhi = n_valid - 1;
        float s = 0.f;
        for (int j = jlo; j <= jhi; j++) s += psum[j];
        blk[b] = s;
    }
    __syncthreads();

    // top-16 selection: value desc, lowest index first (matches jax.lax.top_k)
    if (tid < 32) {
        int b = tid;
        int t_blk = t >> 6;
        bool forced = (b < 1) || ((b <= t_blk) && (b >= t_blk - 1)); // init=1, local=2
        bool valid  = (b * 64 <= t);
        float sc = forced ? 1e30f : blk[b];
        sc = valid ? sc : -1e30f;
        unsigned sel = 0u;
        for (int it = 0; it < 16; it++) {
            float vcur = ((sel >> b) & 1u) ? NEG_INF : sc;
            float m = vcur;
            for (int o = 16; o; o >>= 1) m = fmaxf(m, __shfl_xor_sync(0xffffffffu, m, o));
            unsigned ball = __ballot_sync(0xffffffffu, vcur == m);
            int winb = __ffs(ball) - 1;
            sel |= (1u << winb);
        }
        if (tid == 0) g_sel[t][kh] = sel;
    }
}

// ---------------- K3: fused selected + window attention + gated combine ----------------
__global__ __launch_bounds__(128) void k3_main(
    const float* __restrict__ q, const float* __restrict__ k,
    const float* __restrict__ v, const float* __restrict__ w,
    float* __restrict__ out)
{
    int t   = blockIdx.x;
    int kh  = blockIdx.y;
    int tid = threadIdx.x;
    int g   = tid >> 4;     // QK-phase head
    int jl  = tid & 15;     // QK-phase base key index within chunk

    __shared__ float4 q_sh[GQ * 33];      // padded row stride 33 float4
    __shared__ float4 k_sh[64 * 33];
    __shared__ float4 es4[64 * 2];        // p (unnormalized) for selected path, [j][8]
    __shared__ float4 ew4[64 * 2];        // p for window path
    __shared__ float  m_s[GQ], c_s[GQ], l_s[GQ];
    __shared__ float  m_w[GQ], c_w[GQ], l_w[GQ];

    for (int i = tid; i < GQ * 32; i += 128) {
        int gg = i >> 5, d4 = i & 31;
        q_sh[gg * 33 + d4] =
            reinterpret_cast<const float4*>(q)[(size_t)(t * H_HEADS + kh * GQ) * 32 + i];
    }
    if (tid < GQ) {
        m_s[tid] = NEG_INF; l_s[tid] = 0.f;
        m_w[tid] = NEG_INF; l_w[tid] = 0.f;
    }
    unsigned selm = g_sel[t][kh];
    int t_blk = t >> 6;
    float accs[GQ], accw[GQ];
#pragma unroll
    for (int i = 0; i < GQ; i++) { accs[i] = 0.f; accw[i] = 0.f; }
    __syncthreads();

    for (int b = 0; b <= t_blk; b++) {
        bool sel_b = (selm >> b) & 1u;
        bool win_b = (b * 64 + 63 >= t - 511);
        if (!sel_b && !win_b) continue;

        // stage K chunk (coalesced float4)
        for (int i = tid; i < 64 * 32; i += 128) {
            int j = i >> 5, d4 = i & 31;
            int jg = b * 64 + j;
            k_sh[j * 33 + d4] =
                reinterpret_cast<const float4*>(k)[(size_t)(jg * KHN + kh) * 32 + d4];
        }
        __syncthreads();

        // QK: 4 dots per thread (head g, keys jl, jl+16, jl+32, jl+48)
        float lgv[4]; bool wm[4];
#pragma unroll
        for (int jj = 0; jj < 4; jj++) {
            int j  = jl + 16 * jj;
            int jg = b * 64 + j;
            float s = 0.f;
#pragma unroll 8
            for (int d4 = 0; d4 < 32; d4++) {
                float4 a  = q_sh[g * 33 + d4];
                float4 bb = k_sh[j * 33 + d4];
                s += a.x * bb.x + a.y * bb.y + a.z * bb.z + a.w * bb.w;
            }
            bool causal = (jg <= t);
            lgv[jj] = causal ? s * SCALE_F : NEG_INF;
            wm[jj]  = causal && (t - jg < 512);
        }
        // chunk maxima (16-lane group reduce per head)
        float mcs = NEG_INF, mcw = NEG_INF;
#pragma unroll
        for (int jj = 0; jj < 4; jj++) {
            mcs = fmaxf(mcs, lgv[jj]);
            if (wm[jj]) mcw = fmaxf(mcw, lgv[jj]);
        }
        for (int o = 8; o; o >>= 1) {
            mcs = fmaxf(mcs, __shfl_xor_sync(0xffffffffu, mcs, o, 16));
            mcw = fmaxf(mcw, __shfl_xor_sync(0xffffffffu, mcw, o, 16));
        }
        if (jl == 0) {
            if (sel_b) {
                float mn = fmaxf(m_s[g], mcs);
                float c  = __expf(m_s[g] - mn);
                c_s[g] = c; m_s[g] = mn; l_s[g] *= c;
            } else c_s[g] = 1.f;
            if (win_b) {
                float mn = fmaxf(m_w[g], mcw);
                float c  = __expf(m_w[g] - mn);
                c_w[g] = c; m_w[g] = mn; l_w[g] *= c;
            } else c_w[g] = 1.f;
        }
        __syncthreads();

        // exp + row sums
        float ss = 0.f, sw = 0.f;
        float ms = m_s[g], mw = m_w[g];
        float* esf = reinterpret_cast<float*>(es4);
        float* ewf = reinterpret_cast<float*>(ew4);
#pragma unroll
        for (int jj = 0; jj < 4; jj++) {
            int j = jl + 16 * jj;
            if (sel_b) {
                float e = __expf(lgv[jj] - ms);   // -INF -> 0 exactly
                esf[j * 8 + g] = e; ss += e;
            }
            if (win_b) {
                float e = wm[jj] ? __expf(lgv[jj] - mw) : 0.f;
                ewf[j * 8 + g] = e; sw += e;
            }
        }
        for (int o = 8; o; o >>= 1) {
            ss += __shfl_xor_sync(0xffffffffu, ss, o, 16);
            sw += __shfl_xor_sync(0xffffffffu, sw, o, 16);
        }
        if (jl == 0) {
            if (sel_b) l_s[g] += ss;
            if (win_b) l_w[g] += sw;
        }
        __syncthreads();

        // PV: thread = output dim d; v row shared across 8 heads & both paths
        if (sel_b) {
#pragma unroll
            for (int gg = 0; gg < GQ; gg++) accs[gg] *= c_s[gg];
        }
        if (win_b) {
#pragma unroll
            for (int gg = 0; gg < GQ; gg++) accw[gg] *= c_w[gg];
        }
        int jmax = t - b * 64; if (jmax > 63) jmax = 63;
        for (int j = 0; j <= jmax; j++) {
            float vv = v[(size_t)((b * 64 + j) * KHN + kh) * DDIM + tid];
            if (sel_b) {
                float4 e0 = es4[j * 2], e1 = es4[j * 2 + 1];
                accs[0] += e0.x * vv; accs[1] += e0.y * vv;
                accs[2] += e0.z * vv; accs[3] += e0.w * vv;
                accs[4] += e1.x * vv; accs[5] += e1.y * vv;
                accs[6] += e1.z * vv; accs[7] += e1.w * vv;
            }
            if (win_b) {
                float4 e0 = ew4[j * 2], e1 = ew4[j * 2 + 1];
                accw[0] += e0.x * vv; accw[1] += e0.y * vv;
                accw[2] += e0.z * vv; accw[3] += e0.w * vv;
                accw[4] += e1.x * vv; accw[5] += e1.y * vv;
                accw[6] += e1.z * vv; accw[7] += e1.w * vv;
            }
        }
        __syncthreads();
    }

    // epilogue: o = w0*o_cmp + w1*o_slc + w2*o_win
#pragma unroll
    for (int gg = 0; gg < GQ; gg++) {
        int h = kh * GQ + gg;
        float os = accs[gg] / l_s[gg];   // block 0 always selected -> l_s >= 1
        float ow = accw[gg] / l_w[gg];   // j = t always in window  -> l_w >= 1
        float w0 = w[(size_t)(t * H_HEADS + h) * 3 + 0];
        float w1 = w[(size_t)(t * H_HEADS + h) * 3 + 1];
        float w2 = w[(size_t)(t * H_HEADS + h) * 3 + 2];
        float oc = g_ocmp[t][h][tid];
        out[(size_t)(t * H_HEADS + h) * DDIM + tid] = w0 * oc + w1 * os + w2 * ow;
    }
}

// ---------------- launch ----------------
extern "C" void kernel_launch(void* const* d_in, const int* in_sizes, int n_in,
                              void* d_out, int out_size) {
    const float* q = (const float*)d_in[0];
    const float* k = (const float*)d_in[1];
    const float* v = (const float*)d_in[2];
    const float* w = (const float*)d_in[3];
    float* out = (float*)d_out;

    k1_compress<<<dim3(NCMP, KHN), DDIM>>>(k, v);
    k2_cmp_attn<<<dim3(T_LEN, KHN), 128>>>(q);
    k3_main<<<dim3(T_LEN, KHN), 128>>>(q, k, v, w, out);
}

// round 2
// speedup vs baseline: 1.0015x; 1.0015x over previous
#include <cuda_runtime.h>
#include <math.h>

#define T_LEN 2048
#define H_HEADS 16
#define KHN 2
#define GQ 8
#define DDIM 128
#define NCMP 127
#define NBLK 32
#define SCALE_F 0.08838834765f
#define NEG_INF (-INFINITY)

// ---------------- scratch (static device memory; no allocation) ----------------
__device__ float g_cmp_k[KHN][NCMP][DDIM];
__device__ float g_cmp_v[KHN][NCMP][DDIM];
__device__ float g_ocmp[T_LEN][H_HEADS][DDIM];
__device__ unsigned g_sel[T_LEN][KHN];

// ---------------- K1: compressed K/V (windowed means) ----------------
__global__ void k1_compress(const float* __restrict__ k, const float* __restrict__ v) {
    int j  = blockIdx.x;      // 0..126
    int kh = blockIdx.y;      // 0..1
    int d  = threadIdx.x;     // 0..127
    int s  = j * 16;
    float sk = 0.f, sv = 0.f;
#pragma unroll 8
    for (int i = 0; i < 32; i++) {
        sk += k[((size_t)(s + i) * KHN + kh) * DDIM + d];
        sv += v[((size_t)(s + i) * KHN + kh) * DDIM + d];
    }
    g_cmp_k[kh][j][d] = sk * (1.f / 32.f);
    g_cmp_v[kh][j][d] = sv * (1.f / 32.f);
}

// ---------------- K2: compressed attention + block scores + top-16 selection ----------------
__global__ __launch_bounds__(128) void k2_cmp_attn(const float* __restrict__ q) {
    int t   = blockIdx.x;
    int kh  = blockIdx.y;
    int tid = threadIdx.x;
    int lane = tid & 31, wrp = tid >> 5;

    __shared__ float4 q_sh[GQ * 32];
    __shared__ float  lg[GQ][NCMP];
    __shared__ float  psum[NCMP];
    __shared__ float  l_sh[GQ];
    __shared__ float  blk[NBLK];

    for (int i = tid; i < GQ * 32; i += 128)
        q_sh[i] = reinterpret_cast<const float4*>(q)[(size_t)(t * H_HEADS + kh * GQ) * 32 + i];
    if (tid < NCMP) psum[tid] = 0.f;

    int n_valid = (t >= 31) ? ((t - 31) / 16 + 1) : 0;
    if (n_valid > NCMP) n_valid = NCMP;
    __syncthreads();

    if (n_valid > 0) {
        // logits: warp-cooperative dots, coalesced cmp_k reads (L1-resident)
        for (int g = 0; g < GQ; g++) {
            for (int j = wrp; j < n_valid; j += 4) {
                const float4* kr = reinterpret_cast<const float4*>(g_cmp_k[kh][j]);
                float4 a = q_sh[g * 32 + lane];
                float4 b = kr[lane];
                float s = a.x * b.x + a.y * b.y + a.z * b.z + a.w * b.w;
                for (int o = 16; o; o >>= 1) s += __shfl_xor_sync(0xffffffffu, s, o);
                if (lane == 0) lg[g][j] = s * SCALE_F;
            }
        }
        __syncthreads();
        // per-g softmax (accurate expf: selection is tie-sensitive)
        for (int g = wrp; g < GQ; g += 4) {
            float m = NEG_INF;
            for (int j = lane; j < n_valid; j += 32) m = fmaxf(m, lg[g][j]);
            for (int o = 16; o; o >>= 1) m = fmaxf(m, __shfl_xor_sync(0xffffffffu, m, o));
            float sum = 0.f;
            for (int j = lane; j < n_valid; j += 32) {
                float e = expf(lg[g][j] - m);
                lg[g][j] = e;
                sum += e;
            }
            for (int o = 16; o; o >>= 1) sum += __shfl_xor_sync(0xffffffffu, sum, o);
            if (lane == 0) l_sh[g] = sum;
        }
        __syncthreads();
        // group-summed probabilities for block scores
        if (tid < n_valid) {
            float s = 0.f;
#pragma unroll
            for (int g = 0; g < GQ; g++) s += lg[g][tid] / l_sh[g];
            psum[tid] = s;
        }
        // o_cmp: thread = d; v row loaded once, used for all 8 heads
        {
            float acc[GQ];
#pragma unroll
            for (int g = 0; g < GQ; g++) acc[g] = 0.f;
            for (int j = 0; j < n_valid; j++) {
                float vv = g_cmp_v[kh][j][tid];
#pragma unroll
                for (int g = 0; g < GQ; g++) acc[g] += lg[g][j] * vv;
            }
#pragma unroll
            for (int g = 0; g < GQ; g++)
                g_ocmp[t][kh * GQ + g][tid] = acc[g] / l_sh[g];
        }
    } else {
#pragma unroll
        for (int g = 0; g < GQ; g++) g_ocmp[t][kh * GQ + g][tid] = 0.f;
    }
    __syncthreads();

    // blk_score[b] = sum of psum over windows j in [4b-1, 4b+3]
    if (tid < NBLK) {
        int b = tid;
        int jlo = 4 * b - 1; if (jlo < 0) jlo = 0;
        int jhi = 4 * b + 3; if (jhi > n_valid - 1) jhi = n_valid - 1;
        float s = 0.f;
        for (int j = jlo; j <= jhi; j++) s += psum[j];
        blk[b] = s;
    }
    __syncthreads();

    // top-16 selection: value desc, lowest index first (matches jax.lax.top_k)
    if (tid < 32) {
        int b = tid;
        int t_blk = t >> 6;
        bool forced = (b < 1) || ((b <= t_blk) && (b >= t_blk - 1)); // init=1, local=2
        bool valid  = (b * 64 <= t);
        float sc = forced ? 1e30f : blk[b];
        sc = valid ? sc : -1e30f;
        unsigned sel = 0u;
        for (int it = 0; it < 16; it++) {
            float vcur = ((sel >> b) & 1u) ? NEG_INF : sc;
            float m = vcur;
            for (int o = 16; o; o >>= 1) m = fmaxf(m, __shfl_xor_sync(0xffffffffu, m, o));
            unsigned ball = __ballot_sync(0xffffffffu, vcur == m);
            int winb = __ffs(ball) - 1;
            sel |= (1u << winb);
        }
        if (tid == 0) g_sel[t][kh] = sel;
    }
}

// ---------------- K3: fused selected + window attention + gated combine ----------------
__global__ __launch_bounds__(128) void k3_main(
    const float* __restrict__ q, const float* __restrict__ k,
    const float* __restrict__ v, const float* __restrict__ w,
    float* __restrict__ out)
{
    int t   = blockIdx.x;
    int kh  = blockIdx.y;
    int tid = threadIdx.x;
    int g   = tid >> 4;     // QK-phase head
    int jl  = tid & 15;     // QK-phase base key index within chunk

    __shared__ float4 q_sh[GQ * 33];      // padded row stride 33 float4
    __shared__ float4 k_sh[64 * 33];
    __shared__ float4 es4[64 * 2];        // p (unnormalized) for selected path, [j][8]
    __shared__ float4 ew4[64 * 2];        // p for window path
    __shared__ float  m_s[GQ], c_s[GQ], l_s[GQ];
    __shared__ float  m_w[GQ], c_w[GQ], l_w[GQ];

    for (int i = tid; i < GQ * 32; i += 128) {
        int gg = i >> 5, d4 = i & 31;
        q_sh[gg * 33 + d4] =
            reinterpret_cast<const float4*>(q)[(size_t)(t * H_HEADS + kh * GQ) * 32 + i];
    }
    if (tid < GQ) {
        m_s[tid] = NEG_INF; l_s[tid] = 0.f;
        m_w[tid] = NEG_INF; l_w[tid] = 0.f;
    }
    unsigned selm = g_sel[t][kh];
    int t_blk = t >> 6;
    float accs[GQ], accw[GQ];
#pragma unroll
    for (int i = 0; i < GQ; i++) { accs[i] = 0.f; accw[i] = 0.f; }
    __syncthreads();

    for (int b = 0; b <= t_blk; b++) {
        bool sel_b = (selm >> b) & 1u;
        bool win_b = (b * 64 + 63 >= t - 511);
        if (!sel_b && !win_b) continue;

        // stage K chunk (coalesced float4)
        for (int i = tid; i < 64 * 32; i += 128) {
            int j = i >> 5, d4 = i & 31;
            int jg = b * 64 + j;
            k_sh[j * 33 + d4] =
                reinterpret_cast<const float4*>(k)[(size_t)(jg * KHN + kh) * 32 + d4];
        }
        __syncthreads();

        // QK: 4 dots per thread (head g, keys jl, jl+16, jl+32, jl+48)
        float lgv[4]; bool wm[4];
#pragma unroll
        for (int jj = 0; jj < 4; jj++) {
            int j  = jl + 16 * jj;
            int jg = b * 64 + j;
            float s = 0.f;
#pragma unroll 8
            for (int d4 = 0; d4 < 32; d4++) {
                float4 a  = q_sh[g * 33 + d4];
                float4 bb = k_sh[j * 33 + d4];
                s += a.x * bb.x + a.y * bb.y + a.z * bb.z + a.w * bb.w;
            }
            bool causal = (jg <= t);
            lgv[jj] = causal ? s * SCALE_F : NEG_INF;
            wm[jj]  = causal && (t - jg < 512);
        }
        // chunk maxima (16-lane group reduce per head)
        float mcs = NEG_INF, mcw = NEG_INF;
#pragma unroll
        for (int jj = 0; jj < 4; jj++) {
            mcs = fmaxf(mcs, lgv[jj]);
            if (wm[jj]) mcw = fmaxf(mcw, lgv[jj]);
        }
        for (int o = 8; o; o >>= 1) {
            mcs = fmaxf(mcs, __shfl_xor_sync(0xffffffffu, mcs, o, 16));
            mcw = fmaxf(mcw, __shfl_xor_sync(0xffffffffu, mcw, o, 16));
        }
        if (jl == 0) {
            if (sel_b) {
                float mn = fmaxf(m_s[g], mcs);
                float c  = __expf(m_s[g] - mn);
                c_s[g] = c; m_s[g] = mn; l_s[g] *= c;
            } else c_s[g] = 1.f;
            if (win_b) {
                float mn = fmaxf(m_w[g], mcw);
                float c  = __expf(m_w[g] - mn);
                c_w[g] = c; m_w[g] = mn; l_w[g] *= c;
            } else c_w[g] = 1.f;
        }
        __syncthreads();

        // exp + row sums
        float ss = 0.f, sw = 0.f;
        float ms = m_s[g], mw = m_w[g];
        float* esf = reinterpret_cast<float*>(es4);
        float* ewf = reinterpret_cast<float*>(ew4);
#pragma unroll
        for (int jj = 0; jj < 4; jj++) {
            int j = jl + 16 * jj;
            if (sel_b) {
                float e = __expf(lgv[jj] - ms);   // -INF -> 0 exactly
                esf[j * 8 + g] = e; ss += e;
            }
            if (win_b) {
                float e = wm[jj] ? __expf(lgv[jj] - mw) : 0.f;
                ewf[j * 8 + g] = e; sw += e;
            }
        }
        for (int o = 8; o; o >>= 1) {
            ss += __shfl_xor_sync(0xffffffffu, ss, o, 16);
            sw += __shfl_xor_sync(0xffffffffu, sw, o, 16);
        }
        if (jl == 0) {
            if (sel_b) l_s[g] += ss;
            if (win_b) l_w[g] += sw;
        }
        __syncthreads();

        // PV: thread = output dim d; v row shared across 8 heads & both paths
        if (sel_b) {
#pragma unroll
            for (int gg = 0; gg < GQ; gg++) accs[gg] *= c_s[gg];
        }
        if (win_b) {
#pragma unroll
            for (int gg = 0; gg < GQ; gg++) accw[gg] *= c_w[gg];
        }
        int jmax = t - b * 64; if (jmax > 63) jmax = 63;
        for (int j = 0; j <= jmax; j++) {
            float vv = v[(size_t)((b * 64 + j) * KHN + kh) * DDIM + tid];
            if (sel_b) {
                float4 e0 = es4[j * 2], e1 = es4[j * 2 + 1];
                accs[0] += e0.x * vv; accs[1] += e0.y * vv;
                accs[2] += e0.z * vv; accs[3] += e0.w * vv;
                accs[4] += e1.x * vv; accs[5] += e1.y * vv;
                accs[6] += e1.z * vv; accs[7] += e1.w * vv;
            }
            if (win_b) {
                float4 e0 = ew4[j * 2], e1 = ew4[j * 2 + 1];
                accw[0] += e0.x * vv; accw[1] += e0.y * vv;
                accw[2] += e0.z * vv; accw[3] += e0.w * vv;
                accw[4] += e1.x * vv; accw[5] += e1.y * vv;
                accw[6] += e1.z * vv; accw[7] += e1.w * vv;
            }
        }
        __syncthreads();
    }

    // epilogue: o = w0*o_cmp + w1*o_slc + w2*o_win
#pragma unroll
    for (int gg = 0; gg < GQ; gg++) {
        int h = kh * GQ + gg;
        float os = accs[gg] / l_s[gg];   // block 0 always selected -> l_s >= 1
        float ow = accw[gg] / l_w[gg];   // j = t always in window  -> l_w >= 1
        float w0 = w[(size_t)(t * H_HEADS + h) * 3 + 0];
        float w1 = w[(size_t)(t * H_HEADS + h) * 3 + 1];
        float w2 = w[(size_t)(t * H_HEADS + h) * 3 + 2];
        float oc = g_ocmp[t][h][tid];
        out[(size_t)(t * H_HEADS + h) * DDIM + tid] = w0 * oc + w1 * os + w2 * ow;
    }
}

// ---------------- launch ----------------
extern "C" void kernel_launch(void* const* d_in, const int* in_sizes, int n_in,
                              void* d_out, int out_size) {
    const float* q = (const float*)d_in[0];
    const float* k = (const float*)d_in[1];
    const float* v = (const float*)d_in[2];
    const float* w = (const float*)d_in[3];
    float* out = (float*)d_out;

    k1_compress<<<dim3(NCMP, KHN), DDIM>>>(k, v);
    k2_cmp_attn<<<dim3(T_LEN, KHN), 128>>>(q);
    k3_main<<<dim3(T_LEN, KHN), 128>>>(q, k, v, w, out);
}

// round 4
// speedup vs baseline: 2.3835x; 2.3799x over previous
#include <cuda_runtime.h>
#include <cuda_bf16.h>
#include <math.h>
#include <stdint.h>

#define T_LEN 2048
#define H_HEADS 16
#define KHN 2
#define GQ 8
#define DDIM 128
#define NCMP 127
#define NBLK 32
#define TQ 16
#define SCALE_F 0.08838834765f
#define NEG_INF (-INFINITY)

// ---------------- scratch ----------------
__device__ float g_cmp_k[KHN][NCMP][DDIM];
__device__ float g_cmp_v[KHN][NCMP][DDIM];
__device__ float g_ocmp[T_LEN][H_HEADS][DDIM];
__device__ unsigned g_sel[T_LEN][KHN];
__device__ unsigned g_kmax[KHN];   // float-bits; atomicMax idempotent across replays

// ---------------- helpers ----------------
__device__ __forceinline__ uint32_t smem_u32(const void* p) {
    uint32_t a;
    asm("{ .reg .u64 t; cvta.to.shared.u64 t, %1; cvt.u32.u64 %0, t; }" : "=r"(a) : "l"(p));
    return a;
}
__device__ __forceinline__ void mma16816(float* d, const uint32_t* a, uint32_t b0, uint32_t b1) {
    asm volatile("mma.sync.aligned.m16n8k16.row.col.f32.bf16.bf16.f32 "
        "{%0,%1,%2,%3},{%4,%5,%6,%7},{%8,%9},{%0,%1,%2,%3};"
        : "+f"(d[0]), "+f"(d[1]), "+f"(d[2]), "+f"(d[3])
        : "r"(a[0]), "r"(a[1]), "r"(a[2]), "r"(a[3]), "r"(b0), "r"(b1));
}
__device__ __forceinline__ void ldsm4(uint32_t* r, uint32_t addr) {
    asm volatile("ldmatrix.sync.aligned.m8n8.x4.shared.b16 {%0,%1,%2,%3}, [%4];"
        : "=r"(r[0]), "=r"(r[1]), "=r"(r[2]), "=r"(r[3]) : "r"(addr));
}
__device__ __forceinline__ void ldsm4t(uint32_t* r, uint32_t addr) {
    asm volatile("ldmatrix.sync.aligned.m8n8.x4.trans.shared.b16 {%0,%1,%2,%3}, [%4];"
        : "=r"(r[0]), "=r"(r[1]), "=r"(r[2]), "=r"(r[3]) : "r"(addr));
}
// bf16 hi/lo split of a float pair -> packed words (lo 16 bits = first elem)
__device__ __forceinline__ uint32_t pack2(float a, float b, uint32_t& lo) {
    __nv_bfloat16 ah = __float2bfloat16_rn(a), bh = __float2bfloat16_rn(b);
    __nv_bfloat16 al = __float2bfloat16_rn(a - __bfloat162float(ah));
    __nv_bfloat16 bl = __float2bfloat16_rn(b - __bfloat162float(bh));
    lo = ((uint32_t)__bfloat16_as_ushort(bl) << 16) | (uint32_t)__bfloat16_as_ushort(al);
    return ((uint32_t)__bfloat16_as_ushort(bh) << 16) | (uint32_t)__bfloat16_as_ushort(ah);
}

// ---------------- K1: compressed K/V ----------------
__global__ void k1_compress(const float* __restrict__ k, const float* __restrict__ v) {
    int j = blockIdx.x, kh = blockIdx.y, d = threadIdx.x;
    int s = j * 16;
    float sk = 0.f, sv = 0.f;
#pragma unroll 8
    for (int i = 0; i < 32; i++) {
        sk += k[((size_t)(s + i) * KHN + kh) * DDIM + d];
        sv += v[((size_t)(s + i) * KHN + kh) * DDIM + d];
    }
    g_cmp_k[kh][j][d] = sk * (1.f / 32.f);
    g_cmp_v[kh][j][d] = sv * (1.f / 32.f);
}

// ---------------- K1b: max ||k_row|| per kv head ----------------
__global__ void k1b_knorm(const float* __restrict__ k) {
    int t = blockIdx.x, kh = blockIdx.y, lane = threadIdx.x;
    const float4* kr = reinterpret_cast<const float4*>(k) + ((size_t)t * KHN + kh) * 32;
    float4 a = kr[lane];
    float s = a.x * a.x + a.y * a.y + a.z * a.z + a.w * a.w;
    for (int o = 16; o; o >>= 1) s += __shfl_xor_sync(0xffffffffu, s, o);
    if (lane == 0) atomicMax(&g_kmax[kh], __float_as_uint(sqrtf(s)));
}

// ---------------- K2: compressed attention + block scores + top-16 ----------------
__global__ __launch_bounds__(128) void k2_cmp_attn(const float* __restrict__ q) {
    int t = blockIdx.x, kh = blockIdx.y, tid = threadIdx.x;
    int lane = tid & 31, wrp = tid >> 5;

    __shared__ float4 q_sh[GQ * 32];
    __shared__ float  lg[GQ][NCMP];
    __shared__ float  psum[NCMP];
    __shared__ float  l_sh[GQ];
    __shared__ float  blk[NBLK];

    for (int i = tid; i < GQ * 32; i += 128)
        q_sh[i] = reinterpret_cast<const float4*>(q)[(size_t)(t * H_HEADS + kh * GQ) * 32 + i];
    if (tid < NCMP) psum[tid] = 0.f;

    int n_valid = (t >= 31) ? ((t - 31) / 16 + 1) : 0;
    if (n_valid > NCMP) n_valid = NCMP;
    __syncthreads();

    if (n_valid > 0) {
        for (int g = 0; g < GQ; g++) {
            for (int j = wrp; j < n_valid; j += 4) {
                const float4* kr = reinterpret_cast<const float4*>(g_cmp_k[kh][j]);
                float4 a = q_sh[g * 32 + lane];
                float4 b = kr[lane];
                float s = a.x * b.x + a.y * b.y + a.z * b.z + a.w * b.w;
                for (int o = 16; o; o >>= 1) s += __shfl_xor_sync(0xffffffffu, s, o);
                if (lane == 0) lg[g][j] = s * SCALE_F;
            }
        }
        __syncthreads();
        for (int g = wrp; g < GQ; g += 4) {
            float m = NEG_INF;
            for (int j = lane; j < n_valid; j += 32) m = fmaxf(m, lg[g][j]);
            for (int o = 16; o; o >>= 1) m = fmaxf(m, __shfl_xor_sync(0xffffffffu, m, o));
            float sum = 0.f;
            for (int j = lane; j < n_valid; j += 32) {
                float e = expf(lg[g][j] - m);
                lg[g][j] = e; sum += e;
            }
            for (int o = 16; o; o >>= 1) sum += __shfl_xor_sync(0xffffffffu, sum, o);
            if (lane == 0) l_sh[g] = sum;
        }
        __syncthreads();
        if (tid < n_valid) {
            float s = 0.f;
#pragma unroll
            for (int g = 0; g < GQ; g++) s += lg[g][tid] / l_sh[g];
            psum[tid] = s;
        }
        {
            float acc[GQ];
#pragma unroll
            for (int g = 0; g < GQ; g++) acc[g] = 0.f;
            for (int j = 0; j < n_valid; j++) {
                float vv = g_cmp_v[kh][j][tid];
#pragma unroll
                for (int g = 0; g < GQ; g++) acc[g] += lg[g][j] * vv;
            }
#pragma unroll
            for (int g = 0; g < GQ; g++)
                g_ocmp[t][kh * GQ + g][tid] = acc[g] / l_sh[g];
        }
    } else {
#pragma unroll
        for (int g = 0; g < GQ; g++) g_ocmp[t][kh * GQ + g][tid] = 0.f;
    }
    __syncthreads();

    if (tid < NBLK) {
        int b = tid;
        int jlo = 4 * b - 1; if (jlo < 0) jlo = 0;
        int jhi = 4 * b + 3; if (jhi > n_valid - 1) jhi = n_valid - 1;
        float s = 0.f;
        for (int j = jlo; j <= jhi; j++) s += psum[j];
        blk[b] = s;
    }
    __syncthreads();

    if (tid < 32) {
        int b = tid;
        int t_blk = t >> 6;
        bool forced = (b < 1) || ((b <= t_blk) && (b >= t_blk - 1));
        bool valid  = (b * 64 <= t);
        float sc = forced ? 1e30f : blk[b];
        sc = valid ? sc : -1e30f;
        unsigned sel = 0u;
        for (int it = 0; it < 16; it++) {
            float vcur = ((sel >> b) & 1u) ? NEG_INF : sc;
            float m = vcur;
            for (int o = 16; o; o >>= 1) m = fmaxf(m, __shfl_xor_sync(0xffffffffu, m, o));
            unsigned ball = __ballot_sync(0xffffffffu, vcur == m);
            int winb = __ffs(ball) - 1;
            sel |= (1u << winb);
        }
        if (tid == 0) g_sel[t][kh] = sel;
    }
}

// ---------------- K3: HMMA (mma.sync) fused slc+win attention ----------------
// smem byte offsets (dynamic, 128KB)
#define SQHI 0
#define SQLO 32768
#define SKHI 65536
#define SKLO 81920
#define SVHI 98304
#define SVLO 114688
#define SMTOT 131072

__global__ __launch_bounds__(256, 1) void k3_main(
    const float* __restrict__ q, const float* __restrict__ k,
    const float* __restrict__ v, const float* __restrict__ w,
    float* __restrict__ out)
{
    extern __shared__ char smem[];
    uint32_t sbb_ = smem_u32(smem);
    int tid = threadIdx.x;
    int wp = tid >> 5, lane = tid & 31;
    int t0 = blockIdx.x * TQ;
    int kh = blockIdx.y;

    const float4* q4 = reinterpret_cast<const float4*>(q);
    const float4* k4 = reinterpret_cast<const float4*>(k);
    const float4* v4 = reinterpret_cast<const float4*>(v);

    // ---- stage Q (hi/lo split, swizzled, row stride 256B) ----
    for (int i = tid; i < 128 * 16; i += 256) {
        int row = i >> 4, c16 = i & 15;
        size_t gidx = ((size_t)((t0 + (row >> 3)) * H_HEADS + kh * GQ + (row & 7))) * 32 + c16 * 2;
        float4 x = q4[gidx], y = q4[gidx + 1];
        uint32_t l0, l1, l2, l3;
        uint32_t h0 = pack2(x.x, x.y, l0), h1 = pack2(x.z, x.w, l1);
        uint32_t h2 = pack2(y.x, y.y, l2), h3 = pack2(y.z, y.w, l3);
        uint32_t off = (uint32_t)row * 256u + (uint32_t)((c16 ^ (row & 7)) << 4);
        *reinterpret_cast<uint4*>(smem + SQHI + off) = make_uint4(h0, h1, h2, h3);
        *reinterpret_cast<uint4*>(smem + SQLO + off) = make_uint4(l0, l1, l2, l3);
    }

    // lane's rows: t_a (frag c0/c1), t_b (c2/c3); head g = lane>>2
    int g = lane >> 2;
    int t_a = t0 + 2 * wp;
    int t_b = t_a + 1;
    int h = kh * GQ + g;

    float kmax = __uint_as_float(g_kmax[kh]);
    float Ua, Ub;
    {
        float s2 = 0.f;
        const float4* qr = q4 + ((size_t)(t_a * H_HEADS + h)) * 32;
#pragma unroll 8
        for (int d4 = 0; d4 < 32; d4++) { float4 a = qr[d4]; s2 += a.x*a.x + a.y*a.y + a.z*a.z + a.w*a.w; }
        Ua = SCALE_F * sqrtf(s2) * kmax;
        s2 = 0.f;
        qr = q4 + ((size_t)(t_b * H_HEADS + h)) * 32;
#pragma unroll 8
        for (int d4 = 0; d4 < 32; d4++) { float4 a = qr[d4]; s2 += a.x*a.x + a.y*a.y + a.z*a.z + a.w*a.w; }
        Ub = SCALE_F * sqrtf(s2) * kmax;
    }

    unsigned selm_a = g_sel[t_a][kh], selm_b = g_sel[t_b][kh];

    __shared__ unsigned s_union;
    if (tid == 0) s_union = 0u;
    __syncthreads();
    if (lane == 0) atomicOr(&s_union, selm_a | selm_b);
    __syncthreads();
    unsigned selu = s_union;

    float Os[16][4], Ow[16][4];
#pragma unroll
    for (int i = 0; i < 16; i++)
#pragma unroll
        for (int c = 0; c < 4; c++) { Os[i][c] = 0.f; Ow[i][c] = 0.f; }
    float sum_sa = 0.f, sum_sb = 0.f, sum_wa = 0.f, sum_wb = 0.f;

    int t_blk = t0 >> 6;
    int jcl = (lane & 3) * 2;

    for (int b = 0; b <= t_blk; b++) {
        bool do_s = (selu >> b) & 1u;
        bool do_w = (b * 64 + 63 >= t0 - 511);
        if (!do_s && !do_w) continue;

        __syncthreads();
        // ---- stage K and V chunk (hi/lo, swizzled) ----
        for (int i = tid; i < 64 * 16; i += 256) {
            int row = i >> 4, c16 = i & 15;
            size_t gidx = ((size_t)((b * 64 + row) * KHN + kh)) * 32 + c16 * 2;
            uint32_t l0, l1, l2, l3;
            float4 x = k4[gidx], y = k4[gidx + 1];
            uint32_t h0 = pack2(x.x, x.y, l0), h1 = pack2(x.z, x.w, l1);
            uint32_t h2 = pack2(y.x, y.y, l2), h3 = pack2(y.z, y.w, l3);
            uint32_t off = (uint32_t)row * 256u + (uint32_t)((c16 ^ (row & 7)) << 4);
            *reinterpret_cast<uint4*>(smem + SKHI + off) = make_uint4(h0, h1, h2, h3);
            *reinterpret_cast<uint4*>(smem + SKLO + off) = make_uint4(l0, l1, l2, l3);
            x = v4[gidx]; y = v4[gidx + 1];
            h0 = pack2(x.x, x.y, l0); h1 = pack2(x.z, x.w, l1);
            h2 = pack2(y.x, y.y, l2); h3 = pack2(y.z, y.w, l3);
            *reinterpret_cast<uint4*>(smem + SVHI + off) = make_uint4(h0, h1, h2, h3);
            *reinterpret_cast<uint4*>(smem + SVLO + off) = make_uint4(l0, l1, l2, l3);
        }
        __syncthreads();

        // ---- Q hi fragments hoisted (32 regs); Q lo loaded on the fly ----
        uint32_t ah[8][4];
        int grp = lane >> 3;
        {
            int row = 16 * wp + (grp & 1) * 8 + (lane & 7);
            uint32_t rbase = (uint32_t)row * 256u, rx = (uint32_t)(row & 7);
#pragma unroll
            for (int kt = 0; kt < 8; kt++) {
                uint32_t c16 = (uint32_t)(kt * 2 + (grp >> 1));
                ldsm4(ah[kt], sbb_ + SQHI + rbase + ((c16 ^ rx) << 4));
            }
        }

#pragma unroll
        for (int np = 0; np < 4; np++) {
            float s0[4] = {0.f, 0.f, 0.f, 0.f}, s1[4] = {0.f, 0.f, 0.f, 0.f};
            {
                int keyq = np * 16 + (grp >> 1) * 8 + (lane & 7);
                uint32_t kb = (uint32_t)keyq * 256u, rxk = (uint32_t)(keyq & 7);
                int rowq = 16 * wp + (grp & 1) * 8 + (lane & 7);
                uint32_t rb = (uint32_t)rowq * 256u, rxq = (uint32_t)(rowq & 7);
#pragma unroll
                for (int kt = 0; kt < 8; kt++) {
                    uint32_t ck = (uint32_t)(kt * 2 + (grp & 1));
                    uint32_t cq = (uint32_t)(kt * 2 + (grp >> 1));
                    uint32_t bh[4], bl[4], alr[4];
                    ldsm4(bh, sbb_ + SKHI + kb + ((ck ^ rxk) << 4));
                    ldsm4(bl, sbb_ + SKLO + kb + ((ck ^ rxk) << 4));
                    ldsm4(alr, sbb_ + SQLO + rb + ((cq ^ rxq) << 4));
                    mma16816(s0, ah[kt], bh[0], bh[1]);
                    mma16816(s1, ah[kt], bh[2], bh[3]);
                    mma16816(s0, ah[kt], bl[0], bl[1]);
                    mma16816(s1, ah[kt], bl[2], bl[3]);
                    mma16816(s0, alr, bh[0], bh[1]);
                    mma16816(s1, alr, bh[2], bh[3]);
                }
            }
            // ---- exp + masks + P fragments ----
            int j0 = b * 64 + np * 16 + jcl;     // s0 cols j0, j0+1 ; s1 cols j0+8, j0+9
            float ea0 = __expf(s0[0] * SCALE_F - Ua);
            float ea1 = __expf(s0[1] * SCALE_F - Ua);
            float eb0 = __expf(s0[2] * SCALE_F - Ub);
            float eb1 = __expf(s0[3] * SCALE_F - Ub);
            float fa0 = __expf(s1[0] * SCALE_F - Ua);
            float fa1 = __expf(s1[1] * SCALE_F - Ua);
            float fb0 = __expf(s1[2] * SCALE_F - Ub);
            float fb1 = __expf(s1[3] * SCALE_F - Ub);
            bool sa = (selm_a >> b) & 1u, sb2 = (selm_b >> b) & 1u;
            int j1 = j0 + 1, j8 = j0 + 8, j9 = j0 + 9;

            float esa0 = (sa  && j0 <= t_a) ? ea0 : 0.f;
            float esa1 = (sa  && j1 <= t_a) ? ea1 : 0.f;
            float esb0 = (sb2 && j0 <= t_b) ? eb0 : 0.f;
            float esb1 = (sb2 && j1 <= t_b) ? eb1 : 0.f;
            float fsa0 = (sa  && j8 <= t_a) ? fa0 : 0.f;
            float fsa1 = (sa  && j9 <= t_a) ? fa1 : 0.f;
            float fsb0 = (sb2 && j8 <= t_b) ? fb0 : 0.f;
            float fsb1 = (sb2 && j9 <= t_b) ? fb1 : 0.f;

            float ewa0 = (j0 <= t_a && t_a - j0 < 512) ? ea0 : 0.f;
            float ewa1 = (j1 <= t_a && t_a - j1 < 512) ? ea1 : 0.f;
            float ewb0 = (j0 <= t_b && t_b - j0 < 512) ? eb0 : 0.f;
            float ewb1 = (j1 <= t_b && t_b - j1 < 512) ? eb1 : 0.f;
            float fwa0 = (j8 <= t_a && t_a - j8 < 512) ? fa0 : 0.f;
            float fwa1 = (j9 <= t_a && t_a - j9 < 512) ? fa1 : 0.f;
            float fwb0 = (j8 <= t_b && t_b - j8 < 512) ? fb0 : 0.f;
            float fwb1 = (j9 <= t_b && t_b - j9 < 512) ? fb1 : 0.f;

            sum_sa += esa0 + esa1 + fsa0 + fsa1;
            sum_sb += esb0 + esb1 + fsb0 + fsb1;
            sum_wa += ewa0 + ewa1 + fwa0 + fwa1;
            sum_wb += ewb0 + ewb1 + fwb0 + fwb1;

            uint32_t psh[4], psl[4], pwh[4], pwl[4];
            psh[0] = pack2(esa0, esa1, psl[0]);
            psh[1] = pack2(esb0, esb1, psl[1]);
            psh[2] = pack2(fsa0, fsa1, psl[2]);
            psh[3] = pack2(fsb0, fsb1, psl[3]);
            pwh[0] = pack2(ewa0, ewa1, pwl[0]);
            pwh[1] = pack2(ewb0, ewb1, pwl[1]);
            pwh[2] = pack2(fwa0, fwa1, pwl[2]);
            pwh[3] = pack2(fwb0, fwb1, pwl[3]);

            // ---- PV for this k16 (= keys np*16..+15) ----
            {
                int keyv = np * 16 + (grp & 1) * 8 + (lane & 7);
                uint32_t kb = (uint32_t)keyv * 256u, rxv = (uint32_t)(keyv & 7);
#pragma unroll
                for (int dp = 0; dp < 8; dp++) {
                    uint32_t c16 = (uint32_t)(dp * 2 + (grp >> 1));
                    uint32_t off = kb + ((c16 ^ rxv) << 4);
                    uint32_t vh[4], vl[4];
                    ldsm4t(vh, sbb_ + SVHI + off);
                    ldsm4t(vl, sbb_ + SVLO + off);
                    if (do_s) {
                        mma16816(Os[2 * dp],     psh, vh[0], vh[1]);
                        mma16816(Os[2 * dp + 1], psh, vh[2], vh[3]);
                        mma16816(Os[2 * dp],     psl, vh[0], vh[1]);
                        mma16816(Os[2 * dp + 1], psl, vh[2], vh[3]);
                        mma16816(Os[2 * dp],     psh, vl[0], vl[1]);
                        mma16816(Os[2 * dp + 1], psh, vl[2], vl[3]);
                    }
                    if (do_w) {
                        mma16816(Ow[2 * dp],     pwh, vh[0], vh[1]);
                        mma16816(Ow[2 * dp + 1], pwh, vh[2], vh[3]);
                        mma16816(Ow[2 * dp],     pwl, vh[0], vh[1]);
                        mma16816(Ow[2 * dp + 1], pwl, vh[2], vh[3]);
                        mma16816(Ow[2 * dp],     pwh, vl[0], vl[1]);
                        mma16816(Ow[2 * dp + 1], pwh, vl[2], vl[3]);
                    }
                }
            }
        }
    }

    // ---- row-sum reduction within 4-lane groups ----
#pragma unroll
    for (int o = 1; o <= 2; o <<= 1) {
        sum_sa += __shfl_xor_sync(0xffffffffu, sum_sa, o);
        sum_sb += __shfl_xor_sync(0xffffffffu, sum_sb, o);
        sum_wa += __shfl_xor_sync(0xffffffffu, sum_wa, o);
        sum_wb += __shfl_xor_sync(0xffffffffu, sum_wb, o);
    }
    float inv_sa = 1.f / sum_sa, inv_sb = 1.f / sum_sb;
    float inv_wa = 1.f / sum_wa, inv_wb = 1.f / sum_wb;

    const float* wa = w + ((size_t)(t_a * H_HEADS + h)) * 3;
    const float* wb = w + ((size_t)(t_b * H_HEADS + h)) * 3;
    float w0a = wa[0], w1a = wa[1], w2a = wa[2];
    float w0b = wb[0], w1b = wb[1], w2b = wb[2];

#pragma unroll
    for (int nt = 0; nt < 16; nt++) {
        int d0 = nt * 8 + jcl;
        const float2* ca = reinterpret_cast<const float2*>(&g_ocmp[t_a][h][d0]);
        const float2* cb = reinterpret_cast<const float2*>(&g_ocmp[t_b][h][d0]);
        float2 oc_a = *ca, oc_b = *cb;
        float2 oa, ob;
        oa.x = w0a * oc_a.x + w1a * Os[nt][0] * inv_sa + w2a * Ow[nt][0] * inv_wa;
        oa.y = w0a * oc_a.y + w1a * Os[nt][1] * inv_sa + w2a * Ow[nt][1] * inv_wa;
        ob.x = w0b * oc_b.x + w1b * Os[nt][2] * inv_sb + w2b * Ow[nt][2] * inv_wb;
        ob.y = w0b * oc_b.y + w1b * Os[nt][3] * inv_sb + w2b * Ow[nt][3] * inv_wb;
        *reinterpret_cast<float2*>(out + ((size_t)(t_a * H_HEADS + h)) * DDIM + d0) = oa;
        *reinterpret_cast<float2*>(out + ((size_t)(t_b * H_HEADS + h)) * DDIM + d0) = ob;
    }
}

// ---------------- launch ----------------
extern "C" void kernel_launch(void* const* d_in, const int* in_sizes, int n_in,
                              void* d_out, int out_size) {
    const float* q = (const float*)d_in[0];
    const float* k = (const float*)d_in[1];
    const float* v = (const float*)d_in[2];
    const float* w = (const float*)d_in[3];
    float* out = (float*)d_out;

    cudaFuncSetAttribute(k3_main, cudaFuncAttributeMaxDynamicSharedMemorySize, SMTOT);

    k1_compress<<<dim3(NCMP, KHN), DDIM>>>(k, v);
    k1b_knorm<<<dim3(T_LEN, KHN), 32>>>(k);
    k2_cmp_attn<<<dim3(T_LEN, KHN), 128>>>(q);
    k3_main<<<dim3(T_LEN / TQ, KHN), 256, SMTOT>>>(q, k, v, w, out);
}

// round 5
// speedup vs baseline: 3.4330x; 1.4403x over previous
#include <cuda_runtime.h>
#include <cuda_bf16.h>
#include <math.h>
#include <stdint.h>

#define T_LEN 2048
#define H_HEADS 16
#define KHN 2
#define GQ 8
#define DDIM 128
#define NCMP 127
#define NBLK 32
#define TQ 16
#define SCALE_F 0.08838834765f
#define NEG_INF (-INFINITY)

// ---------------- scratch ----------------
__device__ float g_cmp_k[KHN][NCMP][DDIM];
__device__ float g_cmp_v[KHN][NCMP][DDIM];
__device__ float g_ocmp[T_LEN][H_HEADS][DDIM];
__device__ unsigned g_sel[T_LEN][KHN];
__device__ unsigned g_kmax[KHN];

// bf16 hi/lo pre-split tensors
__device__ __align__(16) __nv_bfloat16 g_khi[KHN * T_LEN * DDIM];
__device__ __align__(16) __nv_bfloat16 g_klo[KHN * T_LEN * DDIM];
__device__ __align__(16) __nv_bfloat16 g_vhi[KHN * T_LEN * DDIM];
__device__ __align__(16) __nv_bfloat16 g_vlo[KHN * T_LEN * DDIM];
__device__ __align__(16) __nv_bfloat16 g_qhi[T_LEN * H_HEADS * DDIM];
__device__ __align__(16) __nv_bfloat16 g_qlo[T_LEN * H_HEADS * DDIM];

// ---------------- helpers ----------------
__device__ __forceinline__ uint32_t smem_u32(const void* p) {
    uint32_t a;
    asm("{ .reg .u64 t; cvta.to.shared.u64 t, %1; cvt.u32.u64 %0, t; }" : "=r"(a) : "l"(p));
    return a;
}
__device__ __forceinline__ void mma16816(float* d, const uint32_t* a, uint32_t b0, uint32_t b1) {
    asm volatile("mma.sync.aligned.m16n8k16.row.col.f32.bf16.bf16.f32 "
        "{%0,%1,%2,%3},{%4,%5,%6,%7},{%8,%9},{%0,%1,%2,%3};"
        : "+f"(d[0]), "+f"(d[1]), "+f"(d[2]), "+f"(d[3])
        : "r"(a[0]), "r"(a[1]), "r"(a[2]), "r"(a[3]), "r"(b0), "r"(b1));
}
__device__ __forceinline__ void ldsm4(uint32_t* r, uint32_t addr) {
    asm volatile("ldmatrix.sync.aligned.m8n8.x4.shared.b16 {%0,%1,%2,%3}, [%4];"
        : "=r"(r[0]), "=r"(r[1]), "=r"(r[2]), "=r"(r[3]) : "r"(addr));
}
__device__ __forceinline__ void ldsm4t(uint32_t* r, uint32_t addr) {
    asm volatile("ldmatrix.sync.aligned.m8n8.x4.trans.shared.b16 {%0,%1,%2,%3}, [%4];"
        : "=r"(r[0]), "=r"(r[1]), "=r"(r[2]), "=r"(r[3]) : "r"(addr));
}
__device__ __forceinline__ uint32_t pack2(float a, float b, uint32_t& lo) {
    __nv_bfloat16 ah = __float2bfloat16_rn(a), bh = __float2bfloat16_rn(b);
    __nv_bfloat16 al = __float2bfloat16_rn(a - __bfloat162float(ah));
    __nv_bfloat16 bl = __float2bfloat16_rn(b - __bfloat162float(bh));
    lo = ((uint32_t)__bfloat16_as_ushort(bl) << 16) | (uint32_t)__bfloat16_as_ushort(al);
    return ((uint32_t)__bfloat16_as_ushort(bh) << 16) | (uint32_t)__bfloat16_as_ushort(ah);
}
#define CP_ASYNC16(dst, src) \
    asm volatile("cp.async.cg.shared.global [%0], [%1], 16;" :: "r"(dst), "l"(src) : "memory")
#define CP_COMMIT() asm volatile("cp.async.commit_group;" ::: "memory")
#define CP_WAIT0()  asm volatile("cp.async.wait_group 0;" ::: "memory")

// ---------------- K0: pre-split q/k/v into bf16 hi/lo ----------------
__global__ void k0_split(const float* __restrict__ q, const float* __restrict__ k,
                         const float* __restrict__ v) {
    int stride = gridDim.x * blockDim.x;
    int idx = blockIdx.x * blockDim.x + threadIdx.x;
    const int n_kv = T_LEN * KHN * DDIM;
    for (int i = idx; i < n_kv; i += stride) {
        int d = i & (DDIM - 1);
        int tk = i >> 7;
        int kh = tk & 1, t = tk >> 1;
        int o = (kh * T_LEN + t) * DDIM + d;
        float x = k[i];
        __nv_bfloat16 h = __float2bfloat16_rn(x);
        g_khi[o] = h;
        g_klo[o] = __float2bfloat16_rn(x - __bfloat162float(h));
        x = v[i];
        h = __float2bfloat16_rn(x);
        g_vhi[o] = h;
        g_vlo[o] = __float2bfloat16_rn(x - __bfloat162float(h));
    }
    const int n_q = T_LEN * H_HEADS * DDIM;
    for (int i = idx; i < n_q; i += stride) {
        float x = q[i];
        __nv_bfloat16 h = __float2bfloat16_rn(x);
        g_qhi[i] = h;
        g_qlo[i] = __float2bfloat16_rn(x - __bfloat162float(h));
    }
}

// ---------------- K1: compressed K/V ----------------
__global__ void k1_compress(const float* __restrict__ k, const float* __restrict__ v) {
    int j = blockIdx.x, kh = blockIdx.y, d = threadIdx.x;
    int s = j * 16;
    float sk = 0.f, sv = 0.f;
#pragma unroll 8
    for (int i = 0; i < 32; i++) {
        sk += k[((size_t)(s + i) * KHN + kh) * DDIM + d];
        sv += v[((size_t)(s + i) * KHN + kh) * DDIM + d];
    }
    g_cmp_k[kh][j][d] = sk * (1.f / 32.f);
    g_cmp_v[kh][j][d] = sv * (1.f / 32.f);
}

// ---------------- K1b: max ||k_row|| per kv head ----------------
__global__ void k1b_knorm(const float* __restrict__ k) {
    int t = blockIdx.x, kh = blockIdx.y, lane = threadIdx.x;
    const float4* kr = reinterpret_cast<const float4*>(k) + ((size_t)t * KHN + kh) * 32;
    float4 a = kr[lane];
    float s = a.x * a.x + a.y * a.y + a.z * a.z + a.w * a.w;
    for (int o = 16; o; o >>= 1) s += __shfl_xor_sync(0xffffffffu, s, o);
    if (lane == 0) atomicMax(&g_kmax[kh], __float_as_uint(sqrtf(s)));
}

// ---------------- K2: compressed attention + block scores + top-16 ----------------
__global__ __launch_bounds__(128) void k2_cmp_attn(const float* __restrict__ q) {
    int t = blockIdx.x, kh = blockIdx.y, tid = threadIdx.x;
    int lane = tid & 31, wrp = tid >> 5;

    __shared__ float4 q_sh[GQ * 32];
    __shared__ float  lg[GQ][NCMP];
    __shared__ float  psum[NCMP];
    __shared__ float  l_sh[GQ];
    __shared__ float  blk[NBLK];

    for (int i = tid; i < GQ * 32; i += 128)
        q_sh[i] = reinterpret_cast<const float4*>(q)[(size_t)(t * H_HEADS + kh * GQ) * 32 + i];
    if (tid < NCMP) psum[tid] = 0.f;

    int n_valid = (t >= 31) ? ((t - 31) / 16 + 1) : 0;
    if (n_valid > NCMP) n_valid = NCMP;
    __syncthreads();

    if (n_valid > 0) {
        for (int g = 0; g < GQ; g++) {
            for (int j = wrp; j < n_valid; j += 4) {
                const float4* kr = reinterpret_cast<const float4*>(g_cmp_k[kh][j]);
                float4 a = q_sh[g * 32 + lane];
                float4 b = kr[lane];
                float s = a.x * b.x + a.y * b.y + a.z * b.z + a.w * b.w;
                for (int o = 16; o; o >>= 1) s += __shfl_xor_sync(0xffffffffu, s, o);
                if (lane == 0) lg[g][j] = s * SCALE_F;
            }
        }
        __syncthreads();
        for (int g = wrp; g < GQ; g += 4) {
            float m = NEG_INF;
            for (int j = lane; j < n_valid; j += 32) m = fmaxf(m, lg[g][j]);
            for (int o = 16; o; o >>= 1) m = fmaxf(m, __shfl_xor_sync(0xffffffffu, m, o));
            float sum = 0.f;
            for (int j = lane; j < n_valid; j += 32) {
                float e = expf(lg[g][j] - m);
                lg[g][j] = e; sum += e;
            }
            for (int o = 16; o; o >>= 1) sum += __shfl_xor_sync(0xffffffffu, sum, o);
            if (lane == 0) l_sh[g] = sum;
        }
        __syncthreads();
        if (tid < n_valid) {
            float s = 0.f;
#pragma unroll
            for (int g = 0; g < GQ; g++) s += lg[g][tid] / l_sh[g];
            psum[tid] = s;
        }
        {
            float acc[GQ];
#pragma unroll
            for (int g = 0; g < GQ; g++) acc[g] = 0.f;
            for (int j = 0; j < n_valid; j++) {
                float vv = g_cmp_v[kh][j][tid];
#pragma unroll
                for (int g = 0; g < GQ; g++) acc[g] += lg[g][j] * vv;
            }
#pragma unroll
            for (int g = 0; g < GQ; g++)
                g_ocmp[t][kh * GQ + g][tid] = acc[g] / l_sh[g];
        }
    } else {
#pragma unroll
        for (int g = 0; g < GQ; g++) g_ocmp[t][kh * GQ + g][tid] = 0.f;
    }
    __syncthreads();

    if (tid < NBLK) {
        int b = tid;
        int jlo = 4 * b - 1; if (jlo < 0) jlo = 0;
        int jhi = 4 * b + 3; if (jhi > n_valid - 1) jhi = n_valid - 1;
        float s = 0.f;
        for (int j = jlo; j <= jhi; j++) s += psum[j];
        blk[b] = s;
    }
    __syncthreads();

    if (tid < 32) {
        int b = tid;
        int t_blk = t >> 6;
        bool forced = (b < 1) || ((b <= t_blk) && (b >= t_blk - 1));
        bool valid  = (b * 64 <= t);
        float sc = forced ? 1e30f : blk[b];
        sc = valid ? sc : -1e30f;
        unsigned sel = 0u;
        for (int it = 0; it < 16; it++) {
            float vcur = ((sel >> b) & 1u) ? NEG_INF : sc;
            float m = vcur;
            for (int o = 16; o; o >>= 1) m = fmaxf(m, __shfl_xor_sync(0xffffffffu, m, o));
            unsigned ball = __ballot_sync(0xffffffffu, vcur == m);
            int winb = __ffs(ball) - 1;
            sel |= (1u << winb);
        }
        if (tid == 0) g_sel[t][kh] = sel;
    }
}

// ---------------- K3: HMMA fused slc+win attention (cp.async pipelined) ----------------
// smem: Q hi/lo 64KB + 2 x 64KB KV buffers = 192KB
#define SQHI 0
#define SQLO 32768
#define SBUF 65536
#define BUFSZ 65536
#define KHIO 0
#define KLOO 16384
#define VHIO 32768
#define VLOO 49152
#define SMTOT 196608

__global__ __launch_bounds__(256, 1) void k3_main(
    const float* __restrict__ q, const float* __restrict__ w,
    float* __restrict__ out)
{
    extern __shared__ char smem[];
    uint32_t sbb_ = smem_u32(smem);
    int tid = threadIdx.x;
    int wp = tid >> 5, lane = tid & 31;
    int tile = (int)gridDim.x - 1 - (int)blockIdx.x;   // heavy tiles first
    int t0 = tile * TQ;
    int kh = blockIdx.y;

    __shared__ int s_list[36];
    __shared__ int s_n;
    __shared__ unsigned s_union;

    // lane's rows: t_a (frag c0/c1), t_b (c2/c3); head g = lane>>2
    int g = lane >> 2;
    int t_a = t0 + 2 * wp;
    int t_b = t_a + 1;
    int h = kh * GQ + g;

    unsigned selm_a = g_sel[t_a][kh], selm_b = g_sel[t_b][kh];
    if (tid == 0) s_union = 0u;
    __syncthreads();
    if (lane == 0) atomicOr(&s_union, selm_a | selm_b);

    // ---- stage Q (pre-split bf16, swizzled) via cp.async ----
    for (int i = tid; i < 128 * 16; i += 256) {
        int row = i >> 4, c16 = i & 15;
        int qrow = (t0 + (row >> 3)) * H_HEADS + kh * GQ + (row & 7);
        uint32_t off = (uint32_t)row * 256u + (uint32_t)((c16 ^ (row & 7)) << 4);
        CP_ASYNC16(sbb_ + SQHI + off, g_qhi + (size_t)qrow * DDIM + c16 * 8);
        CP_ASYNC16(sbb_ + SQLO + off, g_qlo + (size_t)qrow * DDIM + c16 * 8);
    }

    // exponent offsets U = scale*||q||*max||k||
    float kmax = __uint_as_float(g_kmax[kh]);
    float Ua, Ub;
    {
        const float4* q4 = reinterpret_cast<const float4*>(q);
        float s2 = 0.f;
        const float4* qr = q4 + ((size_t)(t_a * H_HEADS + h)) * 32;
#pragma unroll 8
        for (int d4 = 0; d4 < 32; d4++) { float4 a = qr[d4]; s2 += a.x*a.x + a.y*a.y + a.z*a.z + a.w*a.w; }
        Ua = SCALE_F * sqrtf(s2) * kmax;
        s2 = 0.f;
        qr = q4 + ((size_t)(t_b * H_HEADS + h)) * 32;
#pragma unroll 8
        for (int d4 = 0; d4 < 32; d4++) { float4 a = qr[d4]; s2 += a.x*a.x + a.y*a.y + a.z*a.z + a.w*a.w; }
        Ub = SCALE_F * sqrtf(s2) * kmax;
    }

    __syncthreads();
    unsigned selu = s_union;
    int t_blk = t0 >> 6;

    if (tid == 0) {
        int n = 0;
        for (int b = 0; b <= t_blk; b++) {
            bool need = ((selu >> b) & 1u) || (b * 64 + 63 >= t0 - 511);
            if (need) s_list[n++] = b;
        }
        s_n = n;
    }
    __syncthreads();
    int nch = s_n;

    const __nv_bfloat16* khbase = g_khi + (size_t)kh * T_LEN * DDIM;
    const __nv_bfloat16* klbase = g_klo + (size_t)kh * T_LEN * DDIM;
    const __nv_bfloat16* vhbase = g_vhi + (size_t)kh * T_LEN * DDIM;
    const __nv_bfloat16* vlbase = g_vlo + (size_t)kh * T_LEN * DDIM;

    // prefetch first chunk (same commit group as Q staging)
    {
        int b0 = s_list[0];
        for (int i = tid; i < 1024; i += 256) {
            int row = i >> 4, c16 = i & 15;
            size_t src = (size_t)(b0 * 64 + row) * DDIM + c16 * 8;
            uint32_t dst = sbb_ + SBUF + ((uint32_t)row * 256u + (uint32_t)((c16 ^ (row & 7)) << 4));
            CP_ASYNC16(dst + KHIO, khbase + src);
            CP_ASYNC16(dst + KLOO, klbase + src);
            CP_ASYNC16(dst + VHIO, vhbase + src);
            CP_ASYNC16(dst + VLOO, vlbase + src);
        }
    }
    CP_COMMIT();

    float Os[16][4], Ow[16][4];
#pragma unroll
    for (int i = 0; i < 16; i++)
#pragma unroll
        for (int c = 0; c < 4; c++) { Os[i][c] = 0.f; Ow[i][c] = 0.f; }
    float sum_sa = 0.f, sum_sb = 0.f, sum_wa = 0.f, sum_wb = 0.f;

    int jcl = (lane & 3) * 2;
    int grp = lane >> 3;

    for (int ci = 0; ci < nch; ci++) {
        int b = s_list[ci];
        bool do_s = (selu >> b) & 1u;
        bool do_w = (b * 64 + 63 >= t0 - 511);
        uint32_t KB = sbb_ + SBUF + (uint32_t)(ci & 1) * BUFSZ;

        CP_WAIT0();
        __syncthreads();

        // prefetch next chunk into other buffer
        if (ci + 1 < nch) {
            int bn = s_list[ci + 1];
            uint32_t NB = sbb_ + SBUF + (uint32_t)((ci + 1) & 1) * BUFSZ;
            for (int i = tid; i < 1024; i += 256) {
                int row = i >> 4, c16 = i & 15;
                size_t src = (size_t)(bn * 64 + row) * DDIM + c16 * 8;
                uint32_t dst = NB + ((uint32_t)row * 256u + (uint32_t)((c16 ^ (row & 7)) << 4));
                CP_ASYNC16(dst + KHIO, khbase + src);
                CP_ASYNC16(dst + KLOO, klbase + src);
                CP_ASYNC16(dst + VHIO, vhbase + src);
                CP_ASYNC16(dst + VLOO, vlbase + src);
            }
            CP_COMMIT();
        }

        // ---- Q hi fragments (per-chunk reload, 8 ldsm) ----
        uint32_t ah[8][4];
        {
            int row = 16 * wp + (grp & 1) * 8 + (lane & 7);
            uint32_t rbase = (uint32_t)row * 256u, rx = (uint32_t)(row & 7);
#pragma unroll
            for (int kt = 0; kt < 8; kt++) {
                uint32_t c16 = (uint32_t)(kt * 2 + (grp >> 1));
                ldsm4(ah[kt], sbb_ + SQHI + rbase + ((c16 ^ rx) << 4));
            }
        }

#pragma unroll
        for (int np = 0; np < 4; np++) {
            float s0[4] = {0.f, 0.f, 0.f, 0.f}, s1[4] = {0.f, 0.f, 0.f, 0.f};
            {
                int keyq = np * 16 + (grp >> 1) * 8 + (lane & 7);
                uint32_t kb = (uint32_t)keyq * 256u, rxk = (uint32_t)(keyq & 7);
                int rowq = 16 * wp + (grp & 1) * 8 + (lane & 7);
                uint32_t rb = (uint32_t)rowq * 256u, rxq = (uint32_t)(rowq & 7);
#pragma unroll
                for (int kt = 0; kt < 8; kt++) {
                    uint32_t ck = (uint32_t)(kt * 2 + (grp & 1));
                    uint32_t cq = (uint32_t)(kt * 2 + (grp >> 1));
                    uint32_t bh[4], bl[4], alr[4];
                    ldsm4(bh, KB + KHIO + kb + ((ck ^ rxk) << 4));
                    ldsm4(bl, KB + KLOO + kb + ((ck ^ rxk) << 4));
                    ldsm4(alr, sbb_ + SQLO + rb + ((cq ^ rxq) << 4));
                    mma16816(s0, ah[kt], bh[0], bh[1]);
                    mma16816(s1, ah[kt], bh[2], bh[3]);
                    mma16816(s0, ah[kt], bl[0], bl[1]);
                    mma16816(s1, ah[kt], bl[2], bl[3]);
                    mma16816(s0, alr, bh[0], bh[1]);
                    mma16816(s1, alr, bh[2], bh[3]);
                }
            }
            // ---- exp + masks + P fragments ----
            int j0 = b * 64 + np * 16 + jcl;
            float ea0 = __expf(s0[0] * SCALE_F - Ua);
            float ea1 = __expf(s0[1] * SCALE_F - Ua);
            float eb0 = __expf(s0[2] * SCALE_F - Ub);
            float eb1 = __expf(s0[3] * SCALE_F - Ub);
            float fa0 = __expf(s1[0] * SCALE_F - Ua);
            float fa1 = __expf(s1[1] * SCALE_F - Ua);
            float fb0 = __expf(s1[2] * SCALE_F - Ub);
            float fb1 = __expf(s1[3] * SCALE_F - Ub);
            bool sa = (selm_a >> b) & 1u, sb2 = (selm_b >> b) & 1u;
            int j1 = j0 + 1, j8 = j0 + 8, j9 = j0 + 9;

            float esa0 = (sa  && j0 <= t_a) ? ea0 : 0.f;
            float esa1 = (sa  && j1 <= t_a) ? ea1 : 0.f;
            float esb0 = (sb2 && j0 <= t_b) ? eb0 : 0.f;
            float esb1 = (sb2 && j1 <= t_b) ? eb1 : 0.f;
            float fsa0 = (sa  && j8 <= t_a) ? fa0 : 0.f;
            float fsa1 = (sa  && j9 <= t_a) ? fa1 : 0.f;
            float fsb0 = (sb2 && j8 <= t_b) ? fb0 : 0.f;
            float fsb1 = (sb2 && j9 <= t_b) ? fb1 : 0.f;

            float ewa0 = (j0 <= t_a && t_a - j0 < 512) ? ea0 : 0.f;
            float ewa1 = (j1 <= t_a && t_a - j1 < 512) ? ea1 : 0.f;
            float ewb0 = (j0 <= t_b && t_b - j0 < 512) ? eb0 : 0.f;
            float ewb1 = (j1 <= t_b && t_b - j1 < 512) ? eb1 : 0.f;
            float fwa0 = (j8 <= t_a && t_a - j8 < 512) ? fa0 : 0.f;
            float fwa1 = (j9 <= t_a && t_a - j9 < 512) ? fa1 : 0.f;
            float fwb0 = (j8 <= t_b && t_b - j8 < 512) ? fb0 : 0.f;
            float fwb1 = (j9 <= t_b && t_b - j9 < 512) ? fb1 : 0.f;

            sum_sa += esa0 + esa1 + fsa0 + fsa1;
            sum_sb += esb0 + esb1 + fsb0 + fsb1;
            sum_wa += ewa0 + ewa1 + fwa0 + fwa1;
            sum_wb += ewb0 + ewb1 + fwb0 + fwb1;

            uint32_t psh[4], psl[4], pwh[4], pwl[4];
            psh[0] = pack2(esa0, esa1, psl[0]);
            psh[1] = pack2(esb0, esb1, psl[1]);
            psh[2] = pack2(fsa0, fsa1, psl[2]);
            psh[3] = pack2(fsb0, fsb1, psl[3]);
            pwh[0] = pack2(ewa0, ewa1, pwl[0]);
            pwh[1] = pack2(ewb0, ewb1, pwl[1]);
            pwh[2] = pack2(fwa0, fwa1, pwl[2]);
            pwh[3] = pack2(fwb0, fwb1, pwl[3]);

            // ---- PV for this k16 ----
            {
                int keyv = np * 16 + (grp & 1) * 8 + (lane & 7);
                uint32_t kb = (uint32_t)keyv * 256u, rxv = (uint32_t)(keyv & 7);
#pragma unroll
                for (int dp = 0; dp < 8; dp++) {
                    uint32_t c16 = (uint32_t)(dp * 2 + (grp >> 1));
                    uint32_t off = kb + ((c16 ^ rxv) << 4);
                    uint32_t vh[4], vl[4];
                    ldsm4t(vh, KB + VHIO + off);
                    ldsm4t(vl, KB + VLOO + off);
                    if (do_s) {
                        mma16816(Os[2 * dp],     psh, vh[0], vh[1]);
                        mma16816(Os[2 * dp + 1], psh, vh[2], vh[3]);
                        mma16816(Os[2 * dp],     psl, vh[0], vh[1]);
                        mma16816(Os[2 * dp + 1], psl, vh[2], vh[3]);
                        mma16816(Os[2 * dp],     psh, vl[0], vl[1]);
                        mma16816(Os[2 * dp + 1], psh, vl[2], vl[3]);
                    }
                    if (do_w) {
                        mma16816(Ow[2 * dp],     pwh, vh[0], vh[1]);
                        mma16816(Ow[2 * dp + 1], pwh, vh[2], vh[3]);
                        mma16816(Ow[2 * dp],     pwl, vh[0], vh[1]);
                        mma16816(Ow[2 * dp + 1], pwl, vh[2], vh[3]);
                        mma16816(Ow[2 * dp],     pwh, vl[0], vl[1]);
                        mma16816(Ow[2 * dp + 1], pwh, vl[2], vl[3]);
                    }
                }
            }
        }
    }

    // ---- row-sum reduction within 4-lane groups ----
#pragma unroll
    for (int o = 1; o <= 2; o <<= 1) {
        sum_sa += __shfl_xor_sync(0xffffffffu, sum_sa, o);
        sum_sb += __shfl_xor_sync(0xffffffffu, sum_sb, o);
        sum_wa += __shfl_xor_sync(0xffffffffu, sum_wa, o);
        sum_wb += __shfl_xor_sync(0xffffffffu, sum_wb, o);
    }
    float inv_sa = 1.f / sum_sa, inv_sb = 1.f / sum_sb;
    float inv_wa = 1.f / sum_wa, inv_wb = 1.f / sum_wb;

    const float* wa = w + ((size_t)(t_a * H_HEADS + h)) * 3;
    const float* wb = w + ((size_t)(t_b * H_HEADS + h)) * 3;
    float w0a = wa[0], w1a = wa[1], w2a = wa[2];
    float w0b = wb[0], w1b = wb[1], w2b = wb[2];

#pragma unroll
    for (int nt = 0; nt < 16; nt++) {
        int d0 = nt * 8 + jcl;
        const float2* ca = reinterpret_cast<const float2*>(&g_ocmp[t_a][h][d0]);
        const float2* cb = reinterpret_cast<const float2*>(&g_ocmp[t_b][h][d0]);
        float2 oc_a = *ca, oc_b = *cb;
        float2 oa, ob;
        oa.x = w0a * oc_a.x + w1a * Os[nt][0] * inv_sa + w2a * Ow[nt][0] * inv_wa;
        oa.y = w0a * oc_a.y + w1a * Os[nt][1] * inv_sa + w2a * Ow[nt][1] * inv_wa;
        ob.x = w0b * oc_b.x + w1b * Os[nt][2] * inv_sb + w2b * Ow[nt][2] * inv_wb;
        ob.y = w0b * oc_b.y + w1b * Os[nt][3] * inv_sb + w2b * Ow[nt][3] * inv_wb;
        *reinterpret_cast<float2*>(out + ((size_t)(t_a * H_HEADS + h)) * DDIM + d0) = oa;
        *reinterpret_cast<float2*>(out + ((size_t)(t_b * H_HEADS + h)) * DDIM + d0) = ob;
    }
}

// ---------------- launch ----------------
extern "C" void kernel_launch(void* const* d_in, const int* in_sizes, int n_in,
                              void* d_out, int out_size) {
    const float* q = (const float*)d_in[0];
    const float* k = (const float*)d_in[1];
    const float* v = (const float*)d_in[2];
    const float* w = (const float*)d_in[3];
    float* out = (float*)d_out;

    cudaFuncSetAttribute(k3_main, cudaFuncAttributeMaxDynamicSharedMemorySize, SMTOT);

    k0_split<<<1024, 256>>>(q, k, v);
    k1_compress<<<dim3(NCMP, KHN), DDIM>>>(k, v);
    k1b_knorm<<<dim3(T_LEN, KHN), 32>>>(k);
    k2_cmp_attn<<<dim3(T_LEN, KHN), 128>>>(q);
    k3_main<<<dim3(T_LEN / TQ, KHN), 256, SMTOT>>>(q, w, out);
}

// round 6
// speedup vs baseline: 4.2691x; 1.2436x over previous
#include <cuda_runtime.h>
#include <cuda_bf16.h>
#include <math.h>
#include <stdint.h>

#define T_LEN 2048
#define H_HEADS 16
#define KHN 2
#define GQ 8
#define DDIM 128
#define NCMP 127
#define NBLK 32
#define TQ 16
#define SCALE_F 0.08838834765f
#define NEG_INF (-INFINITY)

// ---------------- scratch ----------------
__device__ float g_ocmp[T_LEN][H_HEADS][DDIM];
__device__ unsigned g_sel[T_LEN][KHN];
__device__ unsigned g_kmax[KHN];

// pre-split tensors (bf16)
__device__ __align__(16) __nv_bfloat16 g_khi[KHN * T_LEN * DDIM];
__device__ __align__(16) __nv_bfloat16 g_klo[KHN * T_LEN * DDIM];
__device__ __align__(16) __nv_bfloat16 g_vhi[KHN * T_LEN * DDIM];
__device__ __align__(16) __nv_bfloat16 g_vlo[KHN * T_LEN * DDIM];
__device__ __align__(16) __nv_bfloat16 g_qhi[T_LEN * H_HEADS * DDIM];
__device__ __align__(16) __nv_bfloat16 g_qmi[T_LEN * H_HEADS * DDIM];
__device__ __align__(16) __nv_bfloat16 g_qlo[T_LEN * H_HEADS * DDIM];
// compressed K 3-split / V 2-split, row 127 stays zero (padding)
__device__ __align__(16) __nv_bfloat16 g_ckhi[KHN][128][DDIM];
__device__ __align__(16) __nv_bfloat16 g_ckmi[KHN][128][DDIM];
__device__ __align__(16) __nv_bfloat16 g_cklo[KHN][128][DDIM];
__device__ __align__(16) __nv_bfloat16 g_cvhi[KHN][128][DDIM];
__device__ __align__(16) __nv_bfloat16 g_cvlo[KHN][128][DDIM];

// ---------------- helpers ----------------
__device__ __forceinline__ uint32_t smem_u32(const void* p) {
    uint32_t a;
    asm("{ .reg .u64 t; cvta.to.shared.u64 t, %1; cvt.u32.u64 %0, t; }" : "=r"(a) : "l"(p));
    return a;
}
__device__ __forceinline__ void mma16816(float* d, const uint32_t* a, uint32_t b0, uint32_t b1) {
    asm volatile("mma.sync.aligned.m16n8k16.row.col.f32.bf16.bf16.f32 "
        "{%0,%1,%2,%3},{%4,%5,%6,%7},{%8,%9},{%0,%1,%2,%3};"
        : "+f"(d[0]), "+f"(d[1]), "+f"(d[2]), "+f"(d[3])
        : "r"(a[0]), "r"(a[1]), "r"(a[2]), "r"(a[3]), "r"(b0), "r"(b1));
}
__device__ __forceinline__ void ldsm4(uint32_t* r, uint32_t addr) {
    asm volatile("ldmatrix.sync.aligned.m8n8.x4.shared.b16 {%0,%1,%2,%3}, [%4];"
        : "=r"(r[0]), "=r"(r[1]), "=r"(r[2]), "=r"(r[3]) : "r"(addr));
}
__device__ __forceinline__ void ldsm4t(uint32_t* r, uint32_t addr) {
    asm volatile("ldmatrix.sync.aligned.m8n8.x4.trans.shared.b16 {%0,%1,%2,%3}, [%4];"
        : "=r"(r[0]), "=r"(r[1]), "=r"(r[2]), "=r"(r[3]) : "r"(addr));
}
__device__ __forceinline__ uint32_t pack2(float a, float b, uint32_t& lo) {
    __nv_bfloat16 ah = __float2bfloat16_rn(a), bh = __float2bfloat16_rn(b);
    __nv_bfloat16 al = __float2bfloat16_rn(a - __bfloat162float(ah));
    __nv_bfloat16 bl = __float2bfloat16_rn(b - __bfloat162float(bh));
    lo = ((uint32_t)__bfloat16_as_ushort(bl) << 16) | (uint32_t)__bfloat16_as_ushort(al);
    return ((uint32_t)__bfloat16_as_ushort(bh) << 16) | (uint32_t)__bfloat16_as_ushort(ah);
}
#define CP_ASYNC16(dst, src) \
    asm volatile("cp.async.cg.shared.global [%0], [%1], 16;" :: "r"(dst), "l"(src) : "memory")
#define CP_COMMIT() asm volatile("cp.async.commit_group;" ::: "memory")
#define CP_WAIT0()  asm volatile("cp.async.wait_group 0;" ::: "memory")

// ---------------- K0: pre-split q (3-way) / k,v (2-way) ----------------
__global__ void k0_split(const float* __restrict__ q, const float* __restrict__ k,
                         const float* __restrict__ v) {
    int stride = gridDim.x * blockDim.x;
    int idx = blockIdx.x * blockDim.x + threadIdx.x;
    const int n_kv = T_LEN * KHN * DDIM;
    for (int i = idx; i < n_kv; i += stride) {
        int d = i & (DDIM - 1);
        int tk = i >> 7;
        int kh = tk & 1, t = tk >> 1;
        int o = (kh * T_LEN + t) * DDIM + d;
        float x = k[i];
        __nv_bfloat16 h = __float2bfloat16_rn(x);
        g_khi[o] = h;
        g_klo[o] = __float2bfloat16_rn(x - __bfloat162float(h));
        x = v[i];
        h = __float2bfloat16_rn(x);
        g_vhi[o] = h;
        g_vlo[o] = __float2bfloat16_rn(x - __bfloat162float(h));
    }
    const int n_q = T_LEN * H_HEADS * DDIM;
    for (int i = idx; i < n_q; i += stride) {
        float x = q[i];
        __nv_bfloat16 h = __float2bfloat16_rn(x);
        float r1 = x - __bfloat162float(h);
        __nv_bfloat16 m = __float2bfloat16_rn(r1);
        g_qhi[i] = h;
        g_qmi[i] = m;
        g_qlo[i] = __float2bfloat16_rn(r1 - __bfloat162float(m));
    }
}

// ---------------- K1: compressed K/V + 3/2-way splits ----------------
__global__ void k1_compress(const float* __restrict__ k, const float* __restrict__ v) {
    int j = blockIdx.x, kh = blockIdx.y, d = threadIdx.x;
    int s = j * 16;
    float sk = 0.f, sv = 0.f;
#pragma unroll 8
    for (int i = 0; i < 32; i++) {
        sk += k[((size_t)(s + i) * KHN + kh) * DDIM + d];
        sv += v[((size_t)(s + i) * KHN + kh) * DDIM + d];
    }
    float ck = sk * (1.f / 32.f), cv = sv * (1.f / 32.f);
    __nv_bfloat16 h = __float2bfloat16_rn(ck);
    float r1 = ck - __bfloat162float(h);
    __nv_bfloat16 m = __float2bfloat16_rn(r1);
    g_ckhi[kh][j][d] = h;
    g_ckmi[kh][j][d] = m;
    g_cklo[kh][j][d] = __float2bfloat16_rn(r1 - __bfloat162float(m));
    h = __float2bfloat16_rn(cv);
    g_cvhi[kh][j][d] = h;
    g_cvlo[kh][j][d] = __float2bfloat16_rn(cv - __bfloat162float(h));
}

// ---------------- K1b: max ||k_row|| per kv head ----------------
__global__ void k1b_knorm(const float* __restrict__ k) {
    int t = blockIdx.x, kh = blockIdx.y, lane = threadIdx.x;
    const float4* kr = reinterpret_cast<const float4*>(k) + ((size_t)t * KHN + kh) * 32;
    float4 a = kr[lane];
    float s = a.x * a.x + a.y * a.y + a.z * a.z + a.w * a.w;
    for (int o = 16; o; o >>= 1) s += __shfl_xor_sync(0xffffffffu, s, o);
    if (lane == 0) atomicMax(&g_kmax[kh], __float_as_uint(sqrtf(s)));
}

// ---------------- K2: tensor-core compressed attention + selection ----------------
// smem: q hi/mi/lo (3x32KB) + ck hi/mi/lo (3x32KB) + psum 8KB; cv hi/lo reuses q region
#define K2_QH 0
#define K2_QM 32768
#define K2_QL 65536
#define K2_CKH 98304
#define K2_CKM 131072
#define K2_CKL 163840
#define K2_PS  196608
#define K2_TOT 204800
#define K2_VH 0
#define K2_VL 32768

__global__ __launch_bounds__(256, 1) void k2_tc() {
    extern __shared__ char smem[];
    uint32_t sb = smem_u32(smem);
    float* psum_sh = reinterpret_cast<float*>(smem + K2_PS);
    int tid = threadIdx.x;
    int wp = tid >> 5, lane = tid & 31;
    int t0 = blockIdx.x * TQ;
    int kh = blockIdx.y;
    int grp = lane >> 3;
    int jcl = (lane & 3) * 2;

    // ---- stage q (3-split) + cmp_k (3-split) ----
    for (int i = tid; i < 128 * 16; i += 256) {
        int row = i >> 4, c16 = i & 15;
        uint32_t off = (uint32_t)row * 256u + (uint32_t)((c16 ^ (row & 7)) << 4);
        int qrow = (t0 + (row >> 3)) * H_HEADS + kh * GQ + (row & 7);
        CP_ASYNC16(sb + K2_QH + off, g_qhi + (size_t)qrow * DDIM + c16 * 8);
        CP_ASYNC16(sb + K2_QM + off, g_qmi + (size_t)qrow * DDIM + c16 * 8);
        CP_ASYNC16(sb + K2_QL + off, g_qlo + (size_t)qrow * DDIM + c16 * 8);
        CP_ASYNC16(sb + K2_CKH + off, &g_ckhi[kh][row][c16 * 8]);
        CP_ASYNC16(sb + K2_CKM + off, &g_ckmi[kh][row][c16 * 8]);
        CP_ASYNC16(sb + K2_CKL + off, &g_cklo[kh][row][c16 * 8]);
    }
    CP_COMMIT();
    CP_WAIT0();
    __syncthreads();

    int t_a = t0 + 2 * wp;
    int t_b = t_a + 1;
    int g = lane >> 2;
    int h = kh * GQ + g;
    int nva = (t_a >= 31) ? ((t_a - 31) / 16 + 1) : 0;
    int nvb = (t_b >= 31) ? ((t_b - 31) / 16 + 1) : 0;

    // ---- QK: 6-term split MMA -> ~fp32-exact logits ----
    float s[16][4];
#pragma unroll
    for (int i = 0; i < 16; i++)
#pragma unroll
        for (int c = 0; c < 4; c++) s[i][c] = 0.f;

    uint32_t ah[8][4], am[8][4];
    {
        int row = 16 * wp + (grp & 1) * 8 + (lane & 7);
        uint32_t rb = (uint32_t)row * 256u, rx = (uint32_t)(row & 7);
#pragma unroll
        for (int kt = 0; kt < 8; kt++) {
            uint32_t cq = (uint32_t)(kt * 2 + (grp >> 1));
            uint32_t ao = rb + ((cq ^ rx) << 4);
            ldsm4(ah[kt], sb + K2_QH + ao);
            ldsm4(am[kt], sb + K2_QM + ao);
        }
    }
#pragma unroll
    for (int np = 0; np < 8; np++) {
        int keyq = np * 16 + (grp >> 1) * 8 + (lane & 7);
        uint32_t kb = (uint32_t)keyq * 256u, rxk = (uint32_t)(keyq & 7);
        int rowq = 16 * wp + (grp & 1) * 8 + (lane & 7);
        uint32_t rq = (uint32_t)rowq * 256u, rxq = (uint32_t)(rowq & 7);
#pragma unroll
        for (int kt = 0; kt < 8; kt++) {
            uint32_t ck = (uint32_t)(kt * 2 + (grp & 1));
            uint32_t bo = kb + ((ck ^ rxk) << 4);
            uint32_t cq = (uint32_t)(kt * 2 + (grp >> 1));
            uint32_t bh[4], bm[4], bl[4], al[4];
            ldsm4(bh, sb + K2_CKH + bo);
            ldsm4(bm, sb + K2_CKM + bo);
            ldsm4(bl, sb + K2_CKL + bo);
            ldsm4(al, sb + K2_QL + rq + ((cq ^ rxq) << 4));
            mma16816(s[2*np],   ah[kt], bh[0], bh[1]);
            mma16816(s[2*np+1], ah[kt], bh[2], bh[3]);
            mma16816(s[2*np],   ah[kt], bm[0], bm[1]);
            mma16816(s[2*np+1], ah[kt], bm[2], bm[3]);
            mma16816(s[2*np],   ah[kt], bl[0], bl[1]);
            mma16816(s[2*np+1], ah[kt], bl[2], bl[3]);
            mma16816(s[2*np],   am[kt], bh[0], bh[1]);
            mma16816(s[2*np+1], am[kt], bh[2], bh[3]);
            mma16816(s[2*np],   am[kt], bm[0], bm[1]);
            mma16816(s[2*np+1], am[kt], bm[2], bm[3]);
            mma16816(s[2*np],   al,     bh[0], bh[1]);
            mma16816(s[2*np+1], al,     bh[2], bh[3]);
        }
    }
    __syncthreads();   // q/ck reads done -> safe to restage

    // ---- stage cmp_v hi/lo into q region (overlap with softmax) ----
    for (int i = tid; i < 128 * 16; i += 256) {
        int row = i >> 4, c16 = i & 15;
        uint32_t off = (uint32_t)row * 256u + (uint32_t)((c16 ^ (row & 7)) << 4);
        CP_ASYNC16(sb + K2_VH + off, &g_cvhi[kh][row][c16 * 8]);
        CP_ASYNC16(sb + K2_VL + off, &g_cvlo[kh][row][c16 * 8]);
    }
    CP_COMMIT();

    // ---- softmax (exact fp32) ----
    float ma = NEG_INF, mb = NEG_INF;
#pragma unroll
    for (int nt = 0; nt < 16; nt++) {
        int j0 = nt * 8 + jcl;
        if (j0 < nva)     ma = fmaxf(ma, s[nt][0] * SCALE_F);
        if (j0 + 1 < nva) ma = fmaxf(ma, s[nt][1] * SCALE_F);
        if (j0 < nvb)     mb = fmaxf(mb, s[nt][2] * SCALE_F);
        if (j0 + 1 < nvb) mb = fmaxf(mb, s[nt][3] * SCALE_F);
    }
#pragma unroll
    for (int o = 1; o <= 2; o <<= 1) {
        ma = fmaxf(ma, __shfl_xor_sync(0xffffffffu, ma, o));
        mb = fmaxf(mb, __shfl_xor_sync(0xffffffffu, mb, o));
    }
    float la = 0.f, lb = 0.f;
#pragma unroll
    for (int nt = 0; nt < 16; nt++) {
        int j0 = nt * 8 + jcl;
        float e0 = (j0 < nva)     ? expf(s[nt][0] * SCALE_F - ma) : 0.f;
        float e1 = (j0 + 1 < nva) ? expf(s[nt][1] * SCALE_F - ma) : 0.f;
        float e2 = (j0 < nvb)     ? expf(s[nt][2] * SCALE_F - mb) : 0.f;
        float e3 = (j0 + 1 < nvb) ? expf(s[nt][3] * SCALE_F - mb) : 0.f;
        s[nt][0] = e0; s[nt][1] = e1; s[nt][2] = e2; s[nt][3] = e3;
        la += e0 + e1; lb += e2 + e3;
    }
#pragma unroll
    for (int o = 1; o <= 2; o <<= 1) {
        la += __shfl_xor_sync(0xffffffffu, la, o);
        lb += __shfl_xor_sync(0xffffffffu, lb, o);
    }
    float inva = (nva > 0) ? 1.f / la : 0.f;
    float invb = (nvb > 0) ? 1.f / lb : 0.f;
#pragma unroll
    for (int nt = 0; nt < 16; nt++) {
        s[nt][0] *= inva; s[nt][1] *= inva;
        s[nt][2] *= invb; s[nt][3] *= invb;
    }

    // ---- psum (group-summed probabilities) -> shared ----
#pragma unroll
    for (int nt = 0; nt < 16; nt++) {
        float a0 = s[nt][0], a1 = s[nt][1], b0 = s[nt][2], b1 = s[nt][3];
#pragma unroll
        for (int o = 4; o <= 16; o <<= 1) {
            a0 += __shfl_xor_sync(0xffffffffu, a0, o);
            a1 += __shfl_xor_sync(0xffffffffu, a1, o);
            b0 += __shfl_xor_sync(0xffffffffu, b0, o);
            b1 += __shfl_xor_sync(0xffffffffu, b1, o);
        }
        if (lane < 4) {
            int j = nt * 8 + lane * 2;
            psum_sh[(2 * wp) * 128 + j] = a0;
            psum_sh[(2 * wp) * 128 + j + 1] = a1;
            psum_sh[(2 * wp + 1) * 128 + j] = b0;
            psum_sh[(2 * wp + 1) * 128 + j + 1] = b1;
        }
    }
    __syncthreads();

    // ---- top-16 selection (exact fp32, warp per 2 rows) ----
#pragma unroll
    for (int rep = 0; rep < 2; rep++) {
        int t = t0 + 2 * wp + rep;
        int qi = 2 * wp + rep;
        int nv = (t >= 31) ? ((t - 31) / 16 + 1) : 0;
        int b = lane;
        int tb = t >> 6;
        bool forced = (b < 1) || ((b <= tb) && (b >= tb - 1));
        bool valid = (b * 64 <= t);
        float sc;
        if (!valid) sc = -1e30f;
        else if (forced) sc = 1e30f;
        else {
            int jlo = 4 * b - 1; if (jlo < 0) jlo = 0;
            int jhi = 4 * b + 3; if (jhi > nv - 1) jhi = nv - 1;
            float ss = 0.f;
            for (int j = jlo; j <= jhi; j++) ss += psum_sh[qi * 128 + j];
            sc = ss;
        }
        unsigned sel = 0u;
        for (int it = 0; it < 16; it++) {
            float vcur = ((sel >> b) & 1u) ? NEG_INF : sc;
            float m = vcur;
            for (int o = 16; o; o >>= 1) m = fmaxf(m, __shfl_xor_sync(0xffffffffu, m, o));
            unsigned ball = __ballot_sync(0xffffffffu, vcur == m);
            sel |= (1u << (__ffs(ball) - 1));
        }
        if (lane == 0) g_sel[t][kh] = sel;
    }

    // ---- pack P fragments ----
    uint32_t ph[8][4], pl[8][4];
#pragma unroll
    for (int kp = 0; kp < 8; kp++) {
        ph[kp][0] = pack2(s[2*kp][0],   s[2*kp][1],   pl[kp][0]);
        ph[kp][1] = pack2(s[2*kp][2],   s[2*kp][3],   pl[kp][1]);
        ph[kp][2] = pack2(s[2*kp+1][0], s[2*kp+1][1], pl[kp][2]);
        ph[kp][3] = pack2(s[2*kp+1][2], s[2*kp+1][3], pl[kp][3]);
    }

    CP_WAIT0();
    __syncthreads();

    // ---- PV: O_cmp = P * cmp_v (3-term) ----
    float Oc[16][4];
#pragma unroll
    for (int i = 0; i < 16; i++)
#pragma unroll
        for (int c = 0; c < 4; c++) Oc[i][c] = 0.f;
#pragma unroll
    for (int kp = 0; kp < 8; kp++) {
        int keyv = kp * 16 + (grp & 1) * 8 + (lane & 7);
        uint32_t kb = (uint32_t)keyv * 256u, rxv = (uint32_t)(keyv & 7);
#pragma unroll
        for (int dp = 0; dp < 8; dp++) {
            uint32_t c16 = (uint32_t)(dp * 2 + (grp >> 1));
            uint32_t off = kb + ((c16 ^ rxv) << 4);
            uint32_t vh[4], vl[4];
            ldsm4t(vh, sb + K2_VH + off);
            ldsm4t(vl, sb + K2_VL + off);
            mma16816(Oc[2*dp],   ph[kp], vh[0], vh[1]);
            mma16816(Oc[2*dp+1], ph[kp], vh[2], vh[3]);
            mma16816(Oc[2*dp],   pl[kp], vh[0], vh[1]);
            mma16816(Oc[2*dp+1], pl[kp], vh[2], vh[3]);
            mma16816(Oc[2*dp],   ph[kp], vl[0], vl[1]);
            mma16816(Oc[2*dp+1], ph[kp], vl[2], vl[3]);
        }
    }
#pragma unroll
    for (int nt = 0; nt < 16; nt++) {
        int d0 = nt * 8 + jcl;
        *reinterpret_cast<float2*>(&g_ocmp[t_a][h][d0]) = make_float2(Oc[nt][0], Oc[nt][1]);
        *reinterpret_cast<float2*>(&g_ocmp[t_b][h][d0]) = make_float2(Oc[nt][2], Oc[nt][3]);
    }
}

// ---------------- K3: HMMA fused slc+win attention (cp.async pipelined) ----------------
#define SQHI 0
#define SQLO 32768
#define SBUF 65536
#define BUFSZ 65536
#define KHIO 0
#define KLOO 16384
#define VHIO 32768
#define VLOO 49152
#define SMTOT 196608

__global__ __launch_bounds__(256, 1) void k3_main(
    const float* __restrict__ q, const float* __restrict__ w,
    float* __restrict__ out)
{
    extern __shared__ char smem[];
    uint32_t sbb_ = smem_u32(smem);
    int tid = threadIdx.x;
    int wp = tid >> 5, lane = tid & 31;
    int tile = (int)gridDim.x - 1 - (int)blockIdx.x;
    int t0 = tile * TQ;
    int kh = blockIdx.y;

    __shared__ int s_list[36];
    __shared__ int s_n;
    __shared__ unsigned s_union;

    int g = lane >> 2;
    int t_a = t0 + 2 * wp;
    int t_b = t_a + 1;
    int h = kh * GQ + g;

    unsigned selm_a = g_sel[t_a][kh], selm_b = g_sel[t_b][kh];
    if (tid == 0) s_union = 0u;
    __syncthreads();
    if (lane == 0) atomicOr(&s_union, selm_a | selm_b);

    for (int i = tid; i < 128 * 16; i += 256) {
        int row = i >> 4, c16 = i & 15;
        int qrow = (t0 + (row >> 3)) * H_HEADS + kh * GQ + (row & 7);
        uint32_t off = (uint32_t)row * 256u + (uint32_t)((c16 ^ (row & 7)) << 4);
        CP_ASYNC16(sbb_ + SQHI + off, g_qhi + (size_t)qrow * DDIM + c16 * 8);
        CP_ASYNC16(sbb_ + SQLO + off, g_qmi + (size_t)qrow * DDIM + c16 * 8);
    }

    float kmax = __uint_as_float(g_kmax[kh]);
    float Ua, Ub;
    {
        const float4* q4 = reinterpret_cast<const float4*>(q);
        float s2 = 0.f;
        const float4* qr = q4 + ((size_t)(t_a * H_HEADS + h)) * 32;
#pragma unroll 8
        for (int d4 = 0; d4 < 32; d4++) { float4 a = qr[d4]; s2 += a.x*a.x + a.y*a.y + a.z*a.z + a.w*a.w; }
        Ua = SCALE_F * sqrtf(s2) * kmax;
        s2 = 0.f;
        qr = q4 + ((size_t)(t_b * H_HEADS + h)) * 32;
#pragma unroll 8
        for (int d4 = 0; d4 < 32; d4++) { float4 a = qr[d4]; s2 += a.x*a.x + a.y*a.y + a.z*a.z + a.w*a.w; }
        Ub = SCALE_F * sqrtf(s2) * kmax;
    }

    __syncthreads();
    unsigned selu = s_union;
    int t_blk = t0 >> 6;

    if (tid == 0) {
        int n = 0;
        for (int b = 0; b <= t_blk; b++) {
            bool need = ((selu >> b) & 1u) || (b * 64 + 63 >= t0 - 511);
            if (need) s_list[n++] = b;
        }
        s_n = n;
    }
    __syncthreads();
    int nch = s_n;

    const __nv_bfloat16* khbase = g_khi + (size_t)kh * T_LEN * DDIM;
    const __nv_bfloat16* klbase = g_klo + (size_t)kh * T_LEN * DDIM;
    const __nv_bfloat16* vhbase = g_vhi + (size_t)kh * T_LEN * DDIM;
    const __nv_bfloat16* vlbase = g_vlo + (size_t)kh * T_LEN * DDIM;

    {
        int b0 = s_list[0];
        for (int i = tid; i < 1024; i += 256) {
            int row = i >> 4, c16 = i & 15;
            size_t src = (size_t)(b0 * 64 + row) * DDIM + c16 * 8;
            uint32_t dst = sbb_ + SBUF + ((uint32_t)row * 256u + (uint32_t)((c16 ^ (row & 7)) << 4));
            CP_ASYNC16(dst + KHIO, khbase + src);
            CP_ASYNC16(dst + KLOO, klbase + src);
            CP_ASYNC16(dst + VHIO, vhbase + src);
            CP_ASYNC16(dst + VLOO, vlbase + src);
        }
    }
    CP_COMMIT();

    float Os[16][4], Ow[16][4];
#pragma unroll
    for (int i = 0; i < 16; i++)
#pragma unroll
        for (int c = 0; c < 4; c++) { Os[i][c] = 0.f; Ow[i][c] = 0.f; }
    float sum_sa = 0.f, sum_sb = 0.f, sum_wa = 0.f, sum_wb = 0.f;

    int jcl = (lane & 3) * 2;
    int grp = lane >> 3;

    for (int ci = 0; ci < nch; ci++) {
        int b = s_list[ci];
        bool do_s = (selu >> b) & 1u;
        bool do_w = (b * 64 + 63 >= t0 - 511);
        uint32_t KB = sbb_ + SBUF + (uint32_t)(ci & 1) * BUFSZ;

        CP_WAIT0();
        __syncthreads();

        if (ci + 1 < nch) {
            int bn = s_list[ci + 1];
            uint32_t NB = sbb_ + SBUF + (uint32_t)((ci + 1) & 1) * BUFSZ;
            for (int i = tid; i < 1024; i += 256) {
                int row = i >> 4, c16 = i & 15;
                size_t src = (size_t)(bn * 64 + row) * DDIM + c16 * 8;
                uint32_t dst = NB + ((uint32_t)row * 256u + (uint32_t)((c16 ^ (row & 7)) << 4));
                CP_ASYNC16(dst + KHIO, khbase + src);
                CP_ASYNC16(dst + KLOO, klbase + src);
                CP_ASYNC16(dst + VHIO, vhbase + src);
                CP_ASYNC16(dst + VLOO, vlbase + src);
            }
            CP_COMMIT();
        }

        uint32_t ah[8][4];
        {
            int row = 16 * wp + (grp & 1) * 8 + (lane & 7);
            uint32_t rbase = (uint32_t)row * 256u, rx = (uint32_t)(row & 7);
#pragma unroll
            for (int kt = 0; kt < 8; kt++) {
                uint32_t c16 = (uint32_t)(kt * 2 + (grp >> 1));
                ldsm4(ah[kt], sbb_ + SQHI + rbase + ((c16 ^ rx) << 4));
            }
        }

#pragma unroll
        for (int np = 0; np < 4; np++) {
            float s0[4] = {0.f, 0.f, 0.f, 0.f}, s1[4] = {0.f, 0.f, 0.f, 0.f};
            {
                int keyq = np * 16 + (grp >> 1) * 8 + (lane & 7);
                uint32_t kb = (uint32_t)keyq * 256u, rxk = (uint32_t)(keyq & 7);
                int rowq = 16 * wp + (grp & 1) * 8 + (lane & 7);
                uint32_t rb = (uint32_t)rowq * 256u, rxq = (uint32_t)(rowq & 7);
#pragma unroll
                for (int kt = 0; kt < 8; kt++) {
                    uint32_t ck = (uint32_t)(kt * 2 + (grp & 1));
                    uint32_t cq = (uint32_t)(kt * 2 + (grp >> 1));
                    uint32_t bh[4], bl[4], alr[4];
                    ldsm4(bh, KB + KHIO + kb + ((ck ^ rxk) << 4));
                    ldsm4(bl, KB + KLOO + kb + ((ck ^ rxk) << 4));
                    ldsm4(alr, sbb_ + SQLO + rb + ((cq ^ rxq) << 4));
                    mma16816(s0, ah[kt], bh[0], bh[1]);
                    mma16816(s1, ah[kt], bh[2], bh[3]);
                    mma16816(s0, ah[kt], bl[0], bl[1]);
                    mma16816(s1, ah[kt], bl[2], bl[3]);
                    mma16816(s0, alr, bh[0], bh[1]);
                    mma16816(s1, alr, bh[2], bh[3]);
                }
            }
            int j0 = b * 64 + np * 16 + jcl;
            float ea0 = __expf(s0[0] * SCALE_F - Ua);
            float ea1 = __expf(s0[1] * SCALE_F - Ua);
            float eb0 = __expf(s0[2] * SCALE_F - Ub);
            float eb1 = __expf(s0[3] * SCALE_F - Ub);
            float fa0 = __expf(s1[0] * SCALE_F - Ua);
            float fa1 = __expf(s1[1] * SCALE_F - Ua);
            float fb0 = __expf(s1[2] * SCALE_F - Ub);
            float fb1 = __expf(s1[3] * SCALE_F - Ub);
            bool sa = (selm_a >> b) & 1u, sb2 = (selm_b >> b) & 1u;
            int j1 = j0 + 1, j8 = j0 + 8, j9 = j0 + 9;

            float esa0 = (sa  && j0 <= t_a) ? ea0 : 0.f;
            float esa1 = (sa  && j1 <= t_a) ? ea1 : 0.f;
            float esb0 = (sb2 && j0 <= t_b) ? eb0 : 0.f;
            float esb1 = (sb2 && j1 <= t_b) ? eb1 : 0.f;
            float fsa0 = (sa  && j8 <= t_a) ? fa0 : 0.f;
            float fsa1 = (sa  && j9 <= t_a) ? fa1 : 0.f;
            float fsb0 = (sb2 && j8 <= t_b) ? fb0 : 0.f;
            float fsb1 = (sb2 && j9 <= t_b) ? fb1 : 0.f;

            float ewa0 = (j0 <= t_a && t_a - j0 < 512) ? ea0 : 0.f;
            float ewa1 = (j1 <= t_a && t_a - j1 < 512) ? ea1 : 0.f;
            float ewb0 = (j0 <= t_b && t_b - j0 < 512) ? eb0 : 0.f;
            float ewb1 = (j1 <= t_b && t_b - j1 < 512) ? eb1 : 0.f;
            float fwa0 = (j8 <= t_a && t_a - j8 < 512) ? fa0 : 0.f;
            float fwa1 = (j9 <= t_a && t_a - j9 < 512) ? fa1 : 0.f;
            float fwb0 = (j8 <= t_b && t_b - j8 < 512) ? fb0 : 0.f;
            float fwb1 = (j9 <= t_b && t_b - j9 < 512) ? fb1 : 0.f;

            sum_sa += esa0 + esa1 + fsa0 + fsa1;
            sum_sb += esb0 + esb1 + fsb0 + fsb1;
            sum_wa += ewa0 + ewa1 + fwa0 + fwa1;
            sum_wb += ewb0 + ewb1 + fwb0 + fwb1;

            uint32_t psh[4], psl[4], pwh[4], pwl[4];
            psh[0] = pack2(esa0, esa1, psl[0]);
            psh[1] = pack2(esb0, esb1, psl[1]);
            psh[2] = pack2(fsa0, fsa1, psl[2]);
            psh[3] = pack2(fsb0, fsb1, psl[3]);
            pwh[0] = pack2(ewa0, ewa1, pwl[0]);
            pwh[1] = pack2(ewb0, ewb1, pwl[1]);
            pwh[2] = pack2(fwa0, fwa1, pwl[2]);
            pwh[3] = pack2(fwb0, fwb1, pwl[3]);

            {
                int keyv = np * 16 + (grp & 1) * 8 + (lane & 7);
                uint32_t kb = (uint32_t)keyv * 256u, rxv = (uint32_t)(keyv & 7);
#pragma unroll
                for (int dp = 0; dp < 8; dp++) {
                    uint32_t c16 = (uint32_t)(dp * 2 + (grp >> 1));
                    uint32_t off = kb + ((c16 ^ rxv) << 4);
                    uint32_t vh[4], vl[4];
                    ldsm4t(vh, KB + VHIO + off);
                    ldsm4t(vl, KB + VLOO + off);
                    if (do_s) {
                        mma16816(Os[2 * dp],     psh, vh[0], vh[1]);
                        mma16816(Os[2 * dp + 1], psh, vh[2], vh[3]);
                        mma16816(Os[2 * dp],     psl, vh[0], vh[1]);
                        mma16816(Os[2 * dp + 1], psl, vh[2], vh[3]);
                        mma16816(Os[2 * dp],     psh, vl[0], vl[1]);
                        mma16816(Os[2 * dp + 1], psh, vl[2], vl[3]);
                    }
                    if (do_w) {
                        mma16816(Ow[2 * dp],     pwh, vh[0], vh[1]);
                        mma16816(Ow[2 * dp + 1], pwh, vh[2], vh[3]);
                        mma16816(Ow[2 * dp],     pwl, vh[0], vh[1]);
                        mma16816(Ow[2 * dp + 1], pwl, vh[2], vh[3]);
                        mma16816(Ow[2 * dp],     pwh, vl[0], vl[1]);
                        mma16816(Ow[2 * dp + 1], pwh, vl[2], vl[3]);
                    }
                }
            }
        }
    }

#pragma unroll
    for (int o = 1; o <= 2; o <<= 1) {
        sum_sa += __shfl_xor_sync(0xffffffffu, sum_sa, o);
        sum_sb += __shfl_xor_sync(0xffffffffu, sum_sb, o);
        sum_wa += __shfl_xor_sync(0xffffffffu, sum_wa, o);
        sum_wb += __shfl_xor_sync(0xffffffffu, sum_wb, o);
    }
    float inv_sa = 1.f / sum_sa, inv_sb = 1.f / sum_sb;
    float inv_wa = 1.f / sum_wa, inv_wb = 1.f / sum_wb;

    const float* wa = w + ((size_t)(t_a * H_HEADS + h)) * 3;
    const float* wb = w + ((size_t)(t_b * H_HEADS + h)) * 3;
    float w0a = wa[0], w1a = wa[1], w2a = wa[2];
    float w0b = wb[0], w1b = wb[1], w2b = wb[2];

#pragma unroll
    for (int nt = 0; nt < 16; nt++) {
        int d0 = nt * 8 + jcl;
        const float2* ca = reinterpret_cast<const float2*>(&g_ocmp[t_a][h][d0]);
        const float2* cb = reinterpret_cast<const float2*>(&g_ocmp[t_b][h][d0]);
        float2 oc_a = *ca, oc_b = *cb;
        float2 oa, ob;
        oa.x = w0a * oc_a.x + w1a * Os[nt][0] * inv_sa + w2a * Ow[nt][0] * inv_wa;
        oa.y = w0a * oc_a.y + w1a * Os[nt][1] * inv_sa + w2a * Ow[nt][1] * inv_wa;
        ob.x = w0b * oc_b.x + w1b * Os[nt][2] * inv_sb + w2b * Ow[nt][2] * inv_wb;
        ob.y = w0b * oc_b.y + w1b * Os[nt][3] * inv_sb + w2b * Ow[nt][3] * inv_wb;
        *reinterpret_cast<float2*>(out + ((size_t)(t_a * H_HEADS + h)) * DDIM + d0) = oa;
        *reinterpret_cast<float2*>(out + ((size_t)(t_b * H_HEADS + h)) * DDIM + d0) = ob;
    }
}

// ---------------- launch ----------------
extern "C" void kernel_launch(void* const* d_in, const int* in_sizes, int n_in,
                              void* d_out, int out_size) {
    const float* q = (const float*)d_in[0];
    const float* k = (const float*)d_in[1];
    const float* v = (const float*)d_in[2];
    const float* w = (const float*)d_in[3];
    float* out = (float*)d_out;

    cudaFuncSetAttribute(k2_tc, cudaFuncAttributeMaxDynamicSharedMemorySize, K2_TOT);
    cudaFuncSetAttribute(k3_main, cudaFuncAttributeMaxDynamicSharedMemorySize, SMTOT);

    k0_split<<<1024, 256>>>(q, k, v);
    k1_compress<<<dim3(NCMP, KHN), DDIM>>>(k, v);
    k1b_knorm<<<dim3(T_LEN, KHN), 32>>>(k);
    k2_tc<<<dim3(T_LEN / TQ, KHN), 256, K2_TOT>>>();
    k3_main<<<dim3(T_LEN / TQ, KHN), 256, SMTOT>>>(q, w, out);
}

// round 7
// speedup vs baseline: 5.2968x; 1.2407x over previous
#include <cuda_runtime.h>
#include <cuda_bf16.h>
#include <cuda_fp16.h>
#include <math.h>
#include <stdint.h>

#define T_LEN 2048
#define H_HEADS 16
#define KHN 2
#define GQ 8
#define DDIM 128
#define NCMP 127
#define NBLK 32
#define TQ 16
#define SCALE_F 0.08838834765f
#define EXP_SHIFT 10.3972077f   /* ln(2^15) */
#define NEG_INF (-INFINITY)

// ---------------- scratch ----------------
__device__ float g_ocmp[T_LEN][H_HEADS][DDIM];
__device__ unsigned g_sel[T_LEN][KHN];
__device__ unsigned g_kmax[KHN];

// bf16 3-split q + compressed tensors (k2 path, selection-critical — unchanged)
__device__ __align__(16) __nv_bfloat16 g_qhi[T_LEN * H_HEADS * DDIM];
__device__ __align__(16) __nv_bfloat16 g_qmi[T_LEN * H_HEADS * DDIM];
__device__ __align__(16) __nv_bfloat16 g_qlo[T_LEN * H_HEADS * DDIM];
__device__ __align__(16) __nv_bfloat16 g_ckhi[KHN][128][DDIM];
__device__ __align__(16) __nv_bfloat16 g_ckmi[KHN][128][DDIM];
__device__ __align__(16) __nv_bfloat16 g_cklo[KHN][128][DDIM];
__device__ __align__(16) __nv_bfloat16 g_cvhi[KHN][128][DDIM];
__device__ __align__(16) __nv_bfloat16 g_cvlo[KHN][128][DDIM];
// fp16 2-split q/k/v (k3 path)
__device__ __align__(16) __half g_qh16[T_LEN * H_HEADS * DDIM];
__device__ __align__(16) __half g_ql16[T_LEN * H_HEADS * DDIM];
__device__ __align__(16) __half g_kh16[KHN * T_LEN * DDIM];
__device__ __align__(16) __half g_kl16[KHN * T_LEN * DDIM];
__device__ __align__(16) __half g_vh16[KHN * T_LEN * DDIM];
__device__ __align__(16) __half g_vl16[KHN * T_LEN * DDIM];

// ---------------- helpers ----------------
__device__ __forceinline__ uint32_t smem_u32(const void* p) {
    uint32_t a;
    asm("{ .reg .u64 t; cvta.to.shared.u64 t, %1; cvt.u32.u64 %0, t; }" : "=r"(a) : "l"(p));
    return a;
}
__device__ __forceinline__ void mma16816(float* d, const uint32_t* a, uint32_t b0, uint32_t b1) {
    asm volatile("mma.sync.aligned.m16n8k16.row.col.f32.bf16.bf16.f32 "
        "{%0,%1,%2,%3},{%4,%5,%6,%7},{%8,%9},{%0,%1,%2,%3};"
        : "+f"(d[0]), "+f"(d[1]), "+f"(d[2]), "+f"(d[3])
        : "r"(a[0]), "r"(a[1]), "r"(a[2]), "r"(a[3]), "r"(b0), "r"(b1));
}
__device__ __forceinline__ void mma16816h(float* d, const uint32_t* a, uint32_t b0, uint32_t b1) {
    asm volatile("mma.sync.aligned.m16n8k16.row.col.f32.f16.f16.f32 "
        "{%0,%1,%2,%3},{%4,%5,%6,%7},{%8,%9},{%0,%1,%2,%3};"
        : "+f"(d[0]), "+f"(d[1]), "+f"(d[2]), "+f"(d[3])
        : "r"(a[0]), "r"(a[1]), "r"(a[2]), "r"(a[3]), "r"(b0), "r"(b1));
}
__device__ __forceinline__ void ldsm4(uint32_t* r, uint32_t addr) {
    asm volatile("ldmatrix.sync.aligned.m8n8.x4.shared.b16 {%0,%1,%2,%3}, [%4];"
        : "=r"(r[0]), "=r"(r[1]), "=r"(r[2]), "=r"(r[3]) : "r"(addr));
}
__device__ __forceinline__ void ldsm4t(uint32_t* r, uint32_t addr) {
    asm volatile("ldmatrix.sync.aligned.m8n8.x4.trans.shared.b16 {%0,%1,%2,%3}, [%4];"
        : "=r"(r[0]), "=r"(r[1]), "=r"(r[2]), "=r"(r[3]) : "r"(addr));
}
__device__ __forceinline__ uint32_t pack2(float a, float b, uint32_t& lo) {
    __nv_bfloat16 ah = __float2bfloat16_rn(a), bh = __float2bfloat16_rn(b);
    __nv_bfloat16 al = __float2bfloat16_rn(a - __bfloat162float(ah));
    __nv_bfloat16 bl = __float2bfloat16_rn(b - __bfloat162float(bh));
    lo = ((uint32_t)__bfloat16_as_ushort(bl) << 16) | (uint32_t)__bfloat16_as_ushort(al);
    return ((uint32_t)__bfloat16_as_ushort(bh) << 16) | (uint32_t)__bfloat16_as_ushort(ah);
}
__device__ __forceinline__ uint32_t packh2(float a, float b) {
    __half2 h = __floats2half2_rn(a, b);
    return *reinterpret_cast<uint32_t*>(&h);
}
#define CP_ASYNC16(dst, src) \
    asm volatile("cp.async.cg.shared.global [%0], [%1], 16;" :: "r"(dst), "l"(src) : "memory")
#define CP_COMMIT() asm volatile("cp.async.commit_group;" ::: "memory")
#define CP_WAIT0()  asm volatile("cp.async.wait_group 0;" ::: "memory")

// ---------------- K0: pre-split q (bf16 3-way + fp16 2-way), k/v (fp16 2-way) ----------------
__global__ void k0_split(const float* __restrict__ q, const float* __restrict__ k,
                         const float* __restrict__ v) {
    int stride = gridDim.x * blockDim.x;
    int idx = blockIdx.x * blockDim.x + threadIdx.x;
    const int n_kv = T_LEN * KHN * DDIM;
    for (int i = idx; i < n_kv; i += stride) {
        int d = i & (DDIM - 1);
        int tk = i >> 7;
        int kh = tk & 1, t = tk >> 1;
        int o = (kh * T_LEN + t) * DDIM + d;
        float x = k[i];
        __half h = __float2half_rn(x);
        g_kh16[o] = h;
        g_kl16[o] = __float2half_rn(x - __half2float(h));
        x = v[i];
        h = __float2half_rn(x);
        g_vh16[o] = h;
        g_vl16[o] = __float2half_rn(x - __half2float(h));
    }
    const int n_q = T_LEN * H_HEADS * DDIM;
    for (int i = idx; i < n_q; i += stride) {
        float x = q[i];
        __nv_bfloat16 bh = __float2bfloat16_rn(x);
        float r1 = x - __bfloat162float(bh);
        __nv_bfloat16 bm = __float2bfloat16_rn(r1);
        g_qhi[i] = bh;
        g_qmi[i] = bm;
        g_qlo[i] = __float2bfloat16_rn(r1 - __bfloat162float(bm));
        __half hh = __float2half_rn(x);
        g_qh16[i] = hh;
        g_ql16[i] = __float2half_rn(x - __half2float(hh));
    }
}

// ---------------- K1: compressed K/V + splits ----------------
__global__ void k1_compress(const float* __restrict__ k, const float* __restrict__ v) {
    int j = blockIdx.x, kh = blockIdx.y, d = threadIdx.x;
    int s = j * 16;
    float sk = 0.f, sv = 0.f;
#pragma unroll 8
    for (int i = 0; i < 32; i++) {
        sk += k[((size_t)(s + i) * KHN + kh) * DDIM + d];
        sv += v[((size_t)(s + i) * KHN + kh) * DDIM + d];
    }
    float ck = sk * (1.f / 32.f), cv = sv * (1.f / 32.f);
    __nv_bfloat16 h = __float2bfloat16_rn(ck);
    float r1 = ck - __bfloat162float(h);
    __nv_bfloat16 m = __float2bfloat16_rn(r1);
    g_ckhi[kh][j][d] = h;
    g_ckmi[kh][j][d] = m;
    g_cklo[kh][j][d] = __float2bfloat16_rn(r1 - __bfloat162float(m));
    h = __float2bfloat16_rn(cv);
    g_cvhi[kh][j][d] = h;
    g_cvlo[kh][j][d] = __float2bfloat16_rn(cv - __bfloat162float(h));
}

// ---------------- K1b: max ||k_row|| per kv head ----------------
__global__ void k1b_knorm(const float* __restrict__ k) {
    int t = blockIdx.x, kh = blockIdx.y, lane = threadIdx.x;
    const float4* kr = reinterpret_cast<const float4*>(k) + ((size_t)t * KHN + kh) * 32;
    float4 a = kr[lane];
    float s = a.x * a.x + a.y * a.y + a.z * a.z + a.w * a.w;
    for (int o = 16; o; o >>= 1) s += __shfl_xor_sync(0xffffffffu, s, o);
    if (lane == 0) atomicMax(&g_kmax[kh], __float_as_uint(sqrtf(s)));
}

// ---------------- K2: tensor-core compressed attention + selection (unchanged) ----------------
#define K2_QH 0
#define K2_QM 32768
#define K2_QL 65536
#define K2_CKH 98304
#define K2_CKM 131072
#define K2_CKL 163840
#define K2_PS  196608
#define K2_TOT 204800
#define K2_VH 0
#define K2_VL 32768

__global__ __launch_bounds__(256, 1) void k2_tc() {
    extern __shared__ char smem[];
    uint32_t sb = smem_u32(smem);
    float* psum_sh = reinterpret_cast<float*>(smem + K2_PS);
    int tid = threadIdx.x;
    int wp = tid >> 5, lane = tid & 31;
    int t0 = blockIdx.x * TQ;
    int kh = blockIdx.y;
    int grp = lane >> 3;
    int jcl = (lane & 3) * 2;

    for (int i = tid; i < 128 * 16; i += 256) {
        int row = i >> 4, c16 = i & 15;
        uint32_t off = (uint32_t)row * 256u + (uint32_t)((c16 ^ (row & 7)) << 4);
        int qrow = (t0 + (row >> 3)) * H_HEADS + kh * GQ + (row & 7);
        CP_ASYNC16(sb + K2_QH + off, g_qhi + (size_t)qrow * DDIM + c16 * 8);
        CP_ASYNC16(sb + K2_QM + off, g_qmi + (size_t)qrow * DDIM + c16 * 8);
        CP_ASYNC16(sb + K2_QL + off, g_qlo + (size_t)qrow * DDIM + c16 * 8);
        CP_ASYNC16(sb + K2_CKH + off, &g_ckhi[kh][row][c16 * 8]);
        CP_ASYNC16(sb + K2_CKM + off, &g_ckmi[kh][row][c16 * 8]);
        CP_ASYNC16(sb + K2_CKL + off, &g_cklo[kh][row][c16 * 8]);
    }
    CP_COMMIT();
    CP_WAIT0();
    __syncthreads();

    int t_a = t0 + 2 * wp;
    int t_b = t_a + 1;
    int g = lane >> 2;
    int h = kh * GQ + g;
    int nva = (t_a >= 31) ? ((t_a - 31) / 16 + 1) : 0;
    int nvb = (t_b >= 31) ? ((t_b - 31) / 16 + 1) : 0;

    float s[16][4];
#pragma unroll
    for (int i = 0; i < 16; i++)
#pragma unroll
        for (int c = 0; c < 4; c++) s[i][c] = 0.f;

    uint32_t ah[8][4], am[8][4];
    {
        int row = 16 * wp + (grp & 1) * 8 + (lane & 7);
        uint32_t rb = (uint32_t)row * 256u, rx = (uint32_t)(row & 7);
#pragma unroll
        for (int kt = 0; kt < 8; kt++) {
            uint32_t cq = (uint32_t)(kt * 2 + (grp >> 1));
            uint32_t ao = rb + ((cq ^ rx) << 4);
            ldsm4(ah[kt], sb + K2_QH + ao);
            ldsm4(am[kt], sb + K2_QM + ao);
        }
    }
#pragma unroll
    for (int np = 0; np < 8; np++) {
        int keyq = np * 16 + (grp >> 1) * 8 + (lane & 7);
        uint32_t kb = (uint32_t)keyq * 256u, rxk = (uint32_t)(keyq & 7);
        int rowq = 16 * wp + (grp & 1) * 8 + (lane & 7);
        uint32_t rq = (uint32_t)rowq * 256u, rxq = (uint32_t)(rowq & 7);
#pragma unroll
        for (int kt = 0; kt < 8; kt++) {
            uint32_t ck = (uint32_t)(kt * 2 + (grp & 1));
            uint32_t bo = kb + ((ck ^ rxk) << 4);
            uint32_t cq = (uint32_t)(kt * 2 + (grp >> 1));
            uint32_t bh[4], bm[4], bl[4], al[4];
            ldsm4(bh, sb + K2_CKH + bo);
            ldsm4(bm, sb + K2_CKM + bo);
            ldsm4(bl, sb + K2_CKL + bo);
            ldsm4(al, sb + K2_QL + rq + ((cq ^ rxq) << 4));
            mma16816(s[2*np],   ah[kt], bh[0], bh[1]);
            mma16816(s[2*np+1], ah[kt], bh[2], bh[3]);
            mma16816(s[2*np],   ah[kt], bm[0], bm[1]);
            mma16816(s[2*np+1], ah[kt], bm[2], bm[3]);
            mma16816(s[2*np],   ah[kt], bl[0], bl[1]);
            mma16816(s[2*np+1], ah[kt], bl[2], bl[3]);
            mma16816(s[2*np],   am[kt], bh[0], bh[1]);
            mma16816(s[2*np+1], am[kt], bh[2], bh[3]);
            mma16816(s[2*np],   am[kt], bm[0], bm[1]);
            mma16816(s[2*np+1], am[kt], bm[2], bm[3]);
            mma16816(s[2*np],   al,     bh[0], bh[1]);
            mma16816(s[2*np+1], al,     bh[2], bh[3]);
        }
    }
    __syncthreads();

    for (int i = tid; i < 128 * 16; i += 256) {
        int row = i >> 4, c16 = i & 15;
        uint32_t off = (uint32_t)row * 256u + (uint32_t)((c16 ^ (row & 7)) << 4);
        CP_ASYNC16(sb + K2_VH + off, &g_cvhi[kh][row][c16 * 8]);
        CP_ASYNC16(sb + K2_VL + off, &g_cvlo[kh][row][c16 * 8]);
    }
    CP_COMMIT();

    float ma = NEG_INF, mb = NEG_INF;
#pragma unroll
    for (int nt = 0; nt < 16; nt++) {
        int j0 = nt * 8 + jcl;
        if (j0 < nva)     ma = fmaxf(ma, s[nt][0] * SCALE_F);
        if (j0 + 1 < nva) ma = fmaxf(ma, s[nt][1] * SCALE_F);
        if (j0 < nvb)     mb = fmaxf(mb, s[nt][2] * SCALE_F);
        if (j0 + 1 < nvb) mb = fmaxf(mb, s[nt][3] * SCALE_F);
    }
#pragma unroll
    for (int o = 1; o <= 2; o <<= 1) {
        ma = fmaxf(ma, __shfl_xor_sync(0xffffffffu, ma, o));
        mb = fmaxf(mb, __shfl_xor_sync(0xffffffffu, mb, o));
    }
    float la = 0.f, lb = 0.f;
#pragma unroll
    for (int nt = 0; nt < 16; nt++) {
        int j0 = nt * 8 + jcl;
        float e0 = (j0 < nva)     ? expf(s[nt][0] * SCALE_F - ma) : 0.f;
        float e1 = (j0 + 1 < nva) ? expf(s[nt][1] * SCALE_F - ma) : 0.f;
        float e2 = (j0 < nvb)     ? expf(s[nt][2] * SCALE_F - mb) : 0.f;
        float e3 = (j0 + 1 < nvb) ? expf(s[nt][3] * SCALE_F - mb) : 0.f;
        s[nt][0] = e0; s[nt][1] = e1; s[nt][2] = e2; s[nt][3] = e3;
        la += e0 + e1; lb += e2 + e3;
    }
#pragma unroll
    for (int o = 1; o <= 2; o <<= 1) {
        la += __shfl_xor_sync(0xffffffffu, la, o);
        lb += __shfl_xor_sync(0xffffffffu, lb, o);
    }
    float inva = (nva > 0) ? 1.f / la : 0.f;
    float invb = (nvb > 0) ? 1.f / lb : 0.f;
#pragma unroll
    for (int nt = 0; nt < 16; nt++) {
        s[nt][0] *= inva; s[nt][1] *= inva;
        s[nt][2] *= invb; s[nt][3] *= invb;
    }

#pragma unroll
    for (int nt = 0; nt < 16; nt++) {
        float a0 = s[nt][0], a1 = s[nt][1], b0 = s[nt][2], b1 = s[nt][3];
#pragma unroll
        for (int o = 4; o <= 16; o <<= 1) {
            a0 += __shfl_xor_sync(0xffffffffu, a0, o);
            a1 += __shfl_xor_sync(0xffffffffu, a1, o);
            b0 += __shfl_xor_sync(0xffffffffu, b0, o);
            b1 += __shfl_xor_sync(0xffffffffu, b1, o);
        }
        if (lane < 4) {
            int j = nt * 8 + lane * 2;
            psum_sh[(2 * wp) * 128 + j] = a0;
            psum_sh[(2 * wp) * 128 + j + 1] = a1;
            psum_sh[(2 * wp + 1) * 128 + j] = b0;
            psum_sh[(2 * wp + 1) * 128 + j + 1] = b1;
        }
    }
    __syncthreads();

#pragma unroll
    for (int rep = 0; rep < 2; rep++) {
        int t = t0 + 2 * wp + rep;
        int qi = 2 * wp + rep;
        int nv = (t >= 31) ? ((t - 31) / 16 + 1) : 0;
        int b = lane;
        int tb = t >> 6;
        bool forced = (b < 1) || ((b <= tb) && (b >= tb - 1));
        bool valid = (b * 64 <= t);
        float sc;
        if (!valid) sc = -1e30f;
        else if (forced) sc = 1e30f;
        else {
            int jlo = 4 * b - 1; if (jlo < 0) jlo = 0;
            int jhi = 4 * b + 3; if (jhi > nv - 1) jhi = nv - 1;
            float ss = 0.f;
            for (int j = jlo; j <= jhi; j++) ss += psum_sh[qi * 128 + j];
            sc = ss;
        }
        unsigned sel = 0u;
        for (int it = 0; it < 16; it++) {
            float vcur = ((sel >> b) & 1u) ? NEG_INF : sc;
            float m = vcur;
            for (int o = 16; o; o >>= 1) m = fmaxf(m, __shfl_xor_sync(0xffffffffu, m, o));
            unsigned ball = __ballot_sync(0xffffffffu, vcur == m);
            sel |= (1u << (__ffs(ball) - 1));
        }
        if (lane == 0) g_sel[t][kh] = sel;
    }

    uint32_t ph[8][4], pl[8][4];
#pragma unroll
    for (int kp = 0; kp < 8; kp++) {
        ph[kp][0] = pack2(s[2*kp][0],   s[2*kp][1],   pl[kp][0]);
        ph[kp][1] = pack2(s[2*kp][2],   s[2*kp][3],   pl[kp][1]);
        ph[kp][2] = pack2(s[2*kp+1][0], s[2*kp+1][1], pl[kp][2]);
        ph[kp][3] = pack2(s[2*kp+1][2], s[2*kp+1][3], pl[kp][3]);
    }

    CP_WAIT0();
    __syncthreads();

    float Oc[16][4];
#pragma unroll
    for (int i = 0; i < 16; i++)
#pragma unroll
        for (int c = 0; c < 4; c++) Oc[i][c] = 0.f;
#pragma unroll
    for (int kp = 0; kp < 8; kp++) {
        int keyv = kp * 16 + (grp & 1) * 8 + (lane & 7);
        uint32_t kb = (uint32_t)keyv * 256u, rxv = (uint32_t)(keyv & 7);
#pragma unroll
        for (int dp = 0; dp < 8; dp++) {
            uint32_t c16 = (uint32_t)(dp * 2 + (grp >> 1));
            uint32_t off = kb + ((c16 ^ rxv) << 4);
            uint32_t vh[4], vl[4];
            ldsm4t(vh, sb + K2_VH + off);
            ldsm4t(vl, sb + K2_VL + off);
            mma16816(Oc[2*dp],   ph[kp], vh[0], vh[1]);
            mma16816(Oc[2*dp+1], ph[kp], vh[2], vh[3]);
            mma16816(Oc[2*dp],   pl[kp], vh[0], vh[1]);
            mma16816(Oc[2*dp+1], pl[kp], vh[2], vh[3]);
            mma16816(Oc[2*dp],   ph[kp], vl[0], vl[1]);
            mma16816(Oc[2*dp+1], ph[kp], vl[2], vl[3]);
        }
    }
#pragma unroll
    for (int nt = 0; nt < 16; nt++) {
        int d0 = nt * 8 + jcl;
        *reinterpret_cast<float2*>(&g_ocmp[t_a][h][d0]) = make_float2(Oc[nt][0], Oc[nt][1]);
        *reinterpret_cast<float2*>(&g_ocmp[t_b][h][d0]) = make_float2(Oc[nt][2], Oc[nt][3]);
    }
}

// ---------------- K3: fp16 HMMA fused slc+win attention ----------------
#define SQHI 0
#define SQLO 32768
#define SBUF 65536
#define BUFSZ 65536
#define KHIO 0
#define KLOO 16384
#define VHIO 32768
#define VLOO 49152
#define SMTOT 196608

__global__ __launch_bounds__(256, 1) void k3_main(
    const float* __restrict__ q, const float* __restrict__ w,
    float* __restrict__ out)
{
    extern __shared__ char smem[];
    uint32_t sbb_ = smem_u32(smem);
    int tid = threadIdx.x;
    int wp = tid >> 5, lane = tid & 31;
    int tile = (int)gridDim.x - 1 - (int)blockIdx.x;
    int t0 = tile * TQ;
    int kh = blockIdx.y;

    __shared__ int s_list[36];
    __shared__ int s_n;
    __shared__ unsigned s_union;

    int g = lane >> 2;
    int t_a = t0 + 2 * wp;
    int t_b = t_a + 1;
    int h = kh * GQ + g;

    unsigned selm_a = g_sel[t_a][kh], selm_b = g_sel[t_b][kh];
    if (tid == 0) s_union = 0u;
    __syncthreads();
    if (lane == 0) atomicOr(&s_union, selm_a | selm_b);

    // stage Q (fp16 hi/lo, swizzled)
    for (int i = tid; i < 128 * 16; i += 256) {
        int row = i >> 4, c16 = i & 15;
        int qrow = (t0 + (row >> 3)) * H_HEADS + kh * GQ + (row & 7);
        uint32_t off = (uint32_t)row * 256u + (uint32_t)((c16 ^ (row & 7)) << 4);
        CP_ASYNC16(sbb_ + SQHI + off, g_qh16 + (size_t)qrow * DDIM + c16 * 8);
        CP_ASYNC16(sbb_ + SQLO + off, g_ql16 + (size_t)qrow * DDIM + c16 * 8);
    }

    float kmax = __uint_as_float(g_kmax[kh]);
    float Ua, Ub;
    {
        const float4* q4 = reinterpret_cast<const float4*>(q);
        float s2 = 0.f;
        const float4* qr = q4 + ((size_t)(t_a * H_HEADS + h)) * 32;
#pragma unroll 8
        for (int d4 = 0; d4 < 32; d4++) { float4 a = qr[d4]; s2 += a.x*a.x + a.y*a.y + a.z*a.z + a.w*a.w; }
        Ua = SCALE_F * sqrtf(s2) * kmax - EXP_SHIFT;
        s2 = 0.f;
        qr = q4 + ((size_t)(t_b * H_HEADS + h)) * 32;
#pragma unroll 8
        for (int d4 = 0; d4 < 32; d4++) { float4 a = qr[d4]; s2 += a.x*a.x + a.y*a.y + a.z*a.z + a.w*a.w; }
        Ub = SCALE_F * sqrtf(s2) * kmax - EXP_SHIFT;
    }

    __syncthreads();
    unsigned selu = s_union;
    int t_blk = t0 >> 6;

    if (tid == 0) {
        int n = 0;
        for (int b = 0; b <= t_blk; b++) {
            bool need = ((selu >> b) & 1u) || (b * 64 + 63 >= t0 - 511);
            if (need) s_list[n++] = b;
        }
        s_n = n;
    }
    __syncthreads();
    int nch = s_n;

    const __half* khbase = g_kh16 + (size_t)kh * T_LEN * DDIM;
    const __half* klbase = g_kl16 + (size_t)kh * T_LEN * DDIM;
    const __half* vhbase = g_vh16 + (size_t)kh * T_LEN * DDIM;
    const __half* vlbase = g_vl16 + (size_t)kh * T_LEN * DDIM;

    // prefetch first chunk
    {
        int b0 = s_list[0];
        for (int i = tid; i < 1024; i += 256) {
            int row = i >> 4, c16 = i & 15;
            size_t src = (size_t)(b0 * 64 + row) * DDIM + c16 * 8;
            uint32_t dst = sbb_ + SBUF + ((uint32_t)row * 256u + (uint32_t)((c16 ^ (row & 7)) << 4));
            CP_ASYNC16(dst + KHIO, khbase + src);
            CP_ASYNC16(dst + KLOO, klbase + src);
            CP_ASYNC16(dst + VHIO, vhbase + src);
            CP_ASYNC16(dst + VLOO, vlbase + src);
        }
    }
    CP_COMMIT();
    CP_WAIT0();
    __syncthreads();

    int jcl = (lane & 3) * 2;
    int grp = lane >> 3;

    // hoist Q-hi fragments (chunk-invariant)
    uint32_t ah[8][4];
    {
        int row = 16 * wp + (grp & 1) * 8 + (lane & 7);
        uint32_t rbase = (uint32_t)row * 256u, rx = (uint32_t)(row & 7);
#pragma unroll
        for (int kt = 0; kt < 8; kt++) {
            uint32_t c16 = (uint32_t)(kt * 2 + (grp >> 1));
            ldsm4(ah[kt], sbb_ + SQHI + rbase + ((c16 ^ rx) << 4));
        }
    }

    float Os[16][4], Ow[16][4];
#pragma unroll
    for (int i = 0; i < 16; i++)
#pragma unroll
        for (int c = 0; c < 4; c++) { Os[i][c] = 0.f; Ow[i][c] = 0.f; }
    float sum_sa = 0.f, sum_sb = 0.f, sum_wa = 0.f, sum_wb = 0.f;

    for (int ci = 0; ci < nch; ci++) {
        int b = s_list[ci];
        bool do_s = (selu >> b) & 1u;
        bool do_w = (b * 64 + 63 >= t0 - 511);
        uint32_t KB = sbb_ + SBUF + (uint32_t)(ci & 1) * BUFSZ;

        if (ci > 0) {
            CP_WAIT0();
            __syncthreads();
        }
        if (ci + 1 < nch) {
            int bn = s_list[ci + 1];
            uint32_t NB = sbb_ + SBUF + (uint32_t)((ci + 1) & 1) * BUFSZ;
            for (int i = tid; i < 1024; i += 256) {
                int row = i >> 4, c16 = i & 15;
                size_t src = (size_t)(bn * 64 + row) * DDIM + c16 * 8;
                uint32_t dst = NB + ((uint32_t)row * 256u + (uint32_t)((c16 ^ (row & 7)) << 4));
                CP_ASYNC16(dst + KHIO, khbase + src);
                CP_ASYNC16(dst + KLOO, klbase + src);
                CP_ASYNC16(dst + VHIO, vhbase + src);
                CP_ASYNC16(dst + VLOO, vlbase + src);
            }
            CP_COMMIT();
        }

#pragma unroll
        for (int np = 0; np < 4; np++) {
            float s0[4] = {0.f, 0.f, 0.f, 0.f}, s1[4] = {0.f, 0.f, 0.f, 0.f};
            {
                int keyq = np * 16 + (grp >> 1) * 8 + (lane & 7);
                uint32_t kb = (uint32_t)keyq * 256u, rxk = (uint32_t)(keyq & 7);
                int rowq = 16 * wp + (grp & 1) * 8 + (lane & 7);
                uint32_t rb = (uint32_t)rowq * 256u, rxq = (uint32_t)(rowq & 7);
#pragma unroll
                for (int kt = 0; kt < 8; kt++) {
                    uint32_t ck = (uint32_t)(kt * 2 + (grp & 1));
                    uint32_t cq = (uint32_t)(kt * 2 + (grp >> 1));
                    uint32_t bh[4], bl[4], alr[4];
                    ldsm4(bh, KB + KHIO + kb + ((ck ^ rxk) << 4));
                    ldsm4(bl, KB + KLOO + kb + ((ck ^ rxk) << 4));
                    ldsm4(alr, sbb_ + SQLO + rb + ((cq ^ rxq) << 4));
                    mma16816h(s0, ah[kt], bh[0], bh[1]);
                    mma16816h(s1, ah[kt], bh[2], bh[3]);
                    mma16816h(s0, ah[kt], bl[0], bl[1]);
                    mma16816h(s1, ah[kt], bl[2], bl[3]);
                    mma16816h(s0, alr, bh[0], bh[1]);
                    mma16816h(s1, alr, bh[2], bh[3]);
                }
            }
            int j0 = b * 64 + np * 16 + jcl;
            float ea0 = __expf(s0[0] * SCALE_F - Ua);
            float ea1 = __expf(s0[1] * SCALE_F - Ua);
            float eb0 = __expf(s0[2] * SCALE_F - Ub);
            float eb1 = __expf(s0[3] * SCALE_F - Ub);
            float fa0 = __expf(s1[0] * SCALE_F - Ua);
            float fa1 = __expf(s1[1] * SCALE_F - Ua);
            float fb0 = __expf(s1[2] * SCALE_F - Ub);
            float fb1 = __expf(s1[3] * SCALE_F - Ub);
            bool sa = (selm_a >> b) & 1u, sb2 = (selm_b >> b) & 1u;
            int j1 = j0 + 1, j8 = j0 + 8, j9 = j0 + 9;

            float esa0 = (sa  && j0 <= t_a) ? ea0 : 0.f;
            float esa1 = (sa  && j1 <= t_a) ? ea1 : 0.f;
            float esb0 = (sb2 && j0 <= t_b) ? eb0 : 0.f;
            float esb1 = (sb2 && j1 <= t_b) ? eb1 : 0.f;
            float fsa0 = (sa  && j8 <= t_a) ? fa0 : 0.f;
            float fsa1 = (sa  && j9 <= t_a) ? fa1 : 0.f;
            float fsb0 = (sb2 && j8 <= t_b) ? fb0 : 0.f;
            float fsb1 = (sb2 && j9 <= t_b) ? fb1 : 0.f;

            float ewa0 = (j0 <= t_a && t_a - j0 < 512) ? ea0 : 0.f;
            float ewa1 = (j1 <= t_a && t_a - j1 < 512) ? ea1 : 0.f;
            float ewb0 = (j0 <= t_b && t_b - j0 < 512) ? eb0 : 0.f;
            float ewb1 = (j1 <= t_b && t_b - j1 < 512) ? eb1 : 0.f;
            float fwa0 = (j8 <= t_a && t_a - j8 < 512) ? fa0 : 0.f;
            float fwa1 = (j9 <= t_a && t_a - j9 < 512) ? fa1 : 0.f;
            float fwb0 = (j8 <= t_b && t_b - j8 < 512) ? fb0 : 0.f;
            float fwb1 = (j9 <= t_b && t_b - j9 < 512) ? fb1 : 0.f;

            sum_sa += esa0 + esa1 + fsa0 + fsa1;
            sum_sb += esb0 + esb1 + fsb0 + fsb1;
            sum_wa += ewa0 + ewa1 + fwa0 + fwa1;
            sum_wb += ewb0 + ewb1 + fwb0 + fwb1;

            uint32_t ps[4], pw[4];
            ps[0] = packh2(esa0, esa1);
            ps[1] = packh2(esb0, esb1);
            ps[2] = packh2(fsa0, fsa1);
            ps[3] = packh2(fsb0, fsb1);
            pw[0] = packh2(ewa0, ewa1);
            pw[1] = packh2(ewb0, ewb1);
            pw[2] = packh2(fwa0, fwa1);
            pw[3] = packh2(fwb0, fwb1);

            {
                int keyv = np * 16 + (grp & 1) * 8 + (lane & 7);
                uint32_t kb = (uint32_t)keyv * 256u, rxv = (uint32_t)(keyv & 7);
#pragma unroll
                for (int dp = 0; dp < 8; dp++) {
                    uint32_t c16 = (uint32_t)(dp * 2 + (grp >> 1));
                    uint32_t off = kb + ((c16 ^ rxv) << 4);
                    uint32_t vh[4], vl[4];
                    ldsm4t(vh, KB + VHIO + off);
                    ldsm4t(vl, KB + VLOO + off);
                    if (do_s) {
                        mma16816h(Os[2 * dp],     ps, vh[0], vh[1]);
                        mma16816h(Os[2 * dp + 1], ps, vh[2], vh[3]);
                        mma16816h(Os[2 * dp],     ps, vl[0], vl[1]);
                        mma16816h(Os[2 * dp + 1], ps, vl[2], vl[3]);
                    }
                    if (do_w) {
                        mma16816h(Ow[2 * dp],     pw, vh[0], vh[1]);
                        mma16816h(Ow[2 * dp + 1], pw, vh[2], vh[3]);
                        mma16816h(Ow[2 * dp],     pw, vl[0], vl[1]);
                        mma16816h(Ow[2 * dp + 1], pw, vl[2], vl[3]);
                    }
                }
            }
        }
    }

#pragma unroll
    for (int o = 1; o <= 2; o <<= 1) {
        sum_sa += __shfl_xor_sync(0xffffffffu, sum_sa, o);
        sum_sb += __shfl_xor_sync(0xffffffffu, sum_sb, o);
        sum_wa += __shfl_xor_sync(0xffffffffu, sum_wa, o);
        sum_wb += __shfl_xor_sync(0xffffffffu, sum_wb, o);
    }
    float inv_sa = 1.f / sum_sa, inv_sb = 1.f / sum_sb;
    float inv_wa = 1.f / sum_wa, inv_wb = 1.f / sum_wb;

    const float* wa = w + ((size_t)(t_a * H_HEADS + h)) * 3;
    const float* wb = w + ((size_t)(t_b * H_HEADS + h)) * 3;
    float w0a = wa[0], w1a = wa[1], w2a = wa[2];
    float w0b = wb[0], w1b = wb[1], w2b = wb[2];

#pragma unroll
    for (int nt = 0; nt < 16; nt++) {
        int d0 = nt * 8 + jcl;
        const float2* ca = reinterpret_cast<const float2*>(&g_ocmp[t_a][h][d0]);
        const float2* cb = reinterpret_cast<const float2*>(&g_ocmp[t_b][h][d0]);
        float2 oc_a = *ca, oc_b = *cb;
        float2 oa, ob;
        oa.x = w0a * oc_a.x + w1a * Os[nt][0] * inv_sa + w2a * Ow[nt][0] * inv_wa;
        oa.y = w0a * oc_a.y + w1a * Os[nt][1] * inv_sa + w2a * Ow[nt][1] * inv_wa;
        ob.x = w0b * oc_b.x + w1b * Os[nt][2] * inv_sb + w2b * Ow[nt][2] * inv_wb;
        ob.y = w0b * oc_b.y + w1b * Os[nt][3] * inv_sb + w2b * Ow[nt][3] * inv_wb;
        *reinterpret_cast<float2*>(out + ((size_t)(t_a * H_HEADS + h)) * DDIM + d0) = oa;
        *reinterpret_cast<float2*>(out + ((size_t)(t_b * H_HEADS + h)) * DDIM + d0) = ob;
    }
}

// ---------------- launch ----------------
extern "C" void kernel_launch(void* const* d_in, const int* in_sizes, int n_in,
                              void* d_out, int out_size) {
    const float* q = (const float*)d_in[0];
    const float* k = (const float*)d_in[1];
    const float* v = (const float*)d_in[2];
    const float* w = (const float*)d_in[3];
    float* out = (float*)d_out;

    cudaFuncSetAttribute(k2_tc, cudaFuncAttributeMaxDynamicSharedMemorySize, K2_TOT);
    cudaFuncSetAttribute(k3_main, cudaFuncAttributeMaxDynamicSharedMemorySize, SMTOT);

    k0_split<<<1024, 256>>>(q, k, v);
    k1_compress<<<dim3(NCMP, KHN), DDIM>>>(k, v);
    k1b_knorm<<<dim3(T_LEN, KHN), 32>>>(k);
    k2_tc<<<dim3(T_LEN / TQ, KHN), 256, K2_TOT>>>();
    k3_main<<<dim3(T_LEN / TQ, KHN), 256, SMTOT>>>(q, w, out);
}

// round 8
// speedup vs baseline: 6.2052x; 1.1715x over previous
#include <cuda_runtime.h>
#include <cuda_bf16.h>
#include <cuda_fp16.h>
#include <math.h>
#include <stdint.h>

#define T_LEN 2048
#define H_HEADS 16
#define KHN 2
#define GQ 8
#define DDIM 128
#define NCMP 127
#define NBLK 32
#define TQ 16
#define SCALE_F 0.08838834765f
#define EXP_SHIFT 10.3972077f   /* ln(2^15) */
#define NEG_INF (-INFINITY)

// ---------------- scratch ----------------
__device__ float g_ocmp[T_LEN][H_HEADS][DDIM];
__device__ unsigned g_sel[T_LEN][KHN];
__device__ unsigned g_kmax[KHN];

// fp16 2-split q/k/v + compressed tensors
__device__ __align__(16) __half g_qh16[T_LEN * H_HEADS * DDIM];
__device__ __align__(16) __half g_ql16[T_LEN * H_HEADS * DDIM];
__device__ __align__(16) __half g_kh16[KHN * T_LEN * DDIM];
__device__ __align__(16) __half g_kl16[KHN * T_LEN * DDIM];
__device__ __align__(16) __half g_vh16[KHN * T_LEN * DDIM];
__device__ __align__(16) __half g_vl16[KHN * T_LEN * DDIM];
// compressed k 2-split / v 2-split (row 127 stays zero)
__device__ __align__(16) __half g_ckhi[KHN][128][DDIM];
__device__ __align__(16) __half g_cklo[KHN][128][DDIM];
__device__ __align__(16) __half g_cvhi[KHN][128][DDIM];
__device__ __align__(16) __half g_cvlo[KHN][128][DDIM];

// ---------------- helpers ----------------
__device__ __forceinline__ uint32_t smem_u32(const void* p) {
    uint32_t a;
    asm("{ .reg .u64 t; cvta.to.shared.u64 t, %1; cvt.u32.u64 %0, t; }" : "=r"(a) : "l"(p));
    return a;
}
__device__ __forceinline__ void mma16816h(float* d, const uint32_t* a, uint32_t b0, uint32_t b1) {
    asm volatile("mma.sync.aligned.m16n8k16.row.col.f32.f16.f16.f32 "
        "{%0,%1,%2,%3},{%4,%5,%6,%7},{%8,%9},{%0,%1,%2,%3};"
        : "+f"(d[0]), "+f"(d[1]), "+f"(d[2]), "+f"(d[3])
        : "r"(a[0]), "r"(a[1]), "r"(a[2]), "r"(a[3]), "r"(b0), "r"(b1));
}
__device__ __forceinline__ void ldsm4(uint32_t* r, uint32_t addr) {
    asm volatile("ldmatrix.sync.aligned.m8n8.x4.shared.b16 {%0,%1,%2,%3}, [%4];"
        : "=r"(r[0]), "=r"(r[1]), "=r"(r[2]), "=r"(r[3]) : "r"(addr));
}
__device__ __forceinline__ void ldsm4t(uint32_t* r, uint32_t addr) {
    asm volatile("ldmatrix.sync.aligned.m8n8.x4.trans.shared.b16 {%0,%1,%2,%3}, [%4];"
        : "=r"(r[0]), "=r"(r[1]), "=r"(r[2]), "=r"(r[3]) : "r"(addr));
}
__device__ __forceinline__ uint32_t packh2(float a, float b) {
    __half2 h = __floats2half2_rn(a, b);
    return *reinterpret_cast<uint32_t*>(&h);
}
#define CP_ASYNC16(dst, src) \
    asm volatile("cp.async.cg.shared.global [%0], [%1], 16;" :: "r"(dst), "l"(src) : "memory")
#define CP_COMMIT() asm volatile("cp.async.commit_group;" ::: "memory")
#define CP_WAIT0()  asm volatile("cp.async.wait_group 0;" ::: "memory")

// ---------------- K0: pre-split q/k/v into fp16 hi/lo ----------------
__global__ void k0_split(const float* __restrict__ q, const float* __restrict__ k,
                         const float* __restrict__ v) {
    int stride = gridDim.x * blockDim.x;
    int idx = blockIdx.x * blockDim.x + threadIdx.x;
    const int n_kv = T_LEN * KHN * DDIM;
    for (int i = idx; i < n_kv; i += stride) {
        int d = i & (DDIM - 1);
        int tk = i >> 7;
        int kh = tk & 1, t = tk >> 1;
        int o = (kh * T_LEN + t) * DDIM + d;
        float x = k[i];
        __half h = __float2half_rn(x);
        g_kh16[o] = h;
        g_kl16[o] = __float2half_rn(x - __half2float(h));
        x = v[i];
        h = __float2half_rn(x);
        g_vh16[o] = h;
        g_vl16[o] = __float2half_rn(x - __half2float(h));
    }
    const int n_q = T_LEN * H_HEADS * DDIM;
    for (int i = idx; i < n_q; i += stride) {
        float x = q[i];
        __half hh = __float2half_rn(x);
        g_qh16[i] = hh;
        g_ql16[i] = __float2half_rn(x - __half2float(hh));
    }
}

// ---------------- K1: compressed K/V (fp16 2-splits) ----------------
__global__ void k1_compress(const float* __restrict__ k, const float* __restrict__ v) {
    int j = blockIdx.x, kh = blockIdx.y, d = threadIdx.x;
    int s = j * 16;
    float sk = 0.f, sv = 0.f;
#pragma unroll 8
    for (int i = 0; i < 32; i++) {
        sk += k[((size_t)(s + i) * KHN + kh) * DDIM + d];
        sv += v[((size_t)(s + i) * KHN + kh) * DDIM + d];
    }
    float ck = sk * (1.f / 32.f), cv = sv * (1.f / 32.f);
    __half h = __float2half_rn(ck);
    g_ckhi[kh][j][d] = h;
    g_cklo[kh][j][d] = __float2half_rn(ck - __half2float(h));
    h = __float2half_rn(cv);
    g_cvhi[kh][j][d] = h;
    g_cvlo[kh][j][d] = __float2half_rn(cv - __half2float(h));
}

// ---------------- K1b: max ||k_row|| per kv head ----------------
__global__ void k1b_knorm(const float* __restrict__ k) {
    int t = blockIdx.x, kh = blockIdx.y, lane = threadIdx.x;
    const float4* kr = reinterpret_cast<const float4*>(k) + ((size_t)t * KHN + kh) * 32;
    float4 a = kr[lane];
    float s = a.x * a.x + a.y * a.y + a.z * a.z + a.w * a.w;
    for (int o = 16; o; o >>= 1) s += __shfl_xor_sync(0xffffffffu, s, o);
    if (lane == 0) atomicMax(&g_kmax[kh], __float_as_uint(sqrtf(s)));
}

// ---------------- K2: fp16 tensor-core compressed attention + selection ----------------
#define K2_QH 0
#define K2_QL 32768
#define K2_CKH 65536
#define K2_CKL 98304
#define K2_PS  131072
#define K2_TOT 139264
#define K2_VH 0
#define K2_VL 32768

__global__ __launch_bounds__(256, 1) void k2_tc() {
    extern __shared__ char smem[];
    uint32_t sb = smem_u32(smem);
    float* psum_sh = reinterpret_cast<float*>(smem + K2_PS);
    int tid = threadIdx.x;
    int wp = tid >> 5, lane = tid & 31;
    int t0 = blockIdx.x * TQ;
    int kh = blockIdx.y;
    int grp = lane >> 3;
    int jcl = (lane & 3) * 2;

    for (int i = tid; i < 128 * 16; i += 256) {
        int row = i >> 4, c16 = i & 15;
        uint32_t off = (uint32_t)row * 256u + (uint32_t)((c16 ^ (row & 7)) << 4);
        int qrow = (t0 + (row >> 3)) * H_HEADS + kh * GQ + (row & 7);
        CP_ASYNC16(sb + K2_QH + off, g_qh16 + (size_t)qrow * DDIM + c16 * 8);
        CP_ASYNC16(sb + K2_QL + off, g_ql16 + (size_t)qrow * DDIM + c16 * 8);
        CP_ASYNC16(sb + K2_CKH + off, &g_ckhi[kh][row][c16 * 8]);
        CP_ASYNC16(sb + K2_CKL + off, &g_cklo[kh][row][c16 * 8]);
    }
    CP_COMMIT();
    CP_WAIT0();
    __syncthreads();

    int t_a = t0 + 2 * wp;
    int t_b = t_a + 1;
    int g = lane >> 2;
    int h = kh * GQ + g;
    int nva = (t_a >= 31) ? ((t_a - 31) / 16 + 1) : 0;
    int nvb = (t_b >= 31) ? ((t_b - 31) / 16 + 1) : 0;

    float s[16][4];
#pragma unroll
    for (int i = 0; i < 16; i++)
#pragma unroll
        for (int c = 0; c < 4; c++) s[i][c] = 0.f;

    uint32_t ah[8][4];
    {
        int row = 16 * wp + (grp & 1) * 8 + (lane & 7);
        uint32_t rb = (uint32_t)row * 256u, rx = (uint32_t)(row & 7);
#pragma unroll
        for (int kt = 0; kt < 8; kt++) {
            uint32_t cq = (uint32_t)(kt * 2 + (grp >> 1));
            ldsm4(ah[kt], sb + K2_QH + rb + ((cq ^ rx) << 4));
        }
    }
#pragma unroll
    for (int np = 0; np < 8; np++) {
        int keyq = np * 16 + (grp >> 1) * 8 + (lane & 7);
        uint32_t kb = (uint32_t)keyq * 256u, rxk = (uint32_t)(keyq & 7);
        int rowq = 16 * wp + (grp & 1) * 8 + (lane & 7);
        uint32_t rq = (uint32_t)rowq * 256u, rxq = (uint32_t)(rowq & 7);
#pragma unroll
        for (int kt = 0; kt < 8; kt++) {
            uint32_t ck = (uint32_t)(kt * 2 + (grp & 1));
            uint32_t bo = kb + ((ck ^ rxk) << 4);
            uint32_t cq = (uint32_t)(kt * 2 + (grp >> 1));
            uint32_t bh[4], bl[4], al[4];
            ldsm4(bh, sb + K2_CKH + bo);
            ldsm4(bl, sb + K2_CKL + bo);
            ldsm4(al, sb + K2_QL + rq + ((cq ^ rxq) << 4));
            mma16816h(s[2*np],   ah[kt], bh[0], bh[1]);
            mma16816h(s[2*np+1], ah[kt], bh[2], bh[3]);
            mma16816h(s[2*np],   ah[kt], bl[0], bl[1]);
            mma16816h(s[2*np+1], ah[kt], bl[2], bl[3]);
            mma16816h(s[2*np],   al,     bh[0], bh[1]);
            mma16816h(s[2*np+1], al,     bh[2], bh[3]);
        }
    }
    __syncthreads();

    // stage cmp_v hi/lo into q region (overlaps softmax/selection)
    for (int i = tid; i < 128 * 16; i += 256) {
        int row = i >> 4, c16 = i & 15;
        uint32_t off = (uint32_t)row * 256u + (uint32_t)((c16 ^ (row & 7)) << 4);
        CP_ASYNC16(sb + K2_VH + off, &g_cvhi[kh][row][c16 * 8]);
        CP_ASYNC16(sb + K2_VL + off, &g_cvlo[kh][row][c16 * 8]);
    }
    CP_COMMIT();

    float ma = NEG_INF, mb = NEG_INF;
#pragma unroll
    for (int nt = 0; nt < 16; nt++) {
        int j0 = nt * 8 + jcl;
        if (j0 < nva)     ma = fmaxf(ma, s[nt][0] * SCALE_F);
        if (j0 + 1 < nva) ma = fmaxf(ma, s[nt][1] * SCALE_F);
        if (j0 < nvb)     mb = fmaxf(mb, s[nt][2] * SCALE_F);
        if (j0 + 1 < nvb) mb = fmaxf(mb, s[nt][3] * SCALE_F);
    }
#pragma unroll
    for (int o = 1; o <= 2; o <<= 1) {
        ma = fmaxf(ma, __shfl_xor_sync(0xffffffffu, ma, o));
        mb = fmaxf(mb, __shfl_xor_sync(0xffffffffu, mb, o));
    }
    float la = 0.f, lb = 0.f;
#pragma unroll
    for (int nt = 0; nt < 16; nt++) {
        int j0 = nt * 8 + jcl;
        float e0 = (j0 < nva)     ? expf(s[nt][0] * SCALE_F - ma) : 0.f;
        float e1 = (j0 + 1 < nva) ? expf(s[nt][1] * SCALE_F - ma) : 0.f;
        float e2 = (j0 < nvb)     ? expf(s[nt][2] * SCALE_F - mb) : 0.f;
        float e3 = (j0 + 1 < nvb) ? expf(s[nt][3] * SCALE_F - mb) : 0.f;
        s[nt][0] = e0; s[nt][1] = e1; s[nt][2] = e2; s[nt][3] = e3;
        la += e0 + e1; lb += e2 + e3;
    }
#pragma unroll
    for (int o = 1; o <= 2; o <<= 1) {
        la += __shfl_xor_sync(0xffffffffu, la, o);
        lb += __shfl_xor_sync(0xffffffffu, lb, o);
    }
    float inva = (nva > 0) ? 1.f / la : 0.f;
    float invb = (nvb > 0) ? 1.f / lb : 0.f;
#pragma unroll
    for (int nt = 0; nt < 16; nt++) {
        s[nt][0] *= inva; s[nt][1] *= inva;
        s[nt][2] *= invb; s[nt][3] *= invb;
    }

#pragma unroll
    for (int nt = 0; nt < 16; nt++) {
        float a0 = s[nt][0], a1 = s[nt][1], b0 = s[nt][2], b1 = s[nt][3];
#pragma unroll
        for (int o = 4; o <= 16; o <<= 1) {
            a0 += __shfl_xor_sync(0xffffffffu, a0, o);
            a1 += __shfl_xor_sync(0xffffffffu, a1, o);
            b0 += __shfl_xor_sync(0xffffffffu, b0, o);
            b1 += __shfl_xor_sync(0xffffffffu, b1, o);
        }
        if (lane < 4) {
            int j = nt * 8 + lane * 2;
            psum_sh[(2 * wp) * 128 + j] = a0;
            psum_sh[(2 * wp) * 128 + j + 1] = a1;
            psum_sh[(2 * wp + 1) * 128 + j] = b0;
            psum_sh[(2 * wp + 1) * 128 + j + 1] = b1;
        }
    }
    __syncthreads();

#pragma unroll
    for (int rep = 0; rep < 2; rep++) {
        int t = t0 + 2 * wp + rep;
        int qi = 2 * wp + rep;
        int nv = (t >= 31) ? ((t - 31) / 16 + 1) : 0;
        int b = lane;
        int tb = t >> 6;
        bool forced = (b < 1) || ((b <= tb) && (b >= tb - 1));
        bool valid = (b * 64 <= t);
        float sc;
        if (!valid) sc = -1e30f;
        else if (forced) sc = 1e30f;
        else {
            int jlo = 4 * b - 1; if (jlo < 0) jlo = 0;
            int jhi = 4 * b + 3; if (jhi > nv - 1) jhi = nv - 1;
            float ss = 0.f;
            for (int j = jlo; j <= jhi; j++) ss += psum_sh[qi * 128 + j];
            sc = ss;
        }
        unsigned sel = 0u;
        for (int it = 0; it < 16; it++) {
            float vcur = ((sel >> b) & 1u) ? NEG_INF : sc;
            float m = vcur;
            for (int o = 16; o; o >>= 1) m = fmaxf(m, __shfl_xor_sync(0xffffffffu, m, o));
            unsigned ball = __ballot_sync(0xffffffffu, vcur == m);
            sel |= (1u << (__ffs(ball) - 1));
        }
        if (lane == 0) g_sel[t][kh] = sel;
    }

    // pack normalized P (single fp16)
    uint32_t ph[8][4];
#pragma unroll
    for (int kp = 0; kp < 8; kp++) {
        ph[kp][0] = packh2(s[2*kp][0],   s[2*kp][1]);
        ph[kp][1] = packh2(s[2*kp][2],   s[2*kp][3]);
        ph[kp][2] = packh2(s[2*kp+1][0], s[2*kp+1][1]);
        ph[kp][3] = packh2(s[2*kp+1][2], s[2*kp+1][3]);
    }

    CP_WAIT0();
    __syncthreads();

    float Oc[16][4];
#pragma unroll
    for (int i = 0; i < 16; i++)
#pragma unroll
        for (int c = 0; c < 4; c++) Oc[i][c] = 0.f;
#pragma unroll
    for (int kp = 0; kp < 8; kp++) {
        int keyv = kp * 16 + (grp & 1) * 8 + (lane & 7);
        uint32_t kb = (uint32_t)keyv * 256u, rxv = (uint32_t)(keyv & 7);
#pragma unroll
        for (int dp = 0; dp < 8; dp++) {
            uint32_t c16 = (uint32_t)(dp * 2 + (grp >> 1));
            uint32_t off = kb + ((c16 ^ rxv) << 4);
            uint32_t vh[4], vl[4];
            ldsm4t(vh, sb + K2_VH + off);
            ldsm4t(vl, sb + K2_VL + off);
            mma16816h(Oc[2*dp],   ph[kp], vh[0], vh[1]);
            mma16816h(Oc[2*dp+1], ph[kp], vh[2], vh[3]);
            mma16816h(Oc[2*dp],   ph[kp], vl[0], vl[1]);
            mma16816h(Oc[2*dp+1], ph[kp], vl[2], vl[3]);
        }
    }
#pragma unroll
    for (int nt = 0; nt < 16; nt++) {
        int d0 = nt * 8 + jcl;
        *reinterpret_cast<float2*>(&g_ocmp[t_a][h][d0]) = make_float2(Oc[nt][0], Oc[nt][1]);
        *reinterpret_cast<float2*>(&g_ocmp[t_b][h][d0]) = make_float2(Oc[nt][2], Oc[nt][3]);
    }
}

// ---------------- K3: fp16 HMMA fused slc+win attention (2-term QK) ----------------
#define SQHI 0
#define SBUF 32768
#define BUFSZ 65536
#define KHIO 0
#define KLOO 16384
#define VHIO 32768
#define VLOO 49152
#define SMTOT 163840

__global__ __launch_bounds__(256, 1) void k3_main(
    const float* __restrict__ q, const float* __restrict__ w,
    float* __restrict__ out)
{
    extern __shared__ char smem[];
    uint32_t sbb_ = smem_u32(smem);
    int tid = threadIdx.x;
    int wp = tid >> 5, lane = tid & 31;
    int tile = (int)gridDim.x - 1 - (int)blockIdx.x;
    int t0 = tile * TQ;
    int kh = blockIdx.y;

    __shared__ int s_list[36];
    __shared__ int s_n;
    __shared__ unsigned s_union;

    int g = lane >> 2;
    int t_a = t0 + 2 * wp;
    int t_b = t_a + 1;
    int h = kh * GQ + g;

    unsigned selm_a = g_sel[t_a][kh], selm_b = g_sel[t_b][kh];
    if (tid == 0) s_union = 0u;
    __syncthreads();
    if (lane == 0) atomicOr(&s_union, selm_a | selm_b);

    // stage Q (fp16 hi only, swizzled)
    for (int i = tid; i < 128 * 16; i += 256) {
        int row = i >> 4, c16 = i & 15;
        int qrow = (t0 + (row >> 3)) * H_HEADS + kh * GQ + (row & 7);
        uint32_t off = (uint32_t)row * 256u + (uint32_t)((c16 ^ (row & 7)) << 4);
        CP_ASYNC16(sbb_ + SQHI + off, g_qh16 + (size_t)qrow * DDIM + c16 * 8);
    }

    float kmax = __uint_as_float(g_kmax[kh]);
    float Ua, Ub;
    {
        const float4* q4 = reinterpret_cast<const float4*>(q);
        float s2 = 0.f;
        const float4* qr = q4 + ((size_t)(t_a * H_HEADS + h)) * 32;
#pragma unroll 8
        for (int d4 = 0; d4 < 32; d4++) { float4 a = qr[d4]; s2 += a.x*a.x + a.y*a.y + a.z*a.z + a.w*a.w; }
        Ua = SCALE_F * sqrtf(s2) * kmax - EXP_SHIFT;
        s2 = 0.f;
        qr = q4 + ((size_t)(t_b * H_HEADS + h)) * 32;
#pragma unroll 8
        for (int d4 = 0; d4 < 32; d4++) { float4 a = qr[d4]; s2 += a.x*a.x + a.y*a.y + a.z*a.z + a.w*a.w; }
        Ub = SCALE_F * sqrtf(s2) * kmax - EXP_SHIFT;
    }

    __syncthreads();
    unsigned selu = s_union;
    int t_blk = t0 >> 6;

    if (tid == 0) {
        int n = 0;
        for (int b = 0; b <= t_blk; b++) {
            bool need = ((selu >> b) & 1u) || (b * 64 + 63 >= t0 - 511);
            if (need) s_list[n++] = b;
        }
        s_n = n;
    }
    __syncthreads();
    int nch = s_n;

    const __half* khbase = g_kh16 + (size_t)kh * T_LEN * DDIM;
    const __half* klbase = g_kl16 + (size_t)kh * T_LEN * DDIM;
    const __half* vhbase = g_vh16 + (size_t)kh * T_LEN * DDIM;
    const __half* vlbase = g_vl16 + (size_t)kh * T_LEN * DDIM;

    {
        int b0 = s_list[0];
        for (int i = tid; i < 1024; i += 256) {
            int row = i >> 4, c16 = i & 15;
            size_t src = (size_t)(b0 * 64 + row) * DDIM + c16 * 8;
            uint32_t dst = sbb_ + SBUF + ((uint32_t)row * 256u + (uint32_t)((c16 ^ (row & 7)) << 4));
            CP_ASYNC16(dst + KHIO, khbase + src);
            CP_ASYNC16(dst + KLOO, klbase + src);
            CP_ASYNC16(dst + VHIO, vhbase + src);
            CP_ASYNC16(dst + VLOO, vlbase + src);
        }
    }
    CP_COMMIT();
    CP_WAIT0();
    __syncthreads();

    int jcl = (lane & 3) * 2;
    int grp = lane >> 3;

    uint32_t ah[8][4];
    {
        int row = 16 * wp + (grp & 1) * 8 + (lane & 7);
        uint32_t rbase = (uint32_t)row * 256u, rx = (uint32_t)(row & 7);
#pragma unroll
        for (int kt = 0; kt < 8; kt++) {
            uint32_t c16 = (uint32_t)(kt * 2 + (grp >> 1));
            ldsm4(ah[kt], sbb_ + SQHI + rbase + ((c16 ^ rx) << 4));
        }
    }

    float Os[16][4], Ow[16][4];
#pragma unroll
    for (int i = 0; i < 16; i++)
#pragma unroll
        for (int c = 0; c < 4; c++) { Os[i][c] = 0.f; Ow[i][c] = 0.f; }
    float sum_sa = 0.f, sum_sb = 0.f, sum_wa = 0.f, sum_wb = 0.f;

    for (int ci = 0; ci < nch; ci++) {
        int b = s_list[ci];
        bool do_s = (selu >> b) & 1u;
        bool do_w = (b * 64 + 63 >= t0 - 511);
        uint32_t KB = sbb_ + SBUF + (uint32_t)(ci & 1) * BUFSZ;

        if (ci > 0) {
            CP_WAIT0();
            __syncthreads();
        }
        if (ci + 1 < nch) {
            int bn = s_list[ci + 1];
            uint32_t NB = sbb_ + SBUF + (uint32_t)((ci + 1) & 1) * BUFSZ;
            for (int i = tid; i < 1024; i += 256) {
                int row = i >> 4, c16 = i & 15;
                size_t src = (size_t)(bn * 64 + row) * DDIM + c16 * 8;
                uint32_t dst = NB + ((uint32_t)row * 256u + (uint32_t)((c16 ^ (row & 7)) << 4));
                CP_ASYNC16(dst + KHIO, khbase + src);
                CP_ASYNC16(dst + KLOO, klbase + src);
                CP_ASYNC16(dst + VHIO, vhbase + src);
                CP_ASYNC16(dst + VLOO, vlbase + src);
            }
            CP_COMMIT();
        }

#pragma unroll
        for (int np = 0; np < 4; np++) {
            float s0[4] = {0.f, 0.f, 0.f, 0.f}, s1[4] = {0.f, 0.f, 0.f, 0.f};
            {
                int keyq = np * 16 + (grp >> 1) * 8 + (lane & 7);
                uint32_t kb = (uint32_t)keyq * 256u, rxk = (uint32_t)(keyq & 7);
#pragma unroll
                for (int kt = 0; kt < 8; kt++) {
                    uint32_t ck = (uint32_t)(kt * 2 + (grp & 1));
                    uint32_t bh[4], bl[4];
                    ldsm4(bh, KB + KHIO + kb + ((ck ^ rxk) << 4));
                    ldsm4(bl, KB + KLOO + kb + ((ck ^ rxk) << 4));
                    mma16816h(s0, ah[kt], bh[0], bh[1]);
                    mma16816h(s1, ah[kt], bh[2], bh[3]);
                    mma16816h(s0, ah[kt], bl[0], bl[1]);
                    mma16816h(s1, ah[kt], bl[2], bl[3]);
                }
            }
            int j0 = b * 64 + np * 16 + jcl;
            float ea0 = __expf(s0[0] * SCALE_F - Ua);
            float ea1 = __expf(s0[1] * SCALE_F - Ua);
            float eb0 = __expf(s0[2] * SCALE_F - Ub);
            float eb1 = __expf(s0[3] * SCALE_F - Ub);
            float fa0 = __expf(s1[0] * SCALE_F - Ua);
            float fa1 = __expf(s1[1] * SCALE_F - Ua);
            float fb0 = __expf(s1[2] * SCALE_F - Ub);
            float fb1 = __expf(s1[3] * SCALE_F - Ub);
            bool sa = (selm_a >> b) & 1u, sb2 = (selm_b >> b) & 1u;
            int j1 = j0 + 1, j8 = j0 + 8, j9 = j0 + 9;

            float esa0 = (sa  && j0 <= t_a) ? ea0 : 0.f;
            float esa1 = (sa  && j1 <= t_a) ? ea1 : 0.f;
            float esb0 = (sb2 && j0 <= t_b) ? eb0 : 0.f;
            float esb1 = (sb2 && j1 <= t_b) ? eb1 : 0.f;
            float fsa0 = (sa  && j8 <= t_a) ? fa0 : 0.f;
            float fsa1 = (sa  && j9 <= t_a) ? fa1 : 0.f;
            float fsb0 = (sb2 && j8 <= t_b) ? fb0 : 0.f;
            float fsb1 = (sb2 && j9 <= t_b) ? fb1 : 0.f;

            float ewa0 = (j0 <= t_a && t_a - j0 < 512) ? ea0 : 0.f;
            float ewa1 = (j1 <= t_a && t_a - j1 < 512) ? ea1 : 0.f;
            float ewb0 = (j0 <= t_b && t_b - j0 < 512) ? eb0 : 0.f;
            float ewb1 = (j1 <= t_b && t_b - j1 < 512) ? eb1 : 0.f;
            float fwa0 = (j8 <= t_a && t_a - j8 < 512) ? fa0 : 0.f;
            float fwa1 = (j9 <= t_a && t_a - j9 < 512) ? fa1 : 0.f;
            float fwb0 = (j8 <= t_b && t_b - j8 < 512) ? fb0 : 0.f;
            float fwb1 = (j9 <= t_b && t_b - j9 < 512) ? fb1 : 0.f;

            sum_sa += esa0 + esa1 + fsa0 + fsa1;
            sum_sb += esb0 + esb1 + fsb0 + fsb1;
            sum_wa += ewa0 + ewa1 + fwa0 + fwa1;
            sum_wb += ewb0 + ewb1 + fwb0 + fwb1;

            uint32_t ps[4], pw[4];
            ps[0] = packh2(esa0, esa1);
            ps[1] = packh2(esb0, esb1);
            ps[2] = packh2(fsa0, fsa1);
            ps[3] = packh2(fsb0, fsb1);
            pw[0] = packh2(ewa0, ewa1);
            pw[1] = packh2(ewb0, ewb1);
            pw[2] = packh2(fwa0, fwa1);
            pw[3] = packh2(fwb0, fwb1);

            {
                int keyv = np * 16 + (grp & 1) * 8 + (lane & 7);
                uint32_t kb = (uint32_t)keyv * 256u, rxv = (uint32_t)(keyv & 7);
#pragma unroll
                for (int dp = 0; dp < 8; dp++) {
                    uint32_t c16 = (uint32_t)(dp * 2 + (grp >> 1));
                    uint32_t off = kb + ((c16 ^ rxv) << 4);
                    uint32_t vh[4], vl[4];
                    ldsm4t(vh, KB + VHIO + off);
                    ldsm4t(vl, KB + VLOO + off);
                    if (do_s) {
                        mma16816h(Os[2 * dp],     ps, vh[0], vh[1]);
                        mma16816h(Os[2 * dp + 1], ps, vh[2], vh[3]);
                        mma16816h(Os[2 * dp],     ps, vl[0], vl[1]);
                        mma16816h(Os[2 * dp + 1], ps, vl[2], vl[3]);
                    }
                    if (do_w) {
                        mma16816h(Ow[2 * dp],     pw, vh[0], vh[1]);
                        mma16816h(Ow[2 * dp + 1], pw, vh[2], vh[3]);
                        mma16816h(Ow[2 * dp],     pw, vl[0], vl[1]);
                        mma16816h(Ow[2 * dp + 1], pw, vl[2], vl[3]);
                    }
                }
            }
        }
    }

#pragma unroll
    for (int o = 1; o <= 2; o <<= 1) {
        sum_sa += __shfl_xor_sync(0xffffffffu, sum_sa, o);
        sum_sb += __shfl_xor_sync(0xffffffffu, sum_sb, o);
        sum_wa += __shfl_xor_sync(0xffffffffu, sum_wa, o);
        sum_wb += __shfl_xor_sync(0xffffffffu, sum_wb, o);
    }
    float inv_sa = 1.f / sum_sa, inv_sb = 1.f / sum_sb;
    float inv_wa = 1.f / sum_wa, inv_wb = 1.f / sum_wb;

    const float* wa = w + ((size_t)(t_a * H_HEADS + h)) * 3;
    const float* wb = w + ((size_t)(t_b * H_HEADS + h)) * 3;
    float w0a = wa[0], w1a = wa[1], w2a = wa[2];
    float w0b = wb[0], w1b = wb[1], w2b = wb[2];

#pragma unroll
    for (int nt = 0; nt < 16; nt++) {
        int d0 = nt * 8 + jcl;
        const float2* ca = reinterpret_cast<const float2*>(&g_ocmp[t_a][h][d0]);
        const float2* cb = reinterpret_cast<const float2*>(&g_ocmp[t_b][h][d0]);
        float2 oc_a = *ca, oc_b = *cb;
        float2 oa, ob;
        oa.x = w0a * oc_a.x + w1a * Os[nt][0] * inv_sa + w2a * Ow[nt][0] * inv_wa;
        oa.y = w0a * oc_a.y + w1a * Os[nt][1] * inv_sa + w2a * Ow[nt][1] * inv_wa;
        ob.x = w0b * oc_b.x + w1b * Os[nt][2] * inv_sb + w2b * Ow[nt][2] * inv_wb;
        ob.y = w0b * oc_b.y + w1b * Os[nt][3] * inv_sb + w2b * Ow[nt][3] * inv_wb;
        *reinterpret_cast<float2*>(out + ((size_t)(t_a * H_HEADS + h)) * DDIM + d0) = oa;
        *reinterpret_cast<float2*>(out + ((size_t)(t_b * H_HEADS + h)) * DDIM + d0) = ob;
    }
}

// ---------------- launch ----------------
extern "C" void kernel_launch(void* const* d_in, const int* in_sizes, int n_in,
                              void* d_out, int out_size) {
    const float* q = (const float*)d_in[0];
    const float* k = (const float*)d_in[1];
    const float* v = (const float*)d_in[2];
    const float* w = (const float*)d_in[3];
    float* out = (float*)d_out;

    cudaFuncSetAttribute(k2_tc, cudaFuncAttributeMaxDynamicSharedMemorySize, K2_TOT);
    cudaFuncSetAttribute(k3_main, cudaFuncAttributeMaxDynamicSharedMemorySize, SMTOT);

    k0_split<<<1024, 256>>>(q, k, v);
    k1_compress<<<dim3(NCMP, KHN), DDIM>>>(k, v);
    k1b_knorm<<<dim3(T_LEN, KHN), 32>>>(k);
    k2_tc<<<dim3(T_LEN / TQ, KHN), 256, K2_TOT>>>();
    k3_main<<<dim3(T_LEN / TQ, KHN), 256, SMTOT>>>(q, w, out);
}

// round 9
// speedup vs baseline: 9.0316x; 1.4555x over previous
#include <cuda_runtime.h>
#include <cuda_bf16.h>
#include <cuda_fp16.h>
#include <math.h>
#include <stdint.h>

#define T_LEN 2048
#define H_HEADS 16
#define KHN 2
#define GQ 8
#define DDIM 128
#define NCMP 127
#define NBLK 32
#define TQ 16
#define SCALE_F 0.08838834765f
#define EXP_SHIFT 10.3972077f   /* ln(2^15) */
#define NEG_INF (-INFINITY)

// ---------------- scratch ----------------
__device__ float g_ocmp[T_LEN][H_HEADS][DDIM];
__device__ unsigned g_sel[T_LEN][KHN];
__device__ unsigned g_kmax[KHN];

// fp16 tensors: q 2-split (k2 needs lo), k/v hi-only (k3), compressed k 2-split + v hi
__device__ __align__(16) __half g_qh16[T_LEN * H_HEADS * DDIM];
__device__ __align__(16) __half g_ql16[T_LEN * H_HEADS * DDIM];
__device__ __align__(16) __half g_kh16[KHN * T_LEN * DDIM];
__device__ __align__(16) __half g_vh16[KHN * T_LEN * DDIM];
__device__ __align__(16) __half g_ckhi[KHN][128][DDIM];
__device__ __align__(16) __half g_cklo[KHN][128][DDIM];
__device__ __align__(16) __half g_cvhi[KHN][128][DDIM];

// ---------------- helpers ----------------
__device__ __forceinline__ uint32_t smem_u32(const void* p) {
    uint32_t a;
    asm("{ .reg .u64 t; cvta.to.shared.u64 t, %1; cvt.u32.u64 %0, t; }" : "=r"(a) : "l"(p));
    return a;
}
__device__ __forceinline__ void mma16816h(float* d, const uint32_t* a, uint32_t b0, uint32_t b1) {
    asm volatile("mma.sync.aligned.m16n8k16.row.col.f32.f16.f16.f32 "
        "{%0,%1,%2,%3},{%4,%5,%6,%7},{%8,%9},{%0,%1,%2,%3};"
        : "+f"(d[0]), "+f"(d[1]), "+f"(d[2]), "+f"(d[3])
        : "r"(a[0]), "r"(a[1]), "r"(a[2]), "r"(a[3]), "r"(b0), "r"(b1));
}
__device__ __forceinline__ void ldsm4(uint32_t* r, uint32_t addr) {
    asm volatile("ldmatrix.sync.aligned.m8n8.x4.shared.b16 {%0,%1,%2,%3}, [%4];"
        : "=r"(r[0]), "=r"(r[1]), "=r"(r[2]), "=r"(r[3]) : "r"(addr));
}
__device__ __forceinline__ void ldsm4t(uint32_t* r, uint32_t addr) {
    asm volatile("ldmatrix.sync.aligned.m8n8.x4.trans.shared.b16 {%0,%1,%2,%3}, [%4];"
        : "=r"(r[0]), "=r"(r[1]), "=r"(r[2]), "=r"(r[3]) : "r"(addr));
}
__device__ __forceinline__ uint32_t packh2(float a, float b) {
    __half2 h = __floats2half2_rn(a, b);
    return *reinterpret_cast<uint32_t*>(&h);
}
#define CP_ASYNC16(dst, src) \
    asm volatile("cp.async.cg.shared.global [%0], [%1], 16;" :: "r"(dst), "l"(src) : "memory")
#define CP_COMMIT() asm volatile("cp.async.commit_group;" ::: "memory")
#define CP_WAIT0()  asm volatile("cp.async.wait_group 0;" ::: "memory")

// ---------------- K0: pre-split ----------------
__global__ void k0_split(const float* __restrict__ q, const float* __restrict__ k,
                         const float* __restrict__ v) {
    int stride = gridDim.x * blockDim.x;
    int idx = blockIdx.x * blockDim.x + threadIdx.x;
    const int n_kv = T_LEN * KHN * DDIM;
    for (int i = idx; i < n_kv; i += stride) {
        int d = i & (DDIM - 1);
        int tk = i >> 7;
        int kh = tk & 1, t = tk >> 1;
        int o = (kh * T_LEN + t) * DDIM + d;
        g_kh16[o] = __float2half_rn(k[i]);
        g_vh16[o] = __float2half_rn(v[i]);
    }
    const int n_q = T_LEN * H_HEADS * DDIM;
    for (int i = idx; i < n_q; i += stride) {
        float x = q[i];
        __half hh = __float2half_rn(x);
        g_qh16[i] = hh;
        g_ql16[i] = __float2half_rn(x - __half2float(hh));
    }
}

// ---------------- K1: compressed K/V ----------------
__global__ void k1_compress(const float* __restrict__ k, const float* __restrict__ v) {
    int j = blockIdx.x, kh = blockIdx.y, d = threadIdx.x;
    int s = j * 16;
    float sk = 0.f, sv = 0.f;
#pragma unroll 8
    for (int i = 0; i < 32; i++) {
        sk += k[((size_t)(s + i) * KHN + kh) * DDIM + d];
        sv += v[((size_t)(s + i) * KHN + kh) * DDIM + d];
    }
    float ck = sk * (1.f / 32.f), cv = sv * (1.f / 32.f);
    __half h = __float2half_rn(ck);
    g_ckhi[kh][j][d] = h;
    g_cklo[kh][j][d] = __float2half_rn(ck - __half2float(h));
    g_cvhi[kh][j][d] = __float2half_rn(cv);
}

// ---------------- K1b: max ||k_row|| per kv head ----------------
__global__ void k1b_knorm(const float* __restrict__ k) {
    int t = blockIdx.x, kh = blockIdx.y, lane = threadIdx.x;
    const float4* kr = reinterpret_cast<const float4*>(k) + ((size_t)t * KHN + kh) * 32;
    float4 a = kr[lane];
    float s = a.x * a.x + a.y * a.y + a.z * a.z + a.w * a.w;
    for (int o = 16; o; o >>= 1) s += __shfl_xor_sync(0xffffffffu, s, o);
    if (lane == 0) atomicMax(&g_kmax[kh], __float_as_uint(sqrtf(s)));
}

// ---------------- K2: fp16 tensor-core compressed attention + selection ----------------
#define K2_QH 0
#define K2_QL 32768
#define K2_CKH 65536
#define K2_CKL 98304
#define K2_PS  131072
#define K2_TOT 139264
#define K2_VH 0

__global__ __launch_bounds__(256, 1) void k2_tc() {
    extern __shared__ char smem[];
    uint32_t sb = smem_u32(smem);
    float* psum_sh = reinterpret_cast<float*>(smem + K2_PS);
    int tid = threadIdx.x;
    int wp = tid >> 5, lane = tid & 31;
    int t0 = blockIdx.x * TQ;
    int kh = blockIdx.y;
    int grp = lane >> 3;
    int jcl = (lane & 3) * 2;

    for (int i = tid; i < 128 * 16; i += 256) {
        int row = i >> 4, c16 = i & 15;
        uint32_t off = (uint32_t)row * 256u + (uint32_t)((c16 ^ (row & 7)) << 4);
        int qrow = (t0 + (row >> 3)) * H_HEADS + kh * GQ + (row & 7);
        CP_ASYNC16(sb + K2_QH + off, g_qh16 + (size_t)qrow * DDIM + c16 * 8);
        CP_ASYNC16(sb + K2_QL + off, g_ql16 + (size_t)qrow * DDIM + c16 * 8);
        CP_ASYNC16(sb + K2_CKH + off, &g_ckhi[kh][row][c16 * 8]);
        CP_ASYNC16(sb + K2_CKL + off, &g_cklo[kh][row][c16 * 8]);
    }
    CP_COMMIT();
    CP_WAIT0();
    __syncthreads();

    int t_a = t0 + 2 * wp;
    int t_b = t_a + 1;
    int g = lane >> 2;
    int h = kh * GQ + g;
    int nva = (t_a >= 31) ? ((t_a - 31) / 16 + 1) : 0;
    int nvb = (t_b >= 31) ? ((t_b - 31) / 16 + 1) : 0;

    float s[16][4];
#pragma unroll
    for (int i = 0; i < 16; i++)
#pragma unroll
        for (int c = 0; c < 4; c++) s[i][c] = 0.f;

    uint32_t ah[8][4];
    {
        int row = 16 * wp + (grp & 1) * 8 + (lane & 7);
        uint32_t rb = (uint32_t)row * 256u, rx = (uint32_t)(row & 7);
#pragma unroll
        for (int kt = 0; kt < 8; kt++) {
            uint32_t cq = (uint32_t)(kt * 2 + (grp >> 1));
            ldsm4(ah[kt], sb + K2_QH + rb + ((cq ^ rx) << 4));
        }
    }
#pragma unroll
    for (int np = 0; np < 8; np++) {
        int keyq = np * 16 + (grp >> 1) * 8 + (lane & 7);
        uint32_t kb = (uint32_t)keyq * 256u, rxk = (uint32_t)(keyq & 7);
        int rowq = 16 * wp + (grp & 1) * 8 + (lane & 7);
        uint32_t rq = (uint32_t)rowq * 256u, rxq = (uint32_t)(rowq & 7);
#pragma unroll
        for (int kt = 0; kt < 8; kt++) {
            uint32_t ck = (uint32_t)(kt * 2 + (grp & 1));
            uint32_t bo = kb + ((ck ^ rxk) << 4);
            uint32_t cq = (uint32_t)(kt * 2 + (grp >> 1));
            uint32_t bh[4], bl[4], al[4];
            ldsm4(bh, sb + K2_CKH + bo);
            ldsm4(bl, sb + K2_CKL + bo);
            ldsm4(al, sb + K2_QL + rq + ((cq ^ rxq) << 4));
            mma16816h(s[2*np],   ah[kt], bh[0], bh[1]);
            mma16816h(s[2*np+1], ah[kt], bh[2], bh[3]);
            mma16816h(s[2*np],   ah[kt], bl[0], bl[1]);
            mma16816h(s[2*np+1], ah[kt], bl[2], bl[3]);
            mma16816h(s[2*np],   al,     bh[0], bh[1]);
            mma16816h(s[2*np+1], al,     bh[2], bh[3]);
        }
    }
    __syncthreads();

    // stage cmp_v hi into q region (overlaps softmax/selection)
    for (int i = tid; i < 128 * 16; i += 256) {
        int row = i >> 4, c16 = i & 15;
        uint32_t off = (uint32_t)row * 256u + (uint32_t)((c16 ^ (row & 7)) << 4);
        CP_ASYNC16(sb + K2_VH + off, &g_cvhi[kh][row][c16 * 8]);
    }
    CP_COMMIT();

    float ma = NEG_INF, mb = NEG_INF;
#pragma unroll
    for (int nt = 0; nt < 16; nt++) {
        int j0 = nt * 8 + jcl;
        if (j0 < nva)     ma = fmaxf(ma, s[nt][0] * SCALE_F);
        if (j0 + 1 < nva) ma = fmaxf(ma, s[nt][1] * SCALE_F);
        if (j0 < nvb)     mb = fmaxf(mb, s[nt][2] * SCALE_F);
        if (j0 + 1 < nvb) mb = fmaxf(mb, s[nt][3] * SCALE_F);
    }
#pragma unroll
    for (int o = 1; o <= 2; o <<= 1) {
        ma = fmaxf(ma, __shfl_xor_sync(0xffffffffu, ma, o));
        mb = fmaxf(mb, __shfl_xor_sync(0xffffffffu, mb, o));
    }
    float la = 0.f, lb = 0.f;
#pragma unroll
    for (int nt = 0; nt < 16; nt++) {
        int j0 = nt * 8 + jcl;
        float e0 = (j0 < nva)     ? expf(s[nt][0] * SCALE_F - ma) : 0.f;
        float e1 = (j0 + 1 < nva) ? expf(s[nt][1] * SCALE_F - ma) : 0.f;
        float e2 = (j0 < nvb)     ? expf(s[nt][2] * SCALE_F - mb) : 0.f;
        float e3 = (j0 + 1 < nvb) ? expf(s[nt][3] * SCALE_F - mb) : 0.f;
        s[nt][0] = e0; s[nt][1] = e1; s[nt][2] = e2; s[nt][3] = e3;
        la += e0 + e1; lb += e2 + e3;
    }
#pragma unroll
    for (int o = 1; o <= 2; o <<= 1) {
        la += __shfl_xor_sync(0xffffffffu, la, o);
        lb += __shfl_xor_sync(0xffffffffu, lb, o);
    }
    float inva = (nva > 0) ? 1.f / la : 0.f;
    float invb = (nvb > 0) ? 1.f / lb : 0.f;
#pragma unroll
    for (int nt = 0; nt < 16; nt++) {
        s[nt][0] *= inva; s[nt][1] *= inva;
        s[nt][2] *= invb; s[nt][3] *= invb;
    }

#pragma unroll
    for (int nt = 0; nt < 16; nt++) {
        float a0 = s[nt][0], a1 = s[nt][1], b0 = s[nt][2], b1 = s[nt][3];
#pragma unroll
        for (int o = 4; o <= 16; o <<= 1) {
            a0 += __shfl_xor_sync(0xffffffffu, a0, o);
            a1 += __shfl_xor_sync(0xffffffffu, a1, o);
            b0 += __shfl_xor_sync(0xffffffffu, b0, o);
            b1 += __shfl_xor_sync(0xffffffffu, b1, o);
        }
        if (lane < 4) {
            int j = nt * 8 + lane * 2;
            psum_sh[(2 * wp) * 128 + j] = a0;
            psum_sh[(2 * wp) * 128 + j + 1] = a1;
            psum_sh[(2 * wp + 1) * 128 + j] = b0;
            psum_sh[(2 * wp + 1) * 128 + j + 1] = b1;
        }
    }
    __syncthreads();

#pragma unroll
    for (int rep = 0; rep < 2; rep++) {
        int t = t0 + 2 * wp + rep;
        int qi = 2 * wp + rep;
        int nv = (t >= 31) ? ((t - 31) / 16 + 1) : 0;
        int b = lane;
        int tb = t >> 6;
        bool forced = (b < 1) || ((b <= tb) && (b >= tb - 1));
        bool valid = (b * 64 <= t);
        float sc;
        if (!valid) sc = -1e30f;
        else if (forced) sc = 1e30f;
        else {
            int jlo = 4 * b - 1; if (jlo < 0) jlo = 0;
            int jhi = 4 * b + 3; if (jhi > nv - 1) jhi = nv - 1;
            float ss = 0.f;
            for (int j = jlo; j <= jhi; j++) ss += psum_sh[qi * 128 + j];
            sc = ss;
        }
        unsigned sel = 0u;
        for (int it = 0; it < 16; it++) {
            float vcur = ((sel >> b) & 1u) ? NEG_INF : sc;
            float m = vcur;
            for (int o = 16; o; o >>= 1) m = fmaxf(m, __shfl_xor_sync(0xffffffffu, m, o));
            unsigned ball = __ballot_sync(0xffffffffu, vcur == m);
            sel |= (1u << (__ffs(ball) - 1));
        }
        if (lane == 0) g_sel[t][kh] = sel;
    }

    uint32_t ph[8][4];
#pragma unroll
    for (int kp = 0; kp < 8; kp++) {
        ph[kp][0] = packh2(s[2*kp][0],   s[2*kp][1]);
        ph[kp][1] = packh2(s[2*kp][2],   s[2*kp][3]);
        ph[kp][2] = packh2(s[2*kp+1][0], s[2*kp+1][1]);
        ph[kp][3] = packh2(s[2*kp+1][2], s[2*kp+1][3]);
    }

    CP_WAIT0();
    __syncthreads();

    float Oc[16][4];
#pragma unroll
    for (int i = 0; i < 16; i++)
#pragma unroll
        for (int c = 0; c < 4; c++) Oc[i][c] = 0.f;
#pragma unroll
    for (int kp = 0; kp < 8; kp++) {
        int keyv = kp * 16 + (grp & 1) * 8 + (lane & 7);
        uint32_t kb = (uint32_t)keyv * 256u, rxv = (uint32_t)(keyv & 7);
#pragma unroll
        for (int dp = 0; dp < 8; dp++) {
            uint32_t c16 = (uint32_t)(dp * 2 + (grp >> 1));
            uint32_t off = kb + ((c16 ^ rxv) << 4);
            uint32_t vh[4];
            ldsm4t(vh, sb + K2_VH + off);
            mma16816h(Oc[2*dp],   ph[kp], vh[0], vh[1]);
            mma16816h(Oc[2*dp+1], ph[kp], vh[2], vh[3]);
        }
    }
#pragma unroll
    for (int nt = 0; nt < 16; nt++) {
        int d0 = nt * 8 + jcl;
        *reinterpret_cast<float2*>(&g_ocmp[t_a][h][d0]) = make_float2(Oc[nt][0], Oc[nt][1]);
        *reinterpret_cast<float2*>(&g_ocmp[t_b][h][d0]) = make_float2(Oc[nt][2], Oc[nt][3]);
    }
}

// ---------------- K3: pure-fp16 HMMA fused slc+win attention ----------------
#define SQHI 0
#define SBUF 32768
#define BUFSZ 32768
#define KHIO 0
#define VHIO 16384
#define SMTOT 98304

__global__ __launch_bounds__(256, 1) void k3_main(
    const float* __restrict__ q, const float* __restrict__ w,
    float* __restrict__ out)
{
    extern __shared__ char smem[];
    uint32_t sbb_ = smem_u32(smem);
    int tid = threadIdx.x;
    int wp = tid >> 5, lane = tid & 31;
    int tile = (int)gridDim.x - 1 - (int)blockIdx.x;
    int t0 = tile * TQ;
    int kh = blockIdx.y;

    __shared__ int s_list[36];
    __shared__ int s_n;
    __shared__ unsigned s_union;

    int g = lane >> 2;
    int t_a = t0 + 2 * wp;
    int t_b = t_a + 1;
    int h = kh * GQ + g;

    unsigned selm_a = g_sel[t_a][kh], selm_b = g_sel[t_b][kh];
    if (tid == 0) s_union = 0u;
    __syncthreads();
    if (lane == 0) atomicOr(&s_union, selm_a | selm_b);

    // stage Q (fp16 hi, swizzled)
    for (int i = tid; i < 128 * 16; i += 256) {
        int row = i >> 4, c16 = i & 15;
        int qrow = (t0 + (row >> 3)) * H_HEADS + kh * GQ + (row & 7);
        uint32_t off = (uint32_t)row * 256u + (uint32_t)((c16 ^ (row & 7)) << 4);
        CP_ASYNC16(sbb_ + SQHI + off, g_qh16 + (size_t)qrow * DDIM + c16 * 8);
    }

    float kmax = __uint_as_float(g_kmax[kh]);
    float Ua, Ub;
    {
        const float4* q4 = reinterpret_cast<const float4*>(q);
        float s2 = 0.f;
        const float4* qr = q4 + ((size_t)(t_a * H_HEADS + h)) * 32;
#pragma unroll 8
        for (int d4 = 0; d4 < 32; d4++) { float4 a = qr[d4]; s2 += a.x*a.x + a.y*a.y + a.z*a.z + a.w*a.w; }
        Ua = SCALE_F * sqrtf(s2) * kmax - EXP_SHIFT;
        s2 = 0.f;
        qr = q4 + ((size_t)(t_b * H_HEADS + h)) * 32;
#pragma unroll 8
        for (int d4 = 0; d4 < 32; d4++) { float4 a = qr[d4]; s2 += a.x*a.x + a.y*a.y + a.z*a.z + a.w*a.w; }
        Ub = SCALE_F * sqrtf(s2) * kmax - EXP_SHIFT;
    }

    __syncthreads();
    unsigned selu = s_union;
    int t_blk = t0 >> 6;

    if (tid == 0) {
        int n = 0;
        for (int b = 0; b <= t_blk; b++) {
            bool need = ((selu >> b) & 1u) || (b * 64 + 63 >= t0 - 511);
            if (need) s_list[n++] = b;
        }
        s_n = n;
    }
    __syncthreads();
    int nch = s_n;

    const __half* khbase = g_kh16 + (size_t)kh * T_LEN * DDIM;
    const __half* vhbase = g_vh16 + (size_t)kh * T_LEN * DDIM;

    {
        int b0 = s_list[0];
        for (int i = tid; i < 1024; i += 256) {
            int row = i >> 4, c16 = i & 15;
            size_t src = (size_t)(b0 * 64 + row) * DDIM + c16 * 8;
            uint32_t dst = sbb_ + SBUF + ((uint32_t)row * 256u + (uint32_t)((c16 ^ (row & 7)) << 4));
            CP_ASYNC16(dst + KHIO, khbase + src);
            CP_ASYNC16(dst + VHIO, vhbase + src);
        }
    }
    CP_COMMIT();
    CP_WAIT0();
    __syncthreads();

    int jcl = (lane & 3) * 2;
    int grp = lane >> 3;

    uint32_t ah[8][4];
    {
        int row = 16 * wp + (grp & 1) * 8 + (lane & 7);
        uint32_t rbase = (uint32_t)row * 256u, rx = (uint32_t)(row & 7);
#pragma unroll
        for (int kt = 0; kt < 8; kt++) {
            uint32_t c16 = (uint32_t)(kt * 2 + (grp >> 1));
            ldsm4(ah[kt], sbb_ + SQHI + rbase + ((c16 ^ rx) << 4));
        }
    }

    float Os[16][4], Ow[16][4];
#pragma unroll
    for (int i = 0; i < 16; i++)
#pragma unroll
        for (int c = 0; c < 4; c++) { Os[i][c] = 0.f; Ow[i][c] = 0.f; }
    float sum_sa = 0.f, sum_sb = 0.f, sum_wa = 0.f, sum_wb = 0.f;

    for (int ci = 0; ci < nch; ci++) {
        int b = s_list[ci];
        bool do_s = (selu >> b) & 1u;
        bool do_w = (b * 64 + 63 >= t0 - 511);
        uint32_t KB = sbb_ + SBUF + (uint32_t)(ci & 1) * BUFSZ;

        if (ci > 0) {
            CP_WAIT0();
            __syncthreads();
        }
        if (ci + 1 < nch) {
            int bn = s_list[ci + 1];
            uint32_t NB = sbb_ + SBUF + (uint32_t)((ci + 1) & 1) * BUFSZ;
            for (int i = tid; i < 1024; i += 256) {
                int row = i >> 4, c16 = i & 15;
                size_t src = (size_t)(bn * 64 + row) * DDIM + c16 * 8;
                uint32_t dst = NB + ((uint32_t)row * 256u + (uint32_t)((c16 ^ (row & 7)) << 4));
                CP_ASYNC16(dst + KHIO, khbase + src);
                CP_ASYNC16(dst + VHIO, vhbase + src);
            }
            CP_COMMIT();
        }

#pragma unroll
        for (int np = 0; np < 4; np++) {
            float s0[4] = {0.f, 0.f, 0.f, 0.f}, s1[4] = {0.f, 0.f, 0.f, 0.f};
            {
                int keyq = np * 16 + (grp >> 1) * 8 + (lane & 7);
                uint32_t kb = (uint32_t)keyq * 256u, rxk = (uint32_t)(keyq & 7);
#pragma unroll
                for (int kt = 0; kt < 8; kt++) {
                    uint32_t ck = (uint32_t)(kt * 2 + (grp & 1));
                    uint32_t bh[4];
                    ldsm4(bh, KB + KHIO + kb + ((ck ^ rxk) << 4));
                    mma16816h(s0, ah[kt], bh[0], bh[1]);
                    mma16816h(s1, ah[kt], bh[2], bh[3]);
                }
            }
            int j0 = b * 64 + np * 16 + jcl;
            float ea0 = __expf(s0[0] * SCALE_F - Ua);
            float ea1 = __expf(s0[1] * SCALE_F - Ua);
            float eb0 = __expf(s0[2] * SCALE_F - Ub);
            float eb1 = __expf(s0[3] * SCALE_F - Ub);
            float fa0 = __expf(s1[0] * SCALE_F - Ua);
            float fa1 = __expf(s1[1] * SCALE_F - Ua);
            float fb0 = __expf(s1[2] * SCALE_F - Ub);
            float fb1 = __expf(s1[3] * SCALE_F - Ub);
            bool sa = (selm_a >> b) & 1u, sb2 = (selm_b >> b) & 1u;
            int j1 = j0 + 1, j8 = j0 + 8, j9 = j0 + 9;

            float esa0 = (sa  && j0 <= t_a) ? ea0 : 0.f;
            float esa1 = (sa  && j1 <= t_a) ? ea1 : 0.f;
            float esb0 = (sb2 && j0 <= t_b) ? eb0 : 0.f;
            float esb1 = (sb2 && j1 <= t_b) ? eb1 : 0.f;
            float fsa0 = (sa  && j8 <= t_a) ? fa0 : 0.f;
            float fsa1 = (sa  && j9 <= t_a) ? fa1 : 0.f;
            float fsb0 = (sb2 && j8 <= t_b) ? fb0 : 0.f;
            float fsb1 = (sb2 && j9 <= t_b) ? fb1 : 0.f;

            float ewa0 = (j0 <= t_a && t_a - j0 < 512) ? ea0 : 0.f;
            float ewa1 = (j1 <= t_a && t_a - j1 < 512) ? ea1 : 0.f;
            float ewb0 = (j0 <= t_b && t_b - j0 < 512) ? eb0 : 0.f;
            float ewb1 = (j1 <= t_b && t_b - j1 < 512) ? eb1 : 0.f;
            float fwa0 = (j8 <= t_a && t_a - j8 < 512) ? fa0 : 0.f;
            float fwa1 = (j9 <= t_a && t_a - j9 < 512) ? fa1 : 0.f;
            float fwb0 = (j8 <= t_b && t_b - j8 < 512) ? fb0 : 0.f;
            float fwb1 = (j9 <= t_b && t_b - j9 < 512) ? fb1 : 0.f;

            sum_sa += esa0 + esa1 + fsa0 + fsa1;
            sum_sb += esb0 + esb1 + fsb0 + fsb1;
            sum_wa += ewa0 + ewa1 + fwa0 + fwa1;
            sum_wb += ewb0 + ewb1 + fwb0 + fwb1;

            uint32_t ps[4], pw[4];
            ps[0] = packh2(esa0, esa1);
            ps[1] = packh2(esb0, esb1);
            ps[2] = packh2(fsa0, fsa1);
            ps[3] = packh2(fsb0, fsb1);
            pw[0] = packh2(ewa0, ewa1);
            pw[1] = packh2(ewb0, ewb1);
            pw[2] = packh2(fwa0, fwa1);
            pw[3] = packh2(fwb0, fwb1);

            {
                int keyv = np * 16 + (grp & 1) * 8 + (lane & 7);
                uint32_t kb = (uint32_t)keyv * 256u, rxv = (uint32_t)(keyv & 7);
#pragma unroll
                for (int dp = 0; dp < 8; dp++) {
                    uint32_t c16 = (uint32_t)(dp * 2 + (grp >> 1));
                    uint32_t off = kb + ((c16 ^ rxv) << 4);
                    uint32_t vh[4];
                    ldsm4t(vh, KB + VHIO + off);
                    if (do_s) {
                        mma16816h(Os[2 * dp],     ps, vh[0], vh[1]);
                        mma16816h(Os[2 * dp + 1], ps, vh[2], vh[3]);
                    }
                    if (do_w) {
                        mma16816h(Ow[2 * dp],     pw, vh[0], vh[1]);
                        mma16816h(Ow[2 * dp + 1], pw, vh[2], vh[3]);
                    }
                }
            }
        }
    }

#pragma unroll
    for (int o = 1; o <= 2; o <<= 1) {
        sum_sa += __shfl_xor_sync(0xffffffffu, sum_sa, o);
        sum_sb += __shfl_xor_sync(0xffffffffu, sum_sb, o);
        sum_wa += __shfl_xor_sync(0xffffffffu, sum_wa, o);
        sum_wb += __shfl_xor_sync(0xffffffffu, sum_wb, o);
    }
    float inv_sa = 1.f / sum_sa, inv_sb = 1.f / sum_sb;
    float inv_wa = 1.f / sum_wa, inv_wb = 1.f / sum_wb;

    const float* wa = w + ((size_t)(t_a * H_HEADS + h)) * 3;
    const float* wb = w + ((size_t)(t_b * H_HEADS + h)) * 3;
    float w0a = wa[0], w1a = wa[1], w2a = wa[2];
    float w0b = wb[0], w1b = wb[1], w2b = wb[2];

#pragma unroll
    for (int nt = 0; nt < 16; nt++) {
        int d0 = nt * 8 + jcl;
        const float2* ca = reinterpret_cast<const float2*>(&g_ocmp[t_a][h][d0]);
        const float2* cb = reinterpret_cast<const float2*>(&g_ocmp[t_b][h][d0]);
        float2 oc_a = *ca, oc_b = *cb;
        float2 oa, ob;
        oa.x = w0a * oc_a.x + w1a * Os[nt][0] * inv_sa + w2a * Ow[nt][0] * inv_wa;
        oa.y = w0a * oc_a.y + w1a * Os[nt][1] * inv_sa + w2a * Ow[nt][1] * inv_wa;
        ob.x = w0b * oc_b.x + w1b * Os[nt][2] * inv_sb + w2b * Ow[nt][2] * inv_wb;
        ob.y = w0b * oc_b.y + w1b * Os[nt][3] * inv_sb + w2b * Ow[nt][3] * inv_wb;
        *reinterpret_cast<float2*>(out + ((size_t)(t_a * H_HEADS + h)) * DDIM + d0) = oa;
        *reinterpret_cast<float2*>(out + ((size_t)(t_b * H_HEADS + h)) * DDIM + d0) = ob;
    }
}

// ---------------- launch ----------------
extern "C" void kernel_launch(void* const* d_in, const int* in_sizes, int n_in,
                              void* d_out, int out_size) {
    const float* q = (const float*)d_in[0];
    const float* k = (const float*)d_in[1];
    const float* v = (const float*)d_in[2];
    const float* w = (const float*)d_in[3];
    float* out = (float*)d_out;

    cudaFuncSetAttribute(k2_tc, cudaFuncAttributeMaxDynamicSharedMemorySize, K2_TOT);
    cudaFuncSetAttribute(k3_main, cudaFuncAttributeMaxDynamicSharedMemorySize, SMTOT);

    k0_split<<<1024, 256>>>(q, k, v);
    k1_compress<<<dim3(NCMP, KHN), DDIM>>>(k, v);
    k1b_knorm<<<dim3(T_LEN, KHN), 32>>>(k);
    k2_tc<<<dim3(T_LEN / TQ, KHN), 256, K2_TOT>>>();
    k3_main<<<dim3(T_LEN / TQ, KHN), 256, SMTOT>>>(q, w, out);
}

// round 10
// speedup vs baseline: 10.1891x; 1.1282x over previous
#include <cuda_runtime.h>
#include <cuda_fp16.h>
#include <math.h>
#include <stdint.h>

#define T_LEN 2048
#define H_HEADS 16
#define KHN 2
#define GQ 8
#define DDIM 128
#define NCMP 127
#define TQ 16
#define SCALE_F 0.08838834765f
#define EXP_SHIFT 10.3972077f   /* ln(2^15) */
#define NEG_INF (-INFINITY)

// ---------------- scratch ----------------
__device__ unsigned g_kmax[KHN];

__device__ __align__(16) __half g_qh16[T_LEN * H_HEADS * DDIM];
__device__ __align__(16) __half g_ql16[T_LEN * H_HEADS * DDIM];
__device__ __align__(16) __half g_kh16[KHN * T_LEN * DDIM];
__device__ __align__(16) __half g_vh16[KHN * T_LEN * DDIM];
__device__ __align__(16) __half g_ckhi[KHN][128][DDIM];
__device__ __align__(16) __half g_cklo[KHN][128][DDIM];
__device__ __align__(16) __half g_cvhi[KHN][128][DDIM];

// ---------------- helpers ----------------
__device__ __forceinline__ uint32_t smem_u32(const void* p) {
    uint32_t a;
    asm("{ .reg .u64 t; cvta.to.shared.u64 t, %1; cvt.u32.u64 %0, t; }" : "=r"(a) : "l"(p));
    return a;
}
__device__ __forceinline__ void mma16816h(float* d, const uint32_t* a, uint32_t b0, uint32_t b1) {
    asm volatile("mma.sync.aligned.m16n8k16.row.col.f32.f16.f16.f32 "
        "{%0,%1,%2,%3},{%4,%5,%6,%7},{%8,%9},{%0,%1,%2,%3};"
        : "+f"(d[0]), "+f"(d[1]), "+f"(d[2]), "+f"(d[3])
        : "r"(a[0]), "r"(a[1]), "r"(a[2]), "r"(a[3]), "r"(b0), "r"(b1));
}
__device__ __forceinline__ void ldsm4(uint32_t* r, uint32_t addr) {
    asm volatile("ldmatrix.sync.aligned.m8n8.x4.shared.b16 {%0,%1,%2,%3}, [%4];"
        : "=r"(r[0]), "=r"(r[1]), "=r"(r[2]), "=r"(r[3]) : "r"(addr));
}
__device__ __forceinline__ void ldsm4t(uint32_t* r, uint32_t addr) {
    asm volatile("ldmatrix.sync.aligned.m8n8.x4.trans.shared.b16 {%0,%1,%2,%3}, [%4];"
        : "=r"(r[0]), "=r"(r[1]), "=r"(r[2]), "=r"(r[3]) : "r"(addr));
}
__device__ __forceinline__ uint32_t packh2(float a, float b) {
    __half2 h = __floats2half2_rn(a, b);
    return *reinterpret_cast<uint32_t*>(&h);
}
#define CP_ASYNC16(dst, src) \
    asm volatile("cp.async.cg.shared.global [%0], [%1], 16;" :: "r"(dst), "l"(src) : "memory")
#define CP_COMMIT() asm volatile("cp.async.commit_group;" ::: "memory")
#define CP_WAIT0()  asm volatile("cp.async.wait_group 0;" ::: "memory")
#define CP_WAIT1()  asm volatile("cp.async.wait_group 1;" ::: "memory")

// ---------------- K0: pre-split ----------------
__global__ void k0_split(const float* __restrict__ q, const float* __restrict__ k,
                         const float* __restrict__ v) {
    int stride = gridDim.x * blockDim.x;
    int idx = blockIdx.x * blockDim.x + threadIdx.x;
    const int n_kv = T_LEN * KHN * DDIM;
    for (int i = idx; i < n_kv; i += stride) {
        int d = i & (DDIM - 1);
        int tk = i >> 7;
        int kh = tk & 1, t = tk >> 1;
        int o = (kh * T_LEN + t) * DDIM + d;
        g_kh16[o] = __float2half_rn(k[i]);
        g_vh16[o] = __float2half_rn(v[i]);
    }
    const int n_q = T_LEN * H_HEADS * DDIM;
    for (int i = idx; i < n_q; i += stride) {
        float x = q[i];
        __half hh = __float2half_rn(x);
        g_qh16[i] = hh;
        g_ql16[i] = __float2half_rn(x - __half2float(hh));
    }
}

// ---------------- K1: compressed K/V ----------------
__global__ void k1_compress(const float* __restrict__ k, const float* __restrict__ v) {
    int j = blockIdx.x, kh = blockIdx.y, d = threadIdx.x;
    int s = j * 16;
    float sk = 0.f, sv = 0.f;
#pragma unroll 8
    for (int i = 0; i < 32; i++) {
        sk += k[((size_t)(s + i) * KHN + kh) * DDIM + d];
        sv += v[((size_t)(s + i) * KHN + kh) * DDIM + d];
    }
    float ck = sk * (1.f / 32.f), cv = sv * (1.f / 32.f);
    __half h = __float2half_rn(ck);
    g_ckhi[kh][j][d] = h;
    g_cklo[kh][j][d] = __float2half_rn(ck - __half2float(h));
    g_cvhi[kh][j][d] = __float2half_rn(cv);
}

// ---------------- K1b: max ||k_row|| per kv head ----------------
__global__ void k1b_knorm(const float* __restrict__ k) {
    int t = blockIdx.x, kh = blockIdx.y, lane = threadIdx.x;
    const float4* kr = reinterpret_cast<const float4*>(k) + ((size_t)t * KHN + kh) * 32;
    float4 a = kr[lane];
    float s = a.x * a.x + a.y * a.y + a.z * a.z + a.w * a.w;
    for (int o = 16; o; o >>= 1) s += __shfl_xor_sync(0xffffffffu, s, o);
    if (lane == 0) atomicMax(&g_kmax[kh], __float_as_uint(sqrtf(s)));
}

// ---------------- K23: fused compressed + selected + window attention ----------------
// smem layout (bytes), peak 160KB:
//  [0,32K)    QH          (both phases)
//  [32,64K)   QL (ph1 QK)     -> phase2 KV buf0 (KH 16K + VH 16K)
//  [64,96K)   CKH (ph1 QK)    -> CVH (ph1 PV)  -> phase2 KV buf1
//  [96,128K)  CKL (ph1 QK)    -> Oc scratch (lower)
//  [128,136K) psum (ph1)      -> Oc scratch (mid)
//  [136,160K) unused (ph1)    -> Oc scratch (upper)
#define SQH   0
#define SQL   32768
#define SCKH  65536
#define SCKL  98304
#define SPS   131072
#define SOC   98304
#define SBUF  32768
#define BUFSZ 32768
#define VHIO  16384
#define SMTOT 163840

__global__ __launch_bounds__(256, 1) void k23_fused(
    const float* __restrict__ q, const float* __restrict__ w,
    float* __restrict__ out)
{
    extern __shared__ char smem[];
    uint32_t sb = smem_u32(smem);
    float* psum_sh = reinterpret_cast<float*>(smem + SPS);
    float* oc_sh = reinterpret_cast<float*>(smem + SOC);
    int tid = threadIdx.x;
    int wp = tid >> 5, lane = tid & 31;
    int tile = (int)gridDim.x - 1 - (int)blockIdx.x;   // heavy tiles first
    int t0 = tile * TQ;
    int kh = blockIdx.y;
    int grp = lane >> 3;
    int jcl = (lane & 3) * 2;

    __shared__ int s_list[36];
    __shared__ int s_n;
    __shared__ unsigned s_union;

    int t_a = t0 + 2 * wp;
    int t_b = t_a + 1;
    int g = lane >> 2;
    int h = kh * GQ + g;

    if (tid == 0) s_union = 0u;

    // ---- stage QH/QL + CKH/CKL ----
    for (int i = tid; i < 128 * 16; i += 256) {
        int row = i >> 4, c16 = i & 15;
        uint32_t off = (uint32_t)row * 256u + (uint32_t)((c16 ^ (row & 7)) << 4);
        int qrow = (t0 + (row >> 3)) * H_HEADS + kh * GQ + (row & 7);
        CP_ASYNC16(sb + SQH + off, g_qh16 + (size_t)qrow * DDIM + c16 * 8);
        CP_ASYNC16(sb + SQL + off, g_ql16 + (size_t)qrow * DDIM + c16 * 8);
        CP_ASYNC16(sb + SCKH + off, &g_ckhi[kh][row][c16 * 8]);
        CP_ASYNC16(sb + SCKL + off, &g_cklo[kh][row][c16 * 8]);
    }
    CP_COMMIT();

    // exponent offsets (fp32 q)
    float kmaxv = __uint_as_float(g_kmax[kh]);
    float Ua, Ub;
    {
        const float4* q4 = reinterpret_cast<const float4*>(q);
        float s2 = 0.f;
        const float4* qr = q4 + ((size_t)(t_a * H_HEADS + h)) * 32;
#pragma unroll 8
        for (int d4 = 0; d4 < 32; d4++) { float4 a = qr[d4]; s2 += a.x*a.x + a.y*a.y + a.z*a.z + a.w*a.w; }
        Ua = SCALE_F * sqrtf(s2) * kmaxv - EXP_SHIFT;
        s2 = 0.f;
        qr = q4 + ((size_t)(t_b * H_HEADS + h)) * 32;
#pragma unroll 8
        for (int d4 = 0; d4 < 32; d4++) { float4 a = qr[d4]; s2 += a.x*a.x + a.y*a.y + a.z*a.z + a.w*a.w; }
        Ub = SCALE_F * sqrtf(s2) * kmaxv - EXP_SHIFT;
    }

    CP_WAIT0();
    __syncthreads();

    int nva = (t_a >= 31) ? ((t_a - 31) / 16 + 1) : 0;
    int nvb = (t_b >= 31) ? ((t_b - 31) / 16 + 1) : 0;

    // ---- Q-hi fragments (used by BOTH phases) ----
    uint32_t ah[8][4];
    {
        int row = 16 * wp + (grp & 1) * 8 + (lane & 7);
        uint32_t rb = (uint32_t)row * 256u, rx = (uint32_t)(row & 7);
#pragma unroll
        for (int kt = 0; kt < 8; kt++) {
            uint32_t cq = (uint32_t)(kt * 2 + (grp >> 1));
            ldsm4(ah[kt], sb + SQH + rb + ((cq ^ rx) << 4));
        }
    }

    unsigned selm_a, selm_b;

    // ================= PHASE 1: compressed attention + selection =================
    {
        float s[16][4];
#pragma unroll
        for (int i = 0; i < 16; i++)
#pragma unroll
            for (int c = 0; c < 4; c++) s[i][c] = 0.f;

#pragma unroll
        for (int np = 0; np < 8; np++) {
            int keyq = np * 16 + (grp >> 1) * 8 + (lane & 7);
            uint32_t kb = (uint32_t)keyq * 256u, rxk = (uint32_t)(keyq & 7);
            int rowq = 16 * wp + (grp & 1) * 8 + (lane & 7);
            uint32_t rq = (uint32_t)rowq * 256u, rxq = (uint32_t)(rowq & 7);
#pragma unroll
            for (int kt = 0; kt < 8; kt++) {
                uint32_t ck = (uint32_t)(kt * 2 + (grp & 1));
                uint32_t bo = kb + ((ck ^ rxk) << 4);
                uint32_t cq = (uint32_t)(kt * 2 + (grp >> 1));
                uint32_t bh[4], bl[4], al[4];
                ldsm4(bh, sb + SCKH + bo);
                ldsm4(bl, sb + SCKL + bo);
                ldsm4(al, sb + SQL + rq + ((cq ^ rxq) << 4));
                mma16816h(s[2*np],   ah[kt], bh[0], bh[1]);
                mma16816h(s[2*np+1], ah[kt], bh[2], bh[3]);
                mma16816h(s[2*np],   ah[kt], bl[0], bl[1]);
                mma16816h(s[2*np+1], ah[kt], bl[2], bl[3]);
                mma16816h(s[2*np],   al,     bh[0], bh[1]);
                mma16816h(s[2*np+1], al,     bh[2], bh[3]);
            }
        }
        __syncthreads();   // QL/CKH/CKL reads done

        // stage cmp_v-hi into CKH region (group 1)
        for (int i = tid; i < 128 * 16; i += 256) {
            int row = i >> 4, c16 = i & 15;
            uint32_t off = (uint32_t)row * 256u + (uint32_t)((c16 ^ (row & 7)) << 4);
            CP_ASYNC16(sb + SCKH + off, &g_cvhi[kh][row][c16 * 8]);
        }
        CP_COMMIT();

        // softmax (exact fp32)
        float ma = NEG_INF, mb = NEG_INF;
#pragma unroll
        for (int nt = 0; nt < 16; nt++) {
            int j0 = nt * 8 + jcl;
            if (j0 < nva)     ma = fmaxf(ma, s[nt][0] * SCALE_F);
            if (j0 + 1 < nva) ma = fmaxf(ma, s[nt][1] * SCALE_F);
            if (j0 < nvb)     mb = fmaxf(mb, s[nt][2] * SCALE_F);
            if (j0 + 1 < nvb) mb = fmaxf(mb, s[nt][3] * SCALE_F);
        }
#pragma unroll
        for (int o = 1; o <= 2; o <<= 1) {
            ma = fmaxf(ma, __shfl_xor_sync(0xffffffffu, ma, o));
            mb = fmaxf(mb, __shfl_xor_sync(0xffffffffu, mb, o));
        }
        float la = 0.f, lb = 0.f;
#pragma unroll
        for (int nt = 0; nt < 16; nt++) {
            int j0 = nt * 8 + jcl;
            float e0 = (j0 < nva)     ? expf(s[nt][0] * SCALE_F - ma) : 0.f;
            float e1 = (j0 + 1 < nva) ? expf(s[nt][1] * SCALE_F - ma) : 0.f;
            float e2 = (j0 < nvb)     ? expf(s[nt][2] * SCALE_F - mb) : 0.f;
            float e3 = (j0 + 1 < nvb) ? expf(s[nt][3] * SCALE_F - mb) : 0.f;
            s[nt][0] = e0; s[nt][1] = e1; s[nt][2] = e2; s[nt][3] = e3;
            la += e0 + e1; lb += e2 + e3;
        }
#pragma unroll
        for (int o = 1; o <= 2; o <<= 1) {
            la += __shfl_xor_sync(0xffffffffu, la, o);
            lb += __shfl_xor_sync(0xffffffffu, lb, o);
        }
        float inva = (nva > 0) ? 1.f / la : 0.f;
        float invb = (nvb > 0) ? 1.f / lb : 0.f;
#pragma unroll
        for (int nt = 0; nt < 16; nt++) {
            s[nt][0] *= inva; s[nt][1] *= inva;
            s[nt][2] *= invb; s[nt][3] *= invb;
        }

        // psum (group-summed probabilities)
#pragma unroll
        for (int nt = 0; nt < 16; nt++) {
            float a0 = s[nt][0], a1 = s[nt][1], b0 = s[nt][2], b1 = s[nt][3];
#pragma unroll
            for (int o = 4; o <= 16; o <<= 1) {
                a0 += __shfl_xor_sync(0xffffffffu, a0, o);
                a1 += __shfl_xor_sync(0xffffffffu, a1, o);
                b0 += __shfl_xor_sync(0xffffffffu, b0, o);
                b1 += __shfl_xor_sync(0xffffffffu, b1, o);
            }
            if (lane < 4) {
                int j = nt * 8 + lane * 2;
                psum_sh[(2 * wp) * 128 + j] = a0;
                psum_sh[(2 * wp) * 128 + j + 1] = a1;
                psum_sh[(2 * wp + 1) * 128 + j] = b0;
                psum_sh[(2 * wp + 1) * 128 + j + 1] = b1;
            }
        }
        __syncthreads();

        // top-16 selection (exact fp32) — masks stay in registers
        unsigned selres[2];
#pragma unroll
        for (int rep = 0; rep < 2; rep++) {
            int t = t0 + 2 * wp + rep;
            int qi = 2 * wp + rep;
            int nv = (t >= 31) ? ((t - 31) / 16 + 1) : 0;
            int b = lane;
            int tb = t >> 6;
            bool forced = (b < 1) || ((b <= tb) && (b >= tb - 1));
            bool valid = (b * 64 <= t);
            float sc;
            if (!valid) sc = -1e30f;
            else if (forced) sc = 1e30f;
            else {
                int jlo = 4 * b - 1; if (jlo < 0) jlo = 0;
                int jhi = 4 * b + 3; if (jhi > nv - 1) jhi = nv - 1;
                float ss = 0.f;
                for (int j = jlo; j <= jhi; j++) ss += psum_sh[qi * 128 + j];
                sc = ss;
            }
            unsigned sel = 0u;
            for (int it = 0; it < 16; it++) {
                float vcur = ((sel >> b) & 1u) ? NEG_INF : sc;
                float m = vcur;
                for (int o = 16; o; o >>= 1) m = fmaxf(m, __shfl_xor_sync(0xffffffffu, m, o));
                unsigned ball = __ballot_sync(0xffffffffu, vcur == m);
                sel |= (1u << (__ffs(ball) - 1));
            }
            selres[rep] = sel;
        }
        selm_a = selres[0];
        selm_b = selres[1];
        if (lane == 0) atomicOr(&s_union, selm_a | selm_b);

        // pack normalized P
        uint32_t ph[8][4];
#pragma unroll
        for (int kp = 0; kp < 8; kp++) {
            ph[kp][0] = packh2(s[2*kp][0],   s[2*kp][1]);
            ph[kp][1] = packh2(s[2*kp][2],   s[2*kp][3]);
            ph[kp][2] = packh2(s[2*kp+1][0], s[2*kp+1][1]);
            ph[kp][3] = packh2(s[2*kp+1][2], s[2*kp+1][3]);
        }

        CP_WAIT0();
        __syncthreads();   // CVH ready

        // PV: O_cmp = P * cmp_v
        float Oc[16][4];
#pragma unroll
        for (int i = 0; i < 16; i++)
#pragma unroll
            for (int c = 0; c < 4; c++) Oc[i][c] = 0.f;
#pragma unroll
        for (int kp = 0; kp < 8; kp++) {
            int keyv = kp * 16 + (grp & 1) * 8 + (lane & 7);
            uint32_t kb = (uint32_t)keyv * 256u, rxv = (uint32_t)(keyv & 7);
#pragma unroll
            for (int dp = 0; dp < 8; dp++) {
                uint32_t c16 = (uint32_t)(dp * 2 + (grp >> 1));
                uint32_t off = kb + ((c16 ^ rxv) << 4);
                uint32_t vh[4];
                ldsm4t(vh, sb + SCKH + off);
                mma16816h(Oc[2*dp],   ph[kp], vh[0], vh[1]);
                mma16816h(Oc[2*dp+1], ph[kp], vh[2], vh[3]);
            }
        }
        __syncthreads();   // CVH reads done; psum dead -> SOC region free

        // park Oc in smem scratch (conflict-free [idx*256+tid])
#pragma unroll
        for (int nt = 0; nt < 16; nt++)
#pragma unroll
            for (int c = 0; c < 4; c++)
                oc_sh[(nt * 4 + c) * 256 + tid] = Oc[nt][c];
    }

    // ================= PHASE 2: selected + window attention =================
    __syncthreads();
    unsigned selu = s_union;
    int t_blk = t0 >> 6;

    if (tid == 0) {
        int n = 0;
        for (int b = 0; b <= t_blk; b++) {
            bool need = ((selu >> b) & 1u) || (b * 64 + 63 >= t0 - 511);
            if (need) s_list[n++] = b;
        }
        s_n = n;
    }
    __syncthreads();
    int nch = s_n;

    const __half* khbase = g_kh16 + (size_t)kh * T_LEN * DDIM;
    const __half* vhbase = g_vh16 + (size_t)kh * T_LEN * DDIM;

    {
        int b0 = s_list[0];
        for (int i = tid; i < 1024; i += 256) {
            int row = i >> 4, c16 = i & 15;
            size_t src = (size_t)(b0 * 64 + row) * DDIM + c16 * 8;
            uint32_t dst = sb + SBUF + ((uint32_t)row * 256u + (uint32_t)((c16 ^ (row & 7)) << 4));
            CP_ASYNC16(dst, khbase + src);
            CP_ASYNC16(dst + VHIO, vhbase + src);
        }
    }
    CP_COMMIT();
    CP_WAIT0();
    __syncthreads();

    float Os[16][4], Ow[16][4];
#pragma unroll
    for (int i = 0; i < 16; i++)
#pragma unroll
        for (int c = 0; c < 4; c++) { Os[i][c] = 0.f; Ow[i][c] = 0.f; }
    float sum_sa = 0.f, sum_sb = 0.f, sum_wa = 0.f, sum_wb = 0.f;

    for (int ci = 0; ci < nch; ci++) {
        int b = s_list[ci];
        bool do_s = (selu >> b) & 1u;
        bool do_w = (b * 64 + 63 >= t0 - 511);
        uint32_t KB = sb + SBUF + (uint32_t)(ci & 1) * BUFSZ;

        if (ci > 0) {
            CP_WAIT0();
            __syncthreads();
        }
        if (ci + 1 < nch) {
            int bn = s_list[ci + 1];
            uint32_t NB = sb + SBUF + (uint32_t)((ci + 1) & 1) * BUFSZ;
            for (int i = tid; i < 1024; i += 256) {
                int row = i >> 4, c16 = i & 15;
                size_t src = (size_t)(bn * 64 + row) * DDIM + c16 * 8;
                uint32_t dst = NB + ((uint32_t)row * 256u + (uint32_t)((c16 ^ (row & 7)) << 4));
                CP_ASYNC16(dst, khbase + src);
                CP_ASYNC16(dst + VHIO, vhbase + src);
            }
            CP_COMMIT();
        }

#pragma unroll
        for (int np = 0; np < 4; np++) {
            float s0[4] = {0.f, 0.f, 0.f, 0.f}, s1[4] = {0.f, 0.f, 0.f, 0.f};
            {
                int keyq = np * 16 + (grp >> 1) * 8 + (lane & 7);
                uint32_t kb = (uint32_t)keyq * 256u, rxk = (uint32_t)(keyq & 7);
#pragma unroll
                for (int kt = 0; kt < 8; kt++) {
                    uint32_t ck = (uint32_t)(kt * 2 + (grp & 1));
                    uint32_t bh[4];
                    ldsm4(bh, KB + kb + ((ck ^ rxk) << 4));
                    mma16816h(s0, ah[kt], bh[0], bh[1]);
                    mma16816h(s1, ah[kt], bh[2], bh[3]);
                }
            }
            int j0 = b * 64 + np * 16 + jcl;
            float ea0 = __expf(s0[0] * SCALE_F - Ua);
            float ea1 = __expf(s0[1] * SCALE_F - Ua);
            float eb0 = __expf(s0[2] * SCALE_F - Ub);
            float eb1 = __expf(s0[3] * SCALE_F - Ub);
            float fa0 = __expf(s1[0] * SCALE_F - Ua);
            float fa1 = __expf(s1[1] * SCALE_F - Ua);
            float fb0 = __expf(s1[2] * SCALE_F - Ub);
            float fb1 = __expf(s1[3] * SCALE_F - Ub);
            bool sa = (selm_a >> b) & 1u, sb2 = (selm_b >> b) & 1u;
            int j1 = j0 + 1, j8 = j0 + 8, j9 = j0 + 9;

            float esa0 = (sa  && j0 <= t_a) ? ea0 : 0.f;
            float esa1 = (sa  && j1 <= t_a) ? ea1 : 0.f;
            float esb0 = (sb2 && j0 <= t_b) ? eb0 : 0.f;
            float esb1 = (sb2 && j1 <= t_b) ? eb1 : 0.f;
            float fsa0 = (sa  && j8 <= t_a) ? fa0 : 0.f;
            float fsa1 = (sa  && j9 <= t_a) ? fa1 : 0.f;
            float fsb0 = (sb2 && j8 <= t_b) ? fb0 : 0.f;
            float fsb1 = (sb2 && j9 <= t_b) ? fb1 : 0.f;

            float ewa0 = (j0 <= t_a && t_a - j0 < 512) ? ea0 : 0.f;
            float ewa1 = (j1 <= t_a && t_a - j1 < 512) ? ea1 : 0.f;
            float ewb0 = (j0 <= t_b && t_b - j0 < 512) ? eb0 : 0.f;
            float ewb1 = (j1 <= t_b && t_b - j1 < 512) ? eb1 : 0.f;
            float fwa0 = (j8 <= t_a && t_a - j8 < 512) ? fa0 : 0.f;
            float fwa1 = (j9 <= t_a && t_a - j9 < 512) ? fa1 : 0.f;
            float fwb0 = (j8 <= t_b && t_b - j8 < 512) ? fb0 : 0.f;
            float fwb1 = (j9 <= t_b && t_b - j9 < 512) ? fb1 : 0.f;

            sum_sa += esa0 + esa1 + fsa0 + fsa1;
            sum_sb += esb0 + esb1 + fsb0 + fsb1;
            sum_wa += ewa0 + ewa1 + fwa0 + fwa1;
            sum_wb += ewb0 + ewb1 + fwb0 + fwb1;

            uint32_t ps[4], pw[4];
            ps[0] = packh2(esa0, esa1);
            ps[1] = packh2(esb0, esb1);
            ps[2] = packh2(fsa0, fsa1);
            ps[3] = packh2(fsb0, fsb1);
            pw[0] = packh2(ewa0, ewa1);
            pw[1] = packh2(ewb0, ewb1);
            pw[2] = packh2(fwa0, fwa1);
            pw[3] = packh2(fwb0, fwb1);

            {
                int keyv = np * 16 + (grp & 1) * 8 + (lane & 7);
                uint32_t kb = (uint32_t)keyv * 256u, rxv = (uint32_t)(keyv & 7);
#pragma unroll
                for (int dp = 0; dp < 8; dp++) {
                    uint32_t c16 = (uint32_t)(dp * 2 + (grp >> 1));
                    uint32_t off = kb + ((c16 ^ rxv) << 4);
                    uint32_t vh[4];
                    ldsm4t(vh, KB + VHIO + off);
                    if (do_s) {
                        mma16816h(Os[2 * dp],     ps, vh[0], vh[1]);
                        mma16816h(Os[2 * dp + 1], ps, vh[2], vh[3]);
                    }
                    if (do_w) {
                        mma16816h(Ow[2 * dp],     pw, vh[0], vh[1]);
                        mma16816h(Ow[2 * dp + 1], pw, vh[2], vh[3]);
                    }
                }
            }
        }
    }

    // ---- epilogue ----
#pragma unroll
    for (int o = 1; o <= 2; o <<= 1) {
        sum_sa += __shfl_xor_sync(0xffffffffu, sum_sa, o);
        sum_sb += __shfl_xor_sync(0xffffffffu, sum_sb, o);
        sum_wa += __shfl_xor_sync(0xffffffffu, sum_wa, o);
        sum_wb += __shfl_xor_sync(0xffffffffu, sum_wb, o);
    }
    float inv_sa = 1.f / sum_sa, inv_sb = 1.f / sum_sb;
    float inv_wa = 1.f / sum_wa, inv_wb = 1.f / sum_wb;

    const float* wa = w + ((size_t)(t_a * H_HEADS + h)) * 3;
    const float* wb = w + ((size_t)(t_b * H_HEADS + h)) * 3;
    float w0a = wa[0], w1a = wa[1], w2a = wa[2];
    float w0b = wb[0], w1b = wb[1], w2b = wb[2];

#pragma unroll
    for (int nt = 0; nt < 16; nt++) {
        int d0 = nt * 8 + jcl;
        float oca0 = oc_sh[(nt * 4 + 0) * 256 + tid];
        float oca1 = oc_sh[(nt * 4 + 1) * 256 + tid];
        float ocb0 = oc_sh[(nt * 4 + 2) * 256 + tid];
        float ocb1 = oc_sh[(nt * 4 + 3) * 256 + tid];
        float2 oa, ob;
        oa.x = w0a * oca0 + w1a * Os[nt][0] * inv_sa + w2a * Ow[nt][0] * inv_wa;
        oa.y = w0a * oca1 + w1a * Os[nt][1] * inv_sa + w2a * Ow[nt][1] * inv_wa;
        ob.x = w0b * ocb0 + w1b * Os[nt][2] * inv_sb + w2b * Ow[nt][2] * inv_wb;
        ob.y = w0b * ocb1 + w1b * Os[nt][3] * inv_sb + w2b * Ow[nt][3] * inv_wb;
        *reinterpret_cast<float2*>(out + ((size_t)(t_a * H_HEADS + h)) * DDIM + d0) = oa;
        *reinterpret_cast<float2*>(out + ((size_t)(t_b * H_HEADS + h)) * DDIM + d0) = ob;
    }
}

// ---------------- launch ----------------
extern "C" void kernel_launch(void* const* d_in, const int* in_sizes, int n_in,
                              void* d_out, int out_size) {
    const float* q = (const float*)d_in[0];
    const float* k = (const float*)d_in[1];
    const float* v = (const float*)d_in[2];
    const float* w = (const float*)d_in[3];
    float* out = (float*)d_out;

    cudaFuncSetAttribute(k23_fused, cudaFuncAttributeMaxDynamicSharedMemorySize, SMTOT);

    k0_split<<<1024, 256>>>(q, k, v);
    k1_compress<<<dim3(NCMP, KHN), DDIM>>>(k, v);
    k1b_knorm<<<dim3(T_LEN, KHN), 32>>>(k);
    k23_fused<<<dim3(T_LEN / TQ, KHN), 256, SMTOT>>>(q, w, out);
}

// round 11
// speedup vs baseline: 10.4668x; 1.0272x over previous
#include <cuda_runtime.h>
#include <cuda_fp16.h>
#include <math.h>
#include <stdint.h>

#define T_LEN 2048
#define H_HEADS 16
#define KHN 2
#define GQ 8
#define DDIM 128
#define NCMP 127
#define TQ 16
#define SCALE_F 0.08838834765f
#define EXP_SHIFT 10.3972077f   /* ln(2^15) */
#define NEG_INF (-INFINITY)

// ---------------- scratch ----------------
__device__ unsigned g_kmax[KHN];

__device__ __align__(16) __half g_qh16[T_LEN * H_HEADS * DDIM];
__device__ __align__(16) __half g_ql16[T_LEN * H_HEADS * DDIM];
__device__ __align__(16) __half g_kh16[KHN * T_LEN * DDIM];
__device__ __align__(16) __half g_vh16[KHN * T_LEN * DDIM];
__device__ __align__(16) __half g_ckhi[KHN][128][DDIM];
__device__ __align__(16) __half g_cklo[KHN][128][DDIM];
__device__ __align__(16) __half g_cvhi[KHN][128][DDIM];

// ---------------- helpers ----------------
__device__ __forceinline__ uint32_t smem_u32(const void* p) {
    uint32_t a;
    asm("{ .reg .u64 t; cvta.to.shared.u64 t, %1; cvt.u32.u64 %0, t; }" : "=r"(a) : "l"(p));
    return a;
}
__device__ __forceinline__ void mma16816h(float* d, const uint32_t* a, uint32_t b0, uint32_t b1) {
    asm volatile("mma.sync.aligned.m16n8k16.row.col.f32.f16.f16.f32 "
        "{%0,%1,%2,%3},{%4,%5,%6,%7},{%8,%9},{%0,%1,%2,%3};"
        : "+f"(d[0]), "+f"(d[1]), "+f"(d[2]), "+f"(d[3])
        : "r"(a[0]), "r"(a[1]), "r"(a[2]), "r"(a[3]), "r"(b0), "r"(b1));
}
__device__ __forceinline__ void ldsm4(uint32_t* r, uint32_t addr) {
    asm volatile("ldmatrix.sync.aligned.m8n8.x4.shared.b16 {%0,%1,%2,%3}, [%4];"
        : "=r"(r[0]), "=r"(r[1]), "=r"(r[2]), "=r"(r[3]) : "r"(addr));
}
__device__ __forceinline__ void ldsm4t(uint32_t* r, uint32_t addr) {
    asm volatile("ldmatrix.sync.aligned.m8n8.x4.trans.shared.b16 {%0,%1,%2,%3}, [%4];"
        : "=r"(r[0]), "=r"(r[1]), "=r"(r[2]), "=r"(r[3]) : "r"(addr));
}
__device__ __forceinline__ uint32_t packh2(float a, float b) {
    __half2 h = __floats2half2_rn(a, b);
    return *reinterpret_cast<uint32_t*>(&h);
}
#define CP_ASYNC16(dst, src) \
    asm volatile("cp.async.cg.shared.global [%0], [%1], 16;" :: "r"(dst), "l"(src) : "memory")
#define CP_COMMIT() asm volatile("cp.async.commit_group;" ::: "memory")
#define CP_WAIT0()  asm volatile("cp.async.wait_group 0;" ::: "memory")

// ---------------- K0: pre-split ----------------
__global__ void k0_split(const float* __restrict__ q, const float* __restrict__ k,
                         const float* __restrict__ v) {
    int stride = gridDim.x * blockDim.x;
    int idx = blockIdx.x * blockDim.x + threadIdx.x;
    const int n_kv = T_LEN * KHN * DDIM;
    for (int i = idx; i < n_kv; i += stride) {
        int d = i & (DDIM - 1);
        int tk = i >> 7;
        int kh = tk & 1, t = tk >> 1;
        int o = (kh * T_LEN + t) * DDIM + d;
        g_kh16[o] = __float2half_rn(k[i]);
        g_vh16[o] = __float2half_rn(v[i]);
    }
    const int n_q = T_LEN * H_HEADS * DDIM;
    for (int i = idx; i < n_q; i += stride) {
        float x = q[i];
        __half hh = __float2half_rn(x);
        g_qh16[i] = hh;
        g_ql16[i] = __float2half_rn(x - __half2float(hh));
    }
}

// ---------------- K1: compressed K/V ----------------
__global__ void k1_compress(const float* __restrict__ k, const float* __restrict__ v) {
    int j = blockIdx.x, kh = blockIdx.y, d = threadIdx.x;
    int s = j * 16;
    float sk = 0.f, sv = 0.f;
#pragma unroll 8
    for (int i = 0; i < 32; i++) {
        sk += k[((size_t)(s + i) * KHN + kh) * DDIM + d];
        sv += v[((size_t)(s + i) * KHN + kh) * DDIM + d];
    }
    float ck = sk * (1.f / 32.f), cv = sv * (1.f / 32.f);
    __half h = __float2half_rn(ck);
    g_ckhi[kh][j][d] = h;
    g_cklo[kh][j][d] = __float2half_rn(ck - __half2float(h));
    g_cvhi[kh][j][d] = __float2half_rn(cv);
}

// ---------------- K1b: max ||k_row|| ----------------
__global__ void k1b_knorm(const float* __restrict__ k) {
    int t = blockIdx.x, kh = blockIdx.y, lane = threadIdx.x;
    const float4* kr = reinterpret_cast<const float4*>(k) + ((size_t)t * KHN + kh) * 32;
    float4 a = kr[lane];
    float s = a.x * a.x + a.y * a.y + a.z * a.z + a.w * a.w;
    for (int o = 16; o; o >>= 1) s += __shfl_xor_sync(0xffffffffu, s, o);
    if (lane == 0) atomicMax(&g_kmax[kh], __float_as_uint(sqrtf(s)));
}

// ---------------- K23: fused ----------------
#define SQH   0
#define SQL   32768
#define SCKH  65536
#define SCKL  98304
#define SPS   131072
#define SOC   98304
#define SBUF  32768
#define BUFSZ 32768
#define VHIO  16384
#define SMTOT 163840

__global__ __launch_bounds__(256, 1) void k23_fused(
    const float* __restrict__ q, const float* __restrict__ w,
    float* __restrict__ out)
{
    extern __shared__ char smem[];
    uint32_t sb = smem_u32(smem);
    float* psum_sh = reinterpret_cast<float*>(smem + SPS);
    float* oc_sh = reinterpret_cast<float*>(smem + SOC);
    int tid = threadIdx.x;
    int wp = tid >> 5, lane = tid & 31;
    // flattened heavy-first across both kh
    int ridx = (int)gridDim.x - 1 - (int)blockIdx.x;
    int tile = ridx >> 1;
    int kh = ridx & 1;
    int t0 = tile * TQ;
    int grp = lane >> 3;
    int jcl = (lane & 3) * 2;

    __shared__ int s_list[36];
    __shared__ int s_n;
    __shared__ unsigned s_union;

    int t_a = t0 + 2 * wp;
    int t_b = t_a + 1;
    int g = lane >> 2;
    int h = kh * GQ + g;

    if (tid == 0) s_union = 0u;

    // ---- stage QH/QL + CKH/CKL ----
    for (int i = tid; i < 128 * 16; i += 256) {
        int row = i >> 4, c16 = i & 15;
        uint32_t off = (uint32_t)row * 256u + (uint32_t)((c16 ^ (row & 7)) << 4);
        int qrow = (t0 + (row >> 3)) * H_HEADS + kh * GQ + (row & 7);
        CP_ASYNC16(sb + SQH + off, g_qh16 + (size_t)qrow * DDIM + c16 * 8);
        CP_ASYNC16(sb + SQL + off, g_ql16 + (size_t)qrow * DDIM + c16 * 8);
        CP_ASYNC16(sb + SCKH + off, &g_ckhi[kh][row][c16 * 8]);
        CP_ASYNC16(sb + SCKL + off, &g_cklo[kh][row][c16 * 8]);
    }
    CP_COMMIT();

    float kmaxv = __uint_as_float(g_kmax[kh]);
    float Ua, Ub;
    {
        const float4* q4 = reinterpret_cast<const float4*>(q);
        float s2 = 0.f;
        const float4* qr = q4 + ((size_t)(t_a * H_HEADS + h)) * 32;
#pragma unroll 8
        for (int d4 = 0; d4 < 32; d4++) { float4 a = qr[d4]; s2 += a.x*a.x + a.y*a.y + a.z*a.z + a.w*a.w; }
        Ua = SCALE_F * sqrtf(s2) * kmaxv - EXP_SHIFT;
        s2 = 0.f;
        qr = q4 + ((size_t)(t_b * H_HEADS + h)) * 32;
#pragma unroll 8
        for (int d4 = 0; d4 < 32; d4++) { float4 a = qr[d4]; s2 += a.x*a.x + a.y*a.y + a.z*a.z + a.w*a.w; }
        Ub = SCALE_F * sqrtf(s2) * kmaxv - EXP_SHIFT;
    }

    CP_WAIT0();
    __syncthreads();

    int nva = (t_a >= 31) ? ((t_a - 31) / 16 + 1) : 0;
    int nvb = (t_b >= 31) ? ((t_b - 31) / 16 + 1) : 0;

    // ---- Q-hi fragments (both phases) ----
    uint32_t ah[8][4];
    {
        int row = 16 * wp + (grp & 1) * 8 + (lane & 7);
        uint32_t rb = (uint32_t)row * 256u, rx = (uint32_t)(row & 7);
#pragma unroll
        for (int kt = 0; kt < 8; kt++) {
            uint32_t cq = (uint32_t)(kt * 2 + (grp >> 1));
            ldsm4(ah[kt], sb + SQH + rb + ((cq ^ rx) << 4));
        }
    }

    unsigned selm_a, selm_b;
    const __half* khbase = g_kh16 + (size_t)kh * T_LEN * DDIM;
    const __half* vhbase = g_vh16 + (size_t)kh * T_LEN * DDIM;

    // ================= PHASE 1 =================
    {
        float s[16][4];
#pragma unroll
        for (int i = 0; i < 16; i++)
#pragma unroll
            for (int c = 0; c < 4; c++) s[i][c] = 0.f;

#pragma unroll
        for (int np = 0; np < 8; np++) {
            int keyq = np * 16 + (grp >> 1) * 8 + (lane & 7);
            uint32_t kb = (uint32_t)keyq * 256u, rxk = (uint32_t)(keyq & 7);
            int rowq = 16 * wp + (grp & 1) * 8 + (lane & 7);
            uint32_t rq = (uint32_t)rowq * 256u, rxq = (uint32_t)(rowq & 7);
#pragma unroll
            for (int kt = 0; kt < 8; kt++) {
                uint32_t ck = (uint32_t)(kt * 2 + (grp & 1));
                uint32_t bo = kb + ((ck ^ rxk) << 4);
                uint32_t cq = (uint32_t)(kt * 2 + (grp >> 1));
                uint32_t bh[4], bl[4], al[4];
                ldsm4(bh, sb + SCKH + bo);
                ldsm4(bl, sb + SCKL + bo);
                ldsm4(al, sb + SQL + rq + ((cq ^ rxq) << 4));
                mma16816h(s[2*np],   ah[kt], bh[0], bh[1]);
                mma16816h(s[2*np+1], ah[kt], bh[2], bh[3]);
                mma16816h(s[2*np],   ah[kt], bl[0], bl[1]);
                mma16816h(s[2*np+1], ah[kt], bl[2], bl[3]);
                mma16816h(s[2*np],   al,     bh[0], bh[1]);
                mma16816h(s[2*np+1], al,     bh[2], bh[3]);
            }
        }
        __syncthreads();   // QL/CKH/CKL reads done

        // stage cmp_v-hi into CKH region + chunk-0 K/V (block 0 ALWAYS selected)
        for (int i = tid; i < 128 * 16; i += 256) {
            int row = i >> 4, c16 = i & 15;
            uint32_t off = (uint32_t)row * 256u + (uint32_t)((c16 ^ (row & 7)) << 4);
            CP_ASYNC16(sb + SCKH + off, &g_cvhi[kh][row][c16 * 8]);
        }
        for (int i = tid; i < 1024; i += 256) {
            int row = i >> 4, c16 = i & 15;
            size_t src = (size_t)row * DDIM + c16 * 8;
            uint32_t dst = sb + SBUF + ((uint32_t)row * 256u + (uint32_t)((c16 ^ (row & 7)) << 4));
            CP_ASYNC16(dst, khbase + src);
            CP_ASYNC16(dst + VHIO, vhbase + src);
        }
        CP_COMMIT();

        // softmax (fast exp; selection-safe vs accepted split error)
        float ma = NEG_INF, mb = NEG_INF;
#pragma unroll
        for (int nt = 0; nt < 16; nt++) {
            int j0 = nt * 8 + jcl;
            if (j0 < nva)     ma = fmaxf(ma, s[nt][0] * SCALE_F);
            if (j0 + 1 < nva) ma = fmaxf(ma, s[nt][1] * SCALE_F);
            if (j0 < nvb)     mb = fmaxf(mb, s[nt][2] * SCALE_F);
            if (j0 + 1 < nvb) mb = fmaxf(mb, s[nt][3] * SCALE_F);
        }
#pragma unroll
        for (int o = 1; o <= 2; o <<= 1) {
            ma = fmaxf(ma, __shfl_xor_sync(0xffffffffu, ma, o));
            mb = fmaxf(mb, __shfl_xor_sync(0xffffffffu, mb, o));
        }
        float la = 0.f, lb = 0.f;
#pragma unroll
        for (int nt = 0; nt < 16; nt++) {
            int j0 = nt * 8 + jcl;
            float e0 = (j0 < nva)     ? __expf(s[nt][0] * SCALE_F - ma) : 0.f;
            float e1 = (j0 + 1 < nva) ? __expf(s[nt][1] * SCALE_F - ma) : 0.f;
            float e2 = (j0 < nvb)     ? __expf(s[nt][2] * SCALE_F - mb) : 0.f;
            float e3 = (j0 + 1 < nvb) ? __expf(s[nt][3] * SCALE_F - mb) : 0.f;
            s[nt][0] = e0; s[nt][1] = e1; s[nt][2] = e2; s[nt][3] = e3;
            la += e0 + e1; lb += e2 + e3;
        }
#pragma unroll
        for (int o = 1; o <= 2; o <<= 1) {
            la += __shfl_xor_sync(0xffffffffu, la, o);
            lb += __shfl_xor_sync(0xffffffffu, lb, o);
        }
        float inva = (nva > 0) ? 1.f / la : 0.f;
        float invb = (nvb > 0) ? 1.f / lb : 0.f;
#pragma unroll
        for (int nt = 0; nt < 16; nt++) {
            s[nt][0] *= inva; s[nt][1] *= inva;
            s[nt][2] *= invb; s[nt][3] *= invb;
        }

        // psum
#pragma unroll
        for (int nt = 0; nt < 16; nt++) {
            float a0 = s[nt][0], a1 = s[nt][1], b0 = s[nt][2], b1 = s[nt][3];
#pragma unroll
            for (int o = 4; o <= 16; o <<= 1) {
                a0 += __shfl_xor_sync(0xffffffffu, a0, o);
                a1 += __shfl_xor_sync(0xffffffffu, a1, o);
                b0 += __shfl_xor_sync(0xffffffffu, b0, o);
                b1 += __shfl_xor_sync(0xffffffffu, b1, o);
            }
            if (lane < 4) {
                int j = nt * 8 + lane * 2;
                psum_sh[(2 * wp) * 128 + j] = a0;
                psum_sh[(2 * wp) * 128 + j + 1] = a1;
                psum_sh[(2 * wp + 1) * 128 + j] = b0;
                psum_sh[(2 * wp + 1) * 128 + j + 1] = b1;
            }
        }
        __syncthreads();

        // top-16 selection via redux on order-encoded uints (same tie-breaks)
        unsigned selres[2];
#pragma unroll
        for (int rep = 0; rep < 2; rep++) {
            int t = t0 + 2 * wp + rep;
            int qi = 2 * wp + rep;
            int nv = (t >= 31) ? ((t - 31) / 16 + 1) : 0;
            int b = lane;
            int tb = t >> 6;
            bool forced = (b < 1) || ((b <= tb) && (b >= tb - 1));
            bool valid = (b * 64 <= t);
            float sc;
            if (!valid) sc = -1e30f;
            else if (forced) sc = 1e30f;
            else {
                int jlo = 4 * b - 1; if (jlo < 0) jlo = 0;
                int jhi = 4 * b + 3; if (jhi > nv - 1) jhi = nv - 1;
                float ss = 0.f;
                for (int j = jlo; j <= jhi; j++) ss += psum_sh[qi * 128 + j];
                sc = ss;
            }
            unsigned u = __float_as_uint(sc);
            u = ((int)u < 0) ? ~u : (u | 0x80000000u);
            unsigned sel = 0u;
            for (int it = 0; it < 16; it++) {
                unsigned cur = ((sel >> b) & 1u) ? 0u : u;
                unsigned m = __reduce_max_sync(0xffffffffu, cur);
                unsigned ball = __ballot_sync(0xffffffffu, cur == m);
                sel |= (1u << (__ffs(ball) - 1));
            }
            selres[rep] = sel;
        }
        selm_a = selres[0];
        selm_b = selres[1];
        if (lane == 0) atomicOr(&s_union, selm_a | selm_b);

        // pack normalized P
        uint32_t ph[8][4];
#pragma unroll
        for (int kp = 0; kp < 8; kp++) {
            ph[kp][0] = packh2(s[2*kp][0],   s[2*kp][1]);
            ph[kp][1] = packh2(s[2*kp][2],   s[2*kp][3]);
            ph[kp][2] = packh2(s[2*kp+1][0], s[2*kp+1][1]);
            ph[kp][3] = packh2(s[2*kp+1][2], s[2*kp+1][3]);
        }

        CP_WAIT0();        // CVH + chunk0 KV ready
        __syncthreads();

        float Oc[16][4];
#pragma unroll
        for (int i = 0; i < 16; i++)
#pragma unroll
            for (int c = 0; c < 4; c++) Oc[i][c] = 0.f;
#pragma unroll
        for (int kp = 0; kp < 8; kp++) {
            int keyv = kp * 16 + (grp & 1) * 8 + (lane & 7);
            uint32_t kb = (uint32_t)keyv * 256u, rxv = (uint32_t)(keyv & 7);
#pragma unroll
            for (int dp = 0; dp < 8; dp++) {
                uint32_t c16 = (uint32_t)(dp * 2 + (grp >> 1));
                uint32_t off = kb + ((c16 ^ rxv) << 4);
                uint32_t vh[4];
                ldsm4t(vh, sb + SCKH + off);
                mma16816h(Oc[2*dp],   ph[kp], vh[0], vh[1]);
                mma16816h(Oc[2*dp+1], ph[kp], vh[2], vh[3]);
            }
        }
        __syncthreads();

#pragma unroll
        for (int nt = 0; nt < 16; nt++)
#pragma unroll
            for (int c = 0; c < 4; c++)
                oc_sh[(nt * 4 + c) * 256 + tid] = Oc[nt][c];
    }

    // ================= PHASE 2 =================
    __syncthreads();
    unsigned selu = s_union;
    int t_blk = t0 >> 6;

    if (tid == 0) {
        int n = 0;
        for (int b = 0; b <= t_blk; b++) {
            bool need = ((selu >> b) & 1u) || (b * 64 + 63 >= t0 - 511);
            if (need) s_list[n++] = b;
        }
        s_n = n;
    }
    __syncthreads();
    int nch = s_n;

    float Os[16][4], Ow[16][4];
#pragma unroll
    for (int i = 0; i < 16; i++)
#pragma unroll
        for (int c = 0; c < 4; c++) { Os[i][c] = 0.f; Ow[i][c] = 0.f; }
    float sum_sa = 0.f, sum_sb = 0.f, sum_wa = 0.f, sum_wb = 0.f;
    unsigned selw = selm_a | selm_b;

    for (int ci = 0; ci < nch; ci++) {
        int b = s_list[ci];
        uint32_t KB = sb + SBUF + (uint32_t)(ci & 1) * BUFSZ;

        if (ci > 0) {
            CP_WAIT0();
            __syncthreads();
        }
        if (ci + 1 < nch) {
            int bn = s_list[ci + 1];
            uint32_t NB = sb + SBUF + (uint32_t)((ci + 1) & 1) * BUFSZ;
            for (int i = tid; i < 1024; i += 256) {
                int row = i >> 4, c16 = i & 15;
                size_t src = (size_t)(bn * 64 + row) * DDIM + c16 * 8;
                uint32_t dst = NB + ((uint32_t)row * 256u + (uint32_t)((c16 ^ (row & 7)) << 4));
                CP_ASYNC16(dst, khbase + src);
                CP_ASYNC16(dst + VHIO, vhbase + src);
            }
            CP_COMMIT();
        }

        // warp-exact flags (skip work the union forced on other warps)
        bool sel_w = (selw >> b) & 1u;
        bool win_w = (b * 64 + 63 >= t_a - 511);
        if (!sel_w && !win_w) continue;
        bool sa = (selm_a >> b) & 1u, sb2 = (selm_b >> b) & 1u;
        bool needs_causal = (b == t_blk);
        bool needs_wm = win_w && (b * 64 < t_b - 511);
        bool fast = !needs_causal && !needs_wm;

#pragma unroll
        for (int np = 0; np < 4; np++) {
            float s0[4] = {0.f, 0.f, 0.f, 0.f}, s1[4] = {0.f, 0.f, 0.f, 0.f};
            {
                int keyq = np * 16 + (grp >> 1) * 8 + (lane & 7);
                uint32_t kb = (uint32_t)keyq * 256u, rxk = (uint32_t)(keyq & 7);
#pragma unroll
                for (int kt = 0; kt < 8; kt++) {
                    uint32_t ck = (uint32_t)(kt * 2 + (grp & 1));
                    uint32_t bh[4];
                    ldsm4(bh, KB + kb + ((ck ^ rxk) << 4));
                    mma16816h(s0, ah[kt], bh[0], bh[1]);
                    mma16816h(s1, ah[kt], bh[2], bh[3]);
                }
            }
            float ea0 = __expf(s0[0] * SCALE_F - Ua);
            float ea1 = __expf(s0[1] * SCALE_F - Ua);
            float eb0 = __expf(s0[2] * SCALE_F - Ub);
            float eb1 = __expf(s0[3] * SCALE_F - Ub);
            float fa0 = __expf(s1[0] * SCALE_F - Ua);
            float fa1 = __expf(s1[1] * SCALE_F - Ua);
            float fb0 = __expf(s1[2] * SCALE_F - Ub);
            float fb1 = __expf(s1[3] * SCALE_F - Ub);

            uint32_t ps[4], pw[4];
            if (fast) {
                if (sel_w) {
                    float esa0 = sa ? ea0 : 0.f, esa1 = sa ? ea1 : 0.f;
                    float esb0 = sb2 ? eb0 : 0.f, esb1 = sb2 ? eb1 : 0.f;
                    float fsa0 = sa ? fa0 : 0.f, fsa1 = sa ? fa1 : 0.f;
                    float fsb0 = sb2 ? fb0 : 0.f, fsb1 = sb2 ? fb1 : 0.f;
                    sum_sa += esa0 + esa1 + fsa0 + fsa1;
                    sum_sb += esb0 + esb1 + fsb0 + fsb1;
                    ps[0] = packh2(esa0, esa1);
                    ps[1] = packh2(esb0, esb1);
                    ps[2] = packh2(fsa0, fsa1);
                    ps[3] = packh2(fsb0, fsb1);
                }
                if (win_w) {
                    sum_wa += ea0 + ea1 + fa0 + fa1;
                    sum_wb += eb0 + eb1 + fb0 + fb1;
                    pw[0] = packh2(ea0, ea1);
                    pw[1] = packh2(eb0, eb1);
                    pw[2] = packh2(fa0, fa1);
                    pw[3] = packh2(fb0, fb1);
                }
            } else {
                int j0 = b * 64 + np * 16 + jcl;
                int j1 = j0 + 1, j8 = j0 + 8, j9 = j0 + 9;
                if (sel_w) {
                    float esa0 = (sa  && j0 <= t_a) ? ea0 : 0.f;
                    float esa1 = (sa  && j1 <= t_a) ? ea1 : 0.f;
                    float esb0 = (sb2 && j0 <= t_b) ? eb0 : 0.f;
                    float esb1 = (sb2 && j1 <= t_b) ? eb1 : 0.f;
                    float fsa0 = (sa  && j8 <= t_a) ? fa0 : 0.f;
                    float fsa1 = (sa  && j9 <= t_a) ? fa1 : 0.f;
                    float fsb0 = (sb2 && j8 <= t_b) ? fb0 : 0.f;
                    float fsb1 = (sb2 && j9 <= t_b) ? fb1 : 0.f;
                    sum_sa += esa0 + esa1 + fsa0 + fsa1;
                    sum_sb += esb0 + esb1 + fsb0 + fsb1;
                    ps[0] = packh2(esa0, esa1);
                    ps[1] = packh2(esb0, esb1);
                    ps[2] = packh2(fsa0, fsa1);
                    ps[3] = packh2(fsb0, fsb1);
                }
                if (win_w) {
                    float ewa0 = (j0 <= t_a && t_a - j0 < 512) ? ea0 : 0.f;
                    float ewa1 = (j1 <= t_a && t_a - j1 < 512) ? ea1 : 0.f;
                    float ewb0 = (j0 <= t_b && t_b - j0 < 512) ? eb0 : 0.f;
                    float ewb1 = (j1 <= t_b && t_b - j1 < 512) ? eb1 : 0.f;
                    float fwa0 = (j8 <= t_a && t_a - j8 < 512) ? fa0 : 0.f;
                    float fwa1 = (j9 <= t_a && t_a - j9 < 512) ? fa1 : 0.f;
                    float fwb0 = (j8 <= t_b && t_b - j8 < 512) ? fb0 : 0.f;
                    float fwb1 = (j9 <= t_b && t_b - j9 < 512) ? fb1 : 0.f;
                    sum_wa += ewa0 + ewa1 + fwa0 + fwa1;
                    sum_wb += ewb0 + ewb1 + fwb0 + fwb1;
                    pw[0] = packh2(ewa0, ewa1);
                    pw[1] = packh2(ewb0, ewb1);
                    pw[2] = packh2(fwa0, fwa1);
                    pw[3] = packh2(fwb0, fwb1);
                }
            }

            {
                int keyv = np * 16 + (grp & 1) * 8 + (lane & 7);
                uint32_t kb = (uint32_t)keyv * 256u, rxv = (uint32_t)(keyv & 7);
#pragma unroll
                for (int dp = 0; dp < 8; dp++) {
                    uint32_t c16 = (uint32_t)(dp * 2 + (grp >> 1));
                    uint32_t off = kb + ((c16 ^ rxv) << 4);
                    uint32_t vh[4];
                    ldsm4t(vh, KB + VHIO + off);
                    if (sel_w) {
                        mma16816h(Os[2 * dp],     ps, vh[0], vh[1]);
                        mma16816h(Os[2 * dp + 1], ps, vh[2], vh[3]);
                    }
                    if (win_w) {
                        mma16816h(Ow[2 * dp],     pw, vh[0], vh[1]);
                        mma16816h(Ow[2 * dp + 1], pw, vh[2], vh[3]);
                    }
                }
            }
        }
    }

    // ---- epilogue ----
#pragma unroll
    for (int o = 1; o <= 2; o <<= 1) {
        sum_sa += __shfl_xor_sync(0xffffffffu, sum_sa, o);
        sum_sb += __shfl_xor_sync(0xffffffffu, sum_sb, o);
        sum_wa += __shfl_xor_sync(0xffffffffu, sum_wa, o);
        sum_wb += __shfl_xor_sync(0xffffffffu, sum_wb, o);
    }
    float inv_sa = 1.f / sum_sa, inv_sb = 1.f / sum_sb;
    float inv_wa = 1.f / sum_wa, inv_wb = 1.f / sum_wb;

    const float* wa = w + ((size_t)(t_a * H_HEADS + h)) * 3;
    const float* wb = w + ((size_t)(t_b * H_HEADS + h)) * 3;
    float w0a = wa[0], w1a = wa[1], w2a = wa[2];
    float w0b = wb[0], w1b = wb[1], w2b = wb[2];

#pragma unroll
    for (int nt = 0; nt < 16; nt++) {
        int d0 = nt * 8 + jcl;
        float oca0 = oc_sh[(nt * 4 + 0) * 256 + tid];
        float oca1 = oc_sh[(nt * 4 + 1) * 256 + tid];
        float ocb0 = oc_sh[(nt * 4 + 2) * 256 + tid];
        float ocb1 = oc_sh[(nt * 4 + 3) * 256 + tid];
        float2 oa, ob;
        oa.x = w0a * oca0 + w1a * Os[nt][0] * inv_sa + w2a * Ow[nt][0] * inv_wa;
        oa.y = w0a * oca1 + w1a * Os[nt][1] * inv_sa + w2a * Ow[nt][1] * inv_wa;
        ob.x = w0b * ocb0 + w1b * Os[nt][2] * inv_sb + w2b * Ow[nt][2] * inv_wb;
        ob.y = w0b * ocb1 + w1b * Os[nt][3] * inv_sb + w2b * Ow[nt][3] * inv_wb;
        *reinterpret_cast<float2*>(out + ((size_t)(t_a * H_HEADS + h)) * DDIM + d0) = oa;
        *reinterpret_cast<float2*>(out + ((size_t)(t_b * H_HEADS + h)) * DDIM + d0) = ob;
    }
}

// ---------------- launch ----------------
extern "C" void kernel_launch(void* const* d_in, const int* in_sizes, int n_in,
                              void* d_out, int out_size) {
    const float* q = (const float*)d_in[0];
    const float* k = (const float*)d_in[1];
    const float* v = (const float*)d_in[2];
    const float* w = (const float*)d_in[3];
    float* out = (float*)d_out;

    cudaFuncSetAttribute(k23_fused, cudaFuncAttributeMaxDynamicSharedMemorySize, SMTOT);

    k0_split<<<1024, 256>>>(q, k, v);
    k1_compress<<<dim3(NCMP, KHN), DDIM>>>(k, v);
    k1b_knorm<<<dim3(T_LEN, KHN), 32>>>(k);
    k23_fused<<<dim3(T_LEN / TQ * KHN, 1), 256, SMTOT>>>(q, w, out);
}

// round 12
// speedup vs baseline: 10.6956x; 1.0219x over previous
#include <cuda_runtime.h>
#include <cuda_fp16.h>
#include <math.h>
#include <stdint.h>

#define T_LEN 2048
#define H_HEADS 16
#define KHN 2
#define GQ 8
#define DDIM 128
#define NCMP 127
#define TQ 16
#define SCALE_F 0.08838834765f
#define EXP_SHIFT 10.3972077f   /* ln(2^15) */
#define NEG_INF (-INFINITY)

// ---------------- scratch ----------------
__device__ unsigned g_kmax[KHN];

__device__ __align__(16) __half g_qh16[T_LEN * H_HEADS * DDIM];
__device__ __align__(16) __half g_ql16[T_LEN * H_HEADS * DDIM];
__device__ __align__(16) __half g_kh16[KHN * T_LEN * DDIM];
__device__ __align__(16) __half g_vh16[KHN * T_LEN * DDIM];
__device__ __align__(16) __half g_ckhi[KHN][128][DDIM];
__device__ __align__(16) __half g_cklo[KHN][128][DDIM];
__device__ __align__(16) __half g_cvhi[KHN][128][DDIM];

// ---------------- helpers ----------------
__device__ __forceinline__ uint32_t smem_u32(const void* p) {
    uint32_t a;
    asm("{ .reg .u64 t; cvta.to.shared.u64 t, %1; cvt.u32.u64 %0, t; }" : "=r"(a) : "l"(p));
    return a;
}
__device__ __forceinline__ void mma16816h(float* d, const uint32_t* a, uint32_t b0, uint32_t b1) {
    asm volatile("mma.sync.aligned.m16n8k16.row.col.f32.f16.f16.f32 "
        "{%0,%1,%2,%3},{%4,%5,%6,%7},{%8,%9},{%0,%1,%2,%3};"
        : "+f"(d[0]), "+f"(d[1]), "+f"(d[2]), "+f"(d[3])
        : "r"(a[0]), "r"(a[1]), "r"(a[2]), "r"(a[3]), "r"(b0), "r"(b1));
}
__device__ __forceinline__ void ldsm4(uint32_t* r, uint32_t addr) {
    asm volatile("ldmatrix.sync.aligned.m8n8.x4.shared.b16 {%0,%1,%2,%3}, [%4];"
        : "=r"(r[0]), "=r"(r[1]), "=r"(r[2]), "=r"(r[3]) : "r"(addr));
}
__device__ __forceinline__ void ldsm4t(uint32_t* r, uint32_t addr) {
    asm volatile("ldmatrix.sync.aligned.m8n8.x4.trans.shared.b16 {%0,%1,%2,%3}, [%4];"
        : "=r"(r[0]), "=r"(r[1]), "=r"(r[2]), "=r"(r[3]) : "r"(addr));
}
__device__ __forceinline__ uint32_t packh2(float a, float b) {
    __half2 h = __floats2half2_rn(a, b);
    return *reinterpret_cast<uint32_t*>(&h);
}
#define CP_ASYNC16(dst, src) \
    asm volatile("cp.async.cg.shared.global [%0], [%1], 16;" :: "r"(dst), "l"(src) : "memory")
#define CP_COMMIT() asm volatile("cp.async.commit_group;" ::: "memory")
#define CP_WAIT0()  asm volatile("cp.async.wait_group 0;" ::: "memory")

// ---------------- K0: pre-split ----------------
__global__ void k0_split(const float* __restrict__ q, const float* __restrict__ k,
                         const float* __restrict__ v) {
    int stride = gridDim.x * blockDim.x;
    int idx = blockIdx.x * blockDim.x + threadIdx.x;
    const int n_kv = T_LEN * KHN * DDIM;
    for (int i = idx; i < n_kv; i += stride) {
        int d = i & (DDIM - 1);
        int tk = i >> 7;
        int kh = tk & 1, t = tk >> 1;
        int o = (kh * T_LEN + t) * DDIM + d;
        g_kh16[o] = __float2half_rn(k[i]);
        g_vh16[o] = __float2half_rn(v[i]);
    }
    const int n_q = T_LEN * H_HEADS * DDIM;
    for (int i = idx; i < n_q; i += stride) {
        float x = q[i];
        __half hh = __float2half_rn(x);
        g_qh16[i] = hh;
        g_ql16[i] = __float2half_rn(x - __half2float(hh));
    }
}

// ---------------- K1: compressed K/V ----------------
__global__ void k1_compress(const float* __restrict__ k, const float* __restrict__ v) {
    int j = blockIdx.x, kh = blockIdx.y, d = threadIdx.x;
    int s = j * 16;
    float sk = 0.f, sv = 0.f;
#pragma unroll 8
    for (int i = 0; i < 32; i++) {
        sk += k[((size_t)(s + i) * KHN + kh) * DDIM + d];
        sv += v[((size_t)(s + i) * KHN + kh) * DDIM + d];
    }
    float ck = sk * (1.f / 32.f), cv = sv * (1.f / 32.f);
    __half h = __float2half_rn(ck);
    g_ckhi[kh][j][d] = h;
    g_cklo[kh][j][d] = __float2half_rn(ck - __half2float(h));
    g_cvhi[kh][j][d] = __float2half_rn(cv);
}

// ---------------- K1b: max ||k_row|| ----------------
__global__ void k1b_knorm(const float* __restrict__ k) {
    int t = blockIdx.x, kh = blockIdx.y, lane = threadIdx.x;
    const float4* kr = reinterpret_cast<const float4*>(k) + ((size_t)t * KHN + kh) * 32;
    float4 a = kr[lane];
    float s = a.x * a.x + a.y * a.y + a.z * a.z + a.w * a.w;
    for (int o = 16; o; o >>= 1) s += __shfl_xor_sync(0xffffffffu, s, o);
    if (lane == 0) atomicMax(&g_kmax[kh], __float_as_uint(sqrtf(s)));
}

// ---------------- K23: fused ----------------
#define SQH   0
#define SQL   32768
#define SCKH  65536
#define SCKL  98304
#define SPS   131072
#define SOC   98304
#define SBUF  32768
#define BUFSZ 32768
#define VHIO  16384
#define SMTOT 163840

__global__ __launch_bounds__(256, 1) void k23_fused(
    const float* __restrict__ q, const float* __restrict__ w,
    float* __restrict__ out)
{
    extern __shared__ char smem[];
    uint32_t sb = smem_u32(smem);
    float* psum_sh = reinterpret_cast<float*>(smem + SPS);
    float* oc_sh = reinterpret_cast<float*>(smem + SOC);
    int tid = threadIdx.x;
    int wp = tid >> 5, lane = tid & 31;
    int ridx = (int)gridDim.x - 1 - (int)blockIdx.x;
    int tile = ridx >> 1;
    int kh = ridx & 1;
    int t0 = tile * TQ;
    int grp = lane >> 3;
    int jcl = (lane & 3) * 2;

    __shared__ int s_list[36];
    __shared__ int s_n;
    __shared__ unsigned s_union;

    int t_a = t0 + 2 * wp;
    int t_b = t_a + 1;
    int g = lane >> 2;
    int h = kh * GQ + g;

    if (tid == 0) s_union = 0u;

    // ---- stage QH/QL + CKH/CKL ----
    for (int i = tid; i < 128 * 16; i += 256) {
        int row = i >> 4, c16 = i & 15;
        uint32_t off = (uint32_t)row * 256u + (uint32_t)((c16 ^ (row & 7)) << 4);
        int qrow = (t0 + (row >> 3)) * H_HEADS + kh * GQ + (row & 7);
        CP_ASYNC16(sb + SQH + off, g_qh16 + (size_t)qrow * DDIM + c16 * 8);
        CP_ASYNC16(sb + SQL + off, g_ql16 + (size_t)qrow * DDIM + c16 * 8);
        CP_ASYNC16(sb + SCKH + off, &g_ckhi[kh][row][c16 * 8]);
        CP_ASYNC16(sb + SCKL + off, &g_cklo[kh][row][c16 * 8]);
    }
    CP_COMMIT();

    float kmaxv = __uint_as_float(g_kmax[kh]);
    float Ua, Ub;
    {
        const float4* q4 = reinterpret_cast<const float4*>(q);
        float s2 = 0.f;
        const float4* qr = q4 + ((size_t)(t_a * H_HEADS + h)) * 32;
#pragma unroll 8
        for (int d4 = 0; d4 < 32; d4++) { float4 a = qr[d4]; s2 += a.x*a.x + a.y*a.y + a.z*a.z + a.w*a.w; }
        Ua = SCALE_F * sqrtf(s2) * kmaxv - EXP_SHIFT;
        s2 = 0.f;
        qr = q4 + ((size_t)(t_b * H_HEADS + h)) * 32;
#pragma unroll 8
        for (int d4 = 0; d4 < 32; d4++) { float4 a = qr[d4]; s2 += a.x*a.x + a.y*a.y + a.z*a.z + a.w*a.w; }
        Ub = SCALE_F * sqrtf(s2) * kmaxv - EXP_SHIFT;
    }

    CP_WAIT0();
    __syncthreads();

    int nva = (t_a >= 31) ? ((t_a - 31) / 16 + 1) : 0;
    int nvb = (t_b >= 31) ? ((t_b - 31) / 16 + 1) : 0;

    // ---- Q-hi fragments (both phases) ----
    uint32_t ah[8][4];
    {
        int row = 16 * wp + (grp & 1) * 8 + (lane & 7);
        uint32_t rb = (uint32_t)row * 256u, rx = (uint32_t)(row & 7);
#pragma unroll
        for (int kt = 0; kt < 8; kt++) {
            uint32_t cq = (uint32_t)(kt * 2 + (grp >> 1));
            ldsm4(ah[kt], sb + SQH + rb + ((cq ^ rx) << 4));
        }
    }

    unsigned selm_a, selm_b;
    const __half* khbase = g_kh16 + (size_t)kh * T_LEN * DDIM;
    const __half* vhbase = g_vh16 + (size_t)kh * T_LEN * DDIM;

    // ================= PHASE 1 =================
    {
        float s[16][4];
#pragma unroll
        for (int i = 0; i < 16; i++)
#pragma unroll
            for (int c = 0; c < 4; c++) s[i][c] = 0.f;

#pragma unroll
        for (int np = 0; np < 8; np++) {
            int keyq = np * 16 + (grp >> 1) * 8 + (lane & 7);
            uint32_t kb = (uint32_t)keyq * 256u, rxk = (uint32_t)(keyq & 7);
            int rowq = 16 * wp + (grp & 1) * 8 + (lane & 7);
            uint32_t rq = (uint32_t)rowq * 256u, rxq = (uint32_t)(rowq & 7);
#pragma unroll
            for (int kt = 0; kt < 8; kt++) {
                uint32_t ck = (uint32_t)(kt * 2 + (grp & 1));
                uint32_t bo = kb + ((ck ^ rxk) << 4);
                uint32_t cq = (uint32_t)(kt * 2 + (grp >> 1));
                uint32_t bh[4], bl[4], al[4];
                ldsm4(bh, sb + SCKH + bo);
                ldsm4(bl, sb + SCKL + bo);
                ldsm4(al, sb + SQL + rq + ((cq ^ rxq) << 4));
                mma16816h(s[2*np],   ah[kt], bh[0], bh[1]);
                mma16816h(s[2*np+1], ah[kt], bh[2], bh[3]);
                mma16816h(s[2*np],   ah[kt], bl[0], bl[1]);
                mma16816h(s[2*np+1], ah[kt], bl[2], bl[3]);
                mma16816h(s[2*np],   al,     bh[0], bh[1]);
                mma16816h(s[2*np+1], al,     bh[2], bh[3]);
            }
        }
        __syncthreads();   // QL/CKH/CKL reads done

        // stage cmp_v-hi + chunk-0 K/V (block 0 ALWAYS selected)
        for (int i = tid; i < 128 * 16; i += 256) {
            int row = i >> 4, c16 = i & 15;
            uint32_t off = (uint32_t)row * 256u + (uint32_t)((c16 ^ (row & 7)) << 4);
            CP_ASYNC16(sb + SCKH + off, &g_cvhi[kh][row][c16 * 8]);
        }
        for (int i = tid; i < 1024; i += 256) {
            int row = i >> 4, c16 = i & 15;
            size_t src = (size_t)row * DDIM + c16 * 8;
            uint32_t dst = sb + SBUF + ((uint32_t)row * 256u + (uint32_t)((c16 ^ (row & 7)) << 4));
            CP_ASYNC16(dst, khbase + src);
            CP_ASYNC16(dst + VHIO, vhbase + src);
        }
        CP_COMMIT();

        float ma = NEG_INF, mb = NEG_INF;
#pragma unroll
        for (int nt = 0; nt < 16; nt++) {
            int j0 = nt * 8 + jcl;
            if (j0 < nva)     ma = fmaxf(ma, s[nt][0] * SCALE_F);
            if (j0 + 1 < nva) ma = fmaxf(ma, s[nt][1] * SCALE_F);
            if (j0 < nvb)     mb = fmaxf(mb, s[nt][2] * SCALE_F);
            if (j0 + 1 < nvb) mb = fmaxf(mb, s[nt][3] * SCALE_F);
        }
#pragma unroll
        for (int o = 1; o <= 2; o <<= 1) {
            ma = fmaxf(ma, __shfl_xor_sync(0xffffffffu, ma, o));
            mb = fmaxf(mb, __shfl_xor_sync(0xffffffffu, mb, o));
        }
        float la = 0.f, lb = 0.f;
#pragma unroll
        for (int nt = 0; nt < 16; nt++) {
            int j0 = nt * 8 + jcl;
            float e0 = (j0 < nva)     ? __expf(s[nt][0] * SCALE_F - ma) : 0.f;
            float e1 = (j0 + 1 < nva) ? __expf(s[nt][1] * SCALE_F - ma) : 0.f;
            float e2 = (j0 < nvb)     ? __expf(s[nt][2] * SCALE_F - mb) : 0.f;
            float e3 = (j0 + 1 < nvb) ? __expf(s[nt][3] * SCALE_F - mb) : 0.f;
            s[nt][0] = e0; s[nt][1] = e1; s[nt][2] = e2; s[nt][3] = e3;
            la += e0 + e1; lb += e2 + e3;
        }
#pragma unroll
        for (int o = 1; o <= 2; o <<= 1) {
            la += __shfl_xor_sync(0xffffffffu, la, o);
            lb += __shfl_xor_sync(0xffffffffu, lb, o);
        }
        float inva = (nva > 0) ? 1.f / la : 0.f;
        float invb = (nvb > 0) ? 1.f / lb : 0.f;
#pragma unroll
        for (int nt = 0; nt < 16; nt++) {
            s[nt][0] *= inva; s[nt][1] *= inva;
            s[nt][2] *= invb; s[nt][3] *= invb;
        }

#pragma unroll
        for (int nt = 0; nt < 16; nt++) {
            float a0 = s[nt][0], a1 = s[nt][1], b0 = s[nt][2], b1 = s[nt][3];
#pragma unroll
            for (int o = 4; o <= 16; o <<= 1) {
                a0 += __shfl_xor_sync(0xffffffffu, a0, o);
                a1 += __shfl_xor_sync(0xffffffffu, a1, o);
                b0 += __shfl_xor_sync(0xffffffffu, b0, o);
                b1 += __shfl_xor_sync(0xffffffffu, b1, o);
            }
            if (lane < 4) {
                int j = nt * 8 + lane * 2;
                psum_sh[(2 * wp) * 128 + j] = a0;
                psum_sh[(2 * wp) * 128 + j + 1] = a1;
                psum_sh[(2 * wp + 1) * 128 + j] = b0;
                psum_sh[(2 * wp + 1) * 128 + j + 1] = b1;
            }
        }
        __syncthreads();

        unsigned selres[2];
#pragma unroll
        for (int rep = 0; rep < 2; rep++) {
            int t = t0 + 2 * wp + rep;
            int qi = 2 * wp + rep;
            int nv = (t >= 31) ? ((t - 31) / 16 + 1) : 0;
            int b = lane;
            int tb = t >> 6;
            bool forced = (b < 1) || ((b <= tb) && (b >= tb - 1));
            bool valid = (b * 64 <= t);
            float sc;
            if (!valid) sc = -1e30f;
            else if (forced) sc = 1e30f;
            else {
                int jlo = 4 * b - 1; if (jlo < 0) jlo = 0;
                int jhi = 4 * b + 3; if (jhi > nv - 1) jhi = nv - 1;
                float ss = 0.f;
                for (int j = jlo; j <= jhi; j++) ss += psum_sh[qi * 128 + j];
                sc = ss;
            }
            unsigned u = __float_as_uint(sc);
            u = ((int)u < 0) ? ~u : (u | 0x80000000u);
            unsigned sel = 0u;
            for (int it = 0; it < 16; it++) {
                unsigned cur = ((sel >> b) & 1u) ? 0u : u;
                unsigned m = __reduce_max_sync(0xffffffffu, cur);
                unsigned ball = __ballot_sync(0xffffffffu, cur == m);
                sel |= (1u << (__ffs(ball) - 1));
            }
            selres[rep] = sel;
        }
        selm_a = selres[0];
        selm_b = selres[1];
        if (lane == 0) atomicOr(&s_union, selm_a | selm_b);

        uint32_t ph[8][4];
#pragma unroll
        for (int kp = 0; kp < 8; kp++) {
            ph[kp][0] = packh2(s[2*kp][0],   s[2*kp][1]);
            ph[kp][1] = packh2(s[2*kp][2],   s[2*kp][3]);
            ph[kp][2] = packh2(s[2*kp+1][0], s[2*kp+1][1]);
            ph[kp][3] = packh2(s[2*kp+1][2], s[2*kp+1][3]);
        }

        CP_WAIT0();
        __syncthreads();

        float Oc[16][4];
#pragma unroll
        for (int i = 0; i < 16; i++)
#pragma unroll
            for (int c = 0; c < 4; c++) Oc[i][c] = 0.f;
#pragma unroll
        for (int kp = 0; kp < 8; kp++) {
            int keyv = kp * 16 + (grp & 1) * 8 + (lane & 7);
            uint32_t kb = (uint32_t)keyv * 256u, rxv = (uint32_t)(keyv & 7);
#pragma unroll
            for (int dp = 0; dp < 8; dp++) {
                uint32_t c16 = (uint32_t)(dp * 2 + (grp >> 1));
                uint32_t off = kb + ((c16 ^ rxv) << 4);
                uint32_t vh[4];
                ldsm4t(vh, sb + SCKH + off);
                mma16816h(Oc[2*dp],   ph[kp], vh[0], vh[1]);
                mma16816h(Oc[2*dp+1], ph[kp], vh[2], vh[3]);
            }
        }
        __syncthreads();

#pragma unroll
        for (int nt = 0; nt < 16; nt++)
#pragma unroll
            for (int c = 0; c < 4; c++)
                oc_sh[(nt * 4 + c) * 256 + tid] = Oc[nt][c];
    }

    // ================= PHASE 2 =================
    __syncthreads();
    unsigned selu = s_union;
    int t_blk = t0 >> 6;

    if (tid == 0) {
        int n = 0;
        for (int b = 0; b <= t_blk; b++) {
            bool need = ((selu >> b) & 1u) || (b * 64 + 63 >= t0 - 511);
            if (need) s_list[n++] = b;
        }
        s_n = n;
    }
    __syncthreads();
    int nch = s_n;

    float Os[16][4], Ow[16][4];
#pragma unroll
    for (int i = 0; i < 16; i++)
#pragma unroll
        for (int c = 0; c < 4; c++) { Os[i][c] = 0.f; Ow[i][c] = 0.f; }
    float sum_sa = 0.f, sum_sb = 0.f, sum_wa = 0.f, sum_wb = 0.f;
    unsigned selw = selm_a | selm_b;

    for (int ci = 0; ci < nch; ci++) {
        int b = s_list[ci];
        uint32_t KB = sb + SBUF + (uint32_t)(ci & 1) * BUFSZ;

        if (ci > 0) {
            CP_WAIT0();
            __syncthreads();
        }
        if (ci + 1 < nch) {
            int bn = s_list[ci + 1];
            uint32_t NB = sb + SBUF + (uint32_t)((ci + 1) & 1) * BUFSZ;
            for (int i = tid; i < 1024; i += 256) {
                int row = i >> 4, c16 = i & 15;
                size_t src = (size_t)(bn * 64 + row) * DDIM + c16 * 8;
                uint32_t dst = NB + ((uint32_t)row * 256u + (uint32_t)((c16 ^ (row & 7)) << 4));
                CP_ASYNC16(dst, khbase + src);
                CP_ASYNC16(dst + VHIO, vhbase + src);
            }
            CP_COMMIT();
        }

        bool sel_w = (selw >> b) & 1u;
        bool win_w = (b * 64 + 63 >= t_a - 511);
        if (!sel_w && !win_w) continue;
        bool sa = (selm_a >> b) & 1u, sb2 = (selm_b >> b) & 1u;
        bool needs_causal = (b == t_blk);
        bool needs_wm = win_w && (b * 64 < t_b - 511);
        bool fast = !needs_causal && !needs_wm;

        // ---- process np in pairs: interleaved QK chains, batched exp, interleaved PV ----
#pragma unroll
        for (int npp = 0; npp < 2; npp++) {
            int npA = npp * 2;
            float sA0[4] = {0.f,0.f,0.f,0.f}, sA1[4] = {0.f,0.f,0.f,0.f};
            float sB0[4] = {0.f,0.f,0.f,0.f}, sB1[4] = {0.f,0.f,0.f,0.f};
            {
                int keyqA = npA * 16 + (grp >> 1) * 8 + (lane & 7);
                int keyqB = keyqA + 16;
                uint32_t kbA = (uint32_t)keyqA * 256u, rxA = (uint32_t)(keyqA & 7);
                uint32_t kbB = (uint32_t)keyqB * 256u, rxB = (uint32_t)(keyqB & 7);
#pragma unroll
                for (int kt = 0; kt < 8; kt++) {
                    uint32_t ck = (uint32_t)(kt * 2 + (grp & 1));
                    uint32_t bhA[4], bhB[4];
                    ldsm4(bhA, KB + kbA + ((ck ^ rxA) << 4));
                    ldsm4(bhB, KB + kbB + ((ck ^ rxB) << 4));
                    mma16816h(sA0, ah[kt], bhA[0], bhA[1]);
                    mma16816h(sB0, ah[kt], bhB[0], bhB[1]);
                    mma16816h(sA1, ah[kt], bhA[2], bhA[3]);
                    mma16816h(sB1, ah[kt], bhB[2], bhB[3]);
                }
            }
            // exp (batched for both np)
            float eaA0 = __expf(sA0[0] * SCALE_F - Ua);
            float eaA1 = __expf(sA0[1] * SCALE_F - Ua);
            float ebA0 = __expf(sA0[2] * SCALE_F - Ub);
            float ebA1 = __expf(sA0[3] * SCALE_F - Ub);
            float faA0 = __expf(sA1[0] * SCALE_F - Ua);
            float faA1 = __expf(sA1[1] * SCALE_F - Ua);
            float fbA0 = __expf(sA1[2] * SCALE_F - Ub);
            float fbA1 = __expf(sA1[3] * SCALE_F - Ub);
            float eaB0 = __expf(sB0[0] * SCALE_F - Ua);
            float eaB1 = __expf(sB0[1] * SCALE_F - Ua);
            float ebB0 = __expf(sB0[2] * SCALE_F - Ub);
            float ebB1 = __expf(sB0[3] * SCALE_F - Ub);
            float faB0 = __expf(sB1[0] * SCALE_F - Ua);
            float faB1 = __expf(sB1[1] * SCALE_F - Ua);
            float fbB0 = __expf(sB1[2] * SCALE_F - Ub);
            float fbB1 = __expf(sB1[3] * SCALE_F - Ub);

            uint32_t psA[4], pwA[4], psB[4], pwB[4];
            if (fast) {
                if (sel_w) {
                    float v0 = sa ? eaA0 : 0.f, v1 = sa ? eaA1 : 0.f;
                    float v2 = sb2 ? ebA0 : 0.f, v3 = sb2 ? ebA1 : 0.f;
                    float v4 = sa ? faA0 : 0.f, v5 = sa ? faA1 : 0.f;
                    float v6 = sb2 ? fbA0 : 0.f, v7 = sb2 ? fbA1 : 0.f;
                    float u0 = sa ? eaB0 : 0.f, u1 = sa ? eaB1 : 0.f;
                    float u2 = sb2 ? ebB0 : 0.f, u3 = sb2 ? ebB1 : 0.f;
                    float u4 = sa ? faB0 : 0.f, u5 = sa ? faB1 : 0.f;
                    float u6 = sb2 ? fbB0 : 0.f, u7 = sb2 ? fbB1 : 0.f;
                    sum_sa += v0 + v1 + v4 + v5 + u0 + u1 + u4 + u5;
                    sum_sb += v2 + v3 + v6 + v7 + u2 + u3 + u6 + u7;
                    psA[0] = packh2(v0, v1); psA[1] = packh2(v2, v3);
                    psA[2] = packh2(v4, v5); psA[3] = packh2(v6, v7);
                    psB[0] = packh2(u0, u1); psB[1] = packh2(u2, u3);
                    psB[2] = packh2(u4, u5); psB[3] = packh2(u6, u7);
                }
                if (win_w) {
                    sum_wa += eaA0 + eaA1 + faA0 + faA1 + eaB0 + eaB1 + faB0 + faB1;
                    sum_wb += ebA0 + ebA1 + fbA0 + fbA1 + ebB0 + ebB1 + fbB0 + fbB1;
                    pwA[0] = packh2(eaA0, eaA1); pwA[1] = packh2(ebA0, ebA1);
                    pwA[2] = packh2(faA0, faA1); pwA[3] = packh2(fbA0, fbA1);
                    pwB[0] = packh2(eaB0, eaB1); pwB[1] = packh2(ebB0, ebB1);
                    pwB[2] = packh2(faB0, faB1); pwB[3] = packh2(fbB0, fbB1);
                }
            } else {
                int j0A = b * 64 + npA * 16 + jcl;
                int j0B = j0A + 16;
                if (sel_w) {
                    float v0 = (sa  && j0A     <= t_a) ? eaA0 : 0.f;
                    float v1 = (sa  && j0A + 1 <= t_a) ? eaA1 : 0.f;
                    float v2 = (sb2 && j0A     <= t_b) ? ebA0 : 0.f;
                    float v3 = (sb2 && j0A + 1 <= t_b) ? ebA1 : 0.f;
                    float v4 = (sa  && j0A + 8 <= t_a) ? faA0 : 0.f;
                    float v5 = (sa  && j0A + 9 <= t_a) ? faA1 : 0.f;
                    float v6 = (sb2 && j0A + 8 <= t_b) ? fbA0 : 0.f;
                    float v7 = (sb2 && j0A + 9 <= t_b) ? fbA1 : 0.f;
                    float u0 = (sa  && j0B     <= t_a) ? eaB0 : 0.f;
                    float u1 = (sa  && j0B + 1 <= t_a) ? eaB1 : 0.f;
                    float u2 = (sb2 && j0B     <= t_b) ? ebB0 : 0.f;
                    float u3 = (sb2 && j0B + 1 <= t_b) ? ebB1 : 0.f;
                    float u4 = (sa  && j0B + 8 <= t_a) ? faB0 : 0.f;
                    float u5 = (sa  && j0B + 9 <= t_a) ? faB1 : 0.f;
                    float u6 = (sb2 && j0B + 8 <= t_b) ? fbB0 : 0.f;
                    float u7 = (sb2 && j0B + 9 <= t_b) ? fbB1 : 0.f;
                    sum_sa += v0 + v1 + v4 + v5 + u0 + u1 + u4 + u5;
                    sum_sb += v2 + v3 + v6 + v7 + u2 + u3 + u6 + u7;
                    psA[0] = packh2(v0, v1); psA[1] = packh2(v2, v3);
                    psA[2] = packh2(v4, v5); psA[3] = packh2(v6, v7);
                    psB[0] = packh2(u0, u1); psB[1] = packh2(u2, u3);
                    psB[2] = packh2(u4, u5); psB[3] = packh2(u6, u7);
                }
                if (win_w) {
                    float v0 = (j0A     <= t_a && t_a - j0A < 512)       ? eaA0 : 0.f;
                    float v1 = (j0A + 1 <= t_a && t_a - (j0A + 1) < 512) ? eaA1 : 0.f;
                    float v2 = (j0A     <= t_b && t_b - j0A < 512)       ? ebA0 : 0.f;
                    float v3 = (j0A + 1 <= t_b && t_b - (j0A + 1) < 512) ? ebA1 : 0.f;
                    float v4 = (j0A + 8 <= t_a && t_a - (j0A + 8) < 512) ? faA0 : 0.f;
                    float v5 = (j0A + 9 <= t_a && t_a - (j0A + 9) < 512) ? faA1 : 0.f;
                    float v6 = (j0A + 8 <= t_b && t_b - (j0A + 8) < 512) ? fbA0 : 0.f;
                    float v7 = (j0A + 9 <= t_b && t_b - (j0A + 9) < 512) ? fbA1 : 0.f;
                    float u0 = (j0B     <= t_a && t_a - j0B < 512)       ? eaB0 : 0.f;
                    float u1 = (j0B + 1 <= t_a && t_a - (j0B + 1) < 512) ? eaB1 : 0.f;
                    float u2 = (j0B     <= t_b && t_b - j0B < 512)       ? ebB0 : 0.f;
                    float u3 = (j0B + 1 <= t_b && t_b - (j0B + 1) < 512) ? ebB1 : 0.f;
                    float u4 = (j0B + 8 <= t_a && t_a - (j0B + 8) < 512) ? faB0 : 0.f;
                    float u5 = (j0B + 9 <= t_a && t_a - (j0B + 9) < 512) ? faB1 : 0.f;
                    float u6 = (j0B + 8 <= t_b && t_b - (j0B + 8) < 512) ? fbB0 : 0.f;
                    float u7 = (j0B + 9 <= t_b && t_b - (j0B + 9) < 512) ? fbB1 : 0.f;
                    sum_wa += v0 + v1 + v4 + v5 + u0 + u1 + u4 + u5;
                    sum_wb += v2 + v3 + v6 + v7 + u2 + u3 + u6 + u7;
                    pwA[0] = packh2(v0, v1); pwA[1] = packh2(v2, v3);
                    pwA[2] = packh2(v4, v5); pwA[3] = packh2(v6, v7);
                    pwB[0] = packh2(u0, u1); pwB[1] = packh2(u2, u3);
                    pwB[2] = packh2(u4, u5); pwB[3] = packh2(u6, u7);
                }
            }

            // PV for both np (interleaved)
            {
                int keyvA = npA * 16 + (grp & 1) * 8 + (lane & 7);
                int keyvB = keyvA + 16;
                uint32_t kbA = (uint32_t)keyvA * 256u, rxA = (uint32_t)(keyvA & 7);
                uint32_t kbB = (uint32_t)keyvB * 256u, rxB = (uint32_t)(keyvB & 7);
#pragma unroll
                for (int dp = 0; dp < 8; dp++) {
                    uint32_t c16 = (uint32_t)(dp * 2 + (grp >> 1));
                    uint32_t vA[4], vB[4];
                    ldsm4t(vA, KB + VHIO + kbA + ((c16 ^ rxA) << 4));
                    ldsm4t(vB, KB + VHIO + kbB + ((c16 ^ rxB) << 4));
                    if (sel_w) {
                        mma16816h(Os[2 * dp],     psA, vA[0], vA[1]);
                        mma16816h(Os[2 * dp + 1], psA, vA[2], vA[3]);
                        mma16816h(Os[2 * dp],     psB, vB[0], vB[1]);
                        mma16816h(Os[2 * dp + 1], psB, vB[2], vB[3]);
                    }
                    if (win_w) {
                        mma16816h(Ow[2 * dp],     pwA, vA[0], vA[1]);
                        mma16816h(Ow[2 * dp + 1], pwA, vA[2], vA[3]);
                        mma16816h(Ow[2 * dp],     pwB, vB[0], vB[1]);
                        mma16816h(Ow[2 * dp + 1], pwB, vB[2], vB[3]);
                    }
                }
            }
        }
    }

    // ---- epilogue ----
#pragma unroll
    for (int o = 1; o <= 2; o <<= 1) {
        sum_sa += __shfl_xor_sync(0xffffffffu, sum_sa, o);
        sum_sb += __shfl_xor_sync(0xffffffffu, sum_sb, o);
        sum_wa += __shfl_xor_sync(0xffffffffu, sum_wa, o);
        sum_wb += __shfl_xor_sync(0xffffffffu, sum_wb, o);
    }
    float inv_sa = 1.f / sum_sa, inv_sb = 1.f / sum_sb;
    float inv_wa = 1.f / sum_wa, inv_wb = 1.f / sum_wb;

    const float* wa = w + ((size_t)(t_a * H_HEADS + h)) * 3;
    const float* wb = w + ((size_t)(t_b * H_HEADS + h)) * 3;
    float w0a = wa[0], w1a = wa[1], w2a = wa[2];
    float w0b = wb[0], w1b = wb[1], w2b = wb[2];

#pragma unroll
    for (int nt = 0; nt < 16; nt++) {
        int d0 = nt * 8 + jcl;
        float oca0 = oc_sh[(nt * 4 + 0) * 256 + tid];
        float oca1 = oc_sh[(nt * 4 + 1) * 256 + tid];
        float ocb0 = oc_sh[(nt * 4 + 2) * 256 + tid];
        float ocb1 = oc_sh[(nt * 4 + 3) * 256 + tid];
        float2 oa, ob;
        oa.x = w0a * oca0 + w1a * Os[nt][0] * inv_sa + w2a * Ow[nt][0] * inv_wa;
        oa.y = w0a * oca1 + w1a * Os[nt][1] * inv_sa + w2a * Ow[nt][1] * inv_wa;
        ob.x = w0b * ocb0 + w1b * Os[nt][2] * inv_sb + w2b * Ow[nt][2] * inv_wb;
        ob.y = w0b * ocb1 + w1b * Os[nt][3] * inv_sb + w2b * Ow[nt][3] * inv_wb;
        *reinterpret_cast<float2*>(out + ((size_t)(t_a * H_HEADS + h)) * DDIM + d0) = oa;
        *reinterpret_cast<float2*>(out + ((size_t)(t_b * H_HEADS + h)) * DDIM + d0) = ob;
    }
}

// ---------------- launch ----------------
extern "C" void kernel_launch(void* const* d_in, const int* in_sizes, int n_in,
                              void* d_out, int out_size) {
    const float* q = (const float*)d_in[0];
    const float* k = (const float*)d_in[1];
    const float* v = (const float*)d_in[2];
    const float* w = (const float*)d_in[3];
    float* out = (float*)d_out;

    cudaFuncSetAttribute(k23_fused, cudaFuncAttributeMaxDynamicSharedMemorySize, SMTOT);

    k0_split<<<1024, 256>>>(q, k, v);
    k1_compress<<<dim3(NCMP, KHN), DDIM>>>(k, v);
    k1b_knorm<<<dim3(T_LEN, KHN), 32>>>(k);
    k23_fused<<<dim3(T_LEN / TQ * KHN, 1), 256, SMTOT>>>(q, w, out);
}

// round 14
// speedup vs baseline: 11.1967x; 1.0469x over previous
#include <cuda_runtime.h>
#include <cuda_fp16.h>
#include <math.h>
#include <stdint.h>

#define T_LEN 2048
#define H_HEADS 16
#define KHN 2
#define GQ 8
#define DDIM 128
#define NCMP 127
#define TQ 16
#define SCALE_F 0.08838834765f
#define EXP_SHIFT 10.3972077f   /* ln(2^15) */
#define NEG_INF (-INFINITY)

// ---------------- scratch ----------------
__device__ unsigned g_kmax[KHN];

__device__ __align__(16) __half g_qh16[T_LEN * H_HEADS * DDIM];
__device__ __align__(16) __half g_ql16[T_LEN * H_HEADS * DDIM];
__device__ __align__(16) __half g_kh16[KHN * T_LEN * DDIM];
__device__ __align__(16) __half g_vh16[KHN * T_LEN * DDIM];
__device__ __align__(16) __half g_ckhi[KHN][128][DDIM];
__device__ __align__(16) __half g_cklo[KHN][128][DDIM];
__device__ __align__(16) __half g_cvhi[KHN][128][DDIM];

// ---------------- helpers ----------------
__device__ __forceinline__ uint32_t smem_u32(const void* p) {
    uint32_t a;
    asm("{ .reg .u64 t; cvta.to.shared.u64 t, %1; cvt.u32.u64 %0, t; }" : "=r"(a) : "l"(p));
    return a;
}
__device__ __forceinline__ void mma16816h(float* d, const uint32_t* a, uint32_t b0, uint32_t b1) {
    asm volatile("mma.sync.aligned.m16n8k16.row.col.f32.f16.f16.f32 "
        "{%0,%1,%2,%3},{%4,%5,%6,%7},{%8,%9},{%0,%1,%2,%3};"
        : "+f"(d[0]), "+f"(d[1]), "+f"(d[2]), "+f"(d[3])
        : "r"(a[0]), "r"(a[1]), "r"(a[2]), "r"(a[3]), "r"(b0), "r"(b1));
}
__device__ __forceinline__ void ldsm4(uint32_t* r, uint32_t addr) {
    asm volatile("ldmatrix.sync.aligned.m8n8.x4.shared.b16 {%0,%1,%2,%3}, [%4];"
        : "=r"(r[0]), "=r"(r[1]), "=r"(r[2]), "=r"(r[3]) : "r"(addr));
}
__device__ __forceinline__ void ldsm4t(uint32_t* r, uint32_t addr) {
    asm volatile("ldmatrix.sync.aligned.m8n8.x4.trans.shared.b16 {%0,%1,%2,%3}, [%4];"
        : "=r"(r[0]), "=r"(r[1]), "=r"(r[2]), "=r"(r[3]) : "r"(addr));
}
__device__ __forceinline__ uint32_t packh2(float a, float b) {
    __half2 h = __floats2half2_rn(a, b);
    return *reinterpret_cast<uint32_t*>(&h);
}
#define CP_ASYNC16(dst, src) \
    asm volatile("cp.async.cg.shared.global [%0], [%1], 16;" :: "r"(dst), "l"(src) : "memory")
#define CP_COMMIT() asm volatile("cp.async.commit_group;" ::: "memory")
#define CP_WAIT0()  asm volatile("cp.async.wait_group 0;" ::: "memory")

// ---------------- K0: pre-split ----------------
__global__ void k0_split(const float* __restrict__ q, const float* __restrict__ k,
                         const float* __restrict__ v) {
    int stride = gridDim.x * blockDim.x;
    int idx = blockIdx.x * blockDim.x + threadIdx.x;
    const int n_kv = T_LEN * KHN * DDIM;
    for (int i = idx; i < n_kv; i += stride) {
        int d = i & (DDIM - 1);
        int tk = i >> 7;
        int kh = tk & 1, t = tk >> 1;
        int o = (kh * T_LEN + t) * DDIM + d;
        g_kh16[o] = __float2half_rn(k[i]);
        g_vh16[o] = __float2half_rn(v[i]);
    }
    const int n_q = T_LEN * H_HEADS * DDIM;
    for (int i = idx; i < n_q; i += stride) {
        float x = q[i];
        __half hh = __float2half_rn(x);
        g_qh16[i] = hh;
        g_ql16[i] = __float2half_rn(x - __half2float(hh));
    }
}

// ---------------- K1: compressed K/V ----------------
__global__ void k1_compress(const float* __restrict__ k, const float* __restrict__ v) {
    int j = blockIdx.x, kh = blockIdx.y, d = threadIdx.x;
    int s = j * 16;
    float sk = 0.f, sv = 0.f;
#pragma unroll 8
    for (int i = 0; i < 32; i++) {
        sk += k[((size_t)(s + i) * KHN + kh) * DDIM + d];
        sv += v[((size_t)(s + i) * KHN + kh) * DDIM + d];
    }
    float ck = sk * (1.f / 32.f), cv = sv * (1.f / 32.f);
    __half h = __float2half_rn(ck);
    g_ckhi[kh][j][d] = h;
    g_cklo[kh][j][d] = __float2half_rn(ck - __half2float(h));
    g_cvhi[kh][j][d] = __float2half_rn(cv);
}

// ---------------- K1b: max ||k_row|| ----------------
__global__ void k1b_knorm(const float* __restrict__ k) {
    int t = blockIdx.x, kh = blockIdx.y, lane = threadIdx.x;
    const float4* kr = reinterpret_cast<const float4*>(k) + ((size_t)t * KHN + kh) * 32;
    float4 a = kr[lane];
    float s = a.x * a.x + a.y * a.y + a.z * a.z + a.w * a.w;
    for (int o = 16; o; o >>= 1) s += __shfl_xor_sync(0xffffffffu, s, o);
    if (lane == 0) atomicMax(&g_kmax[kh], __float_as_uint(sqrtf(s)));
}

// ---------------- K23: fused ----------------
#define SQH   0
#define SQL   32768
#define SCKH  65536
#define SCKL  98304
#define SPS   131072
#define SOC   98304
#define SBUF  32768
#define BUFSZ 32768
#define VHIO  16384
#define SMTOT 163840

__global__ __launch_bounds__(256, 1) void k23_fused(
    const float* __restrict__ q, const float* __restrict__ w,
    float* __restrict__ out)
{
    extern __shared__ char smem[];
    uint32_t sb = smem_u32(smem);
    float* psum_sh = reinterpret_cast<float*>(smem + SPS);
    float* oc_sh = reinterpret_cast<float*>(smem + SOC);
    int tid = threadIdx.x;
    int wp = tid >> 5, lane = tid & 31;
    int ridx = (int)gridDim.x - 1 - (int)blockIdx.x;
    int tile = ridx >> 1;
    int kh = ridx & 1;
    int t0 = tile * TQ;
    int grp = lane >> 3;
    int jcl = (lane & 3) * 2;

    __shared__ int s_list[36];
    __shared__ int s_n;
    __shared__ unsigned s_union;

    int t_a = t0 + 2 * wp;
    int t_b = t_a + 1;
    int g = lane >> 2;
    int h = kh * GQ + g;

    if (tid == 0) s_union = 0u;

    // ---- stage QH/QL + CKH/CKL ----
    for (int i = tid; i < 128 * 16; i += 256) {
        int row = i >> 4, c16 = i & 15;
        uint32_t off = (uint32_t)row * 256u + (uint32_t)((c16 ^ (row & 7)) << 4);
        int qrow = (t0 + (row >> 3)) * H_HEADS + kh * GQ + (row & 7);
        CP_ASYNC16(sb + SQH + off, g_qh16 + (size_t)qrow * DDIM + c16 * 8);
        CP_ASYNC16(sb + SQL + off, g_ql16 + (size_t)qrow * DDIM + c16 * 8);
        CP_ASYNC16(sb + SCKH + off, &g_ckhi[kh][row][c16 * 8]);
        CP_ASYNC16(sb + SCKL + off, &g_cklo[kh][row][c16 * 8]);
    }
    CP_COMMIT();

    float kmaxv = __uint_as_float(g_kmax[kh]);
    float Ua, Ub;
    {
        const float4* q4 = reinterpret_cast<const float4*>(q);
        float s2 = 0.f;
        const float4* qr = q4 + ((size_t)(t_a * H_HEADS + h)) * 32;
#pragma unroll 8
        for (int d4 = 0; d4 < 32; d4++) { float4 a = qr[d4]; s2 += a.x*a.x + a.y*a.y + a.z*a.z + a.w*a.w; }
        Ua = SCALE_F * sqrtf(s2) * kmaxv - EXP_SHIFT;
        s2 = 0.f;
        qr = q4 + ((size_t)(t_b * H_HEADS + h)) * 32;
#pragma unroll 8
        for (int d4 = 0; d4 < 32; d4++) { float4 a = qr[d4]; s2 += a.x*a.x + a.y*a.y + a.z*a.z + a.w*a.w; }
        Ub = SCALE_F * sqrtf(s2) * kmaxv - EXP_SHIFT;
    }

    CP_WAIT0();
    __syncthreads();

    int nva = (t_a >= 31) ? ((t_a - 31) / 16 + 1) : 0;
    int nvb = (t_b >= 31) ? ((t_b - 31) / 16 + 1) : 0;   // nvb >= nva; per-warp uniform bound

    // ---- Q-hi fragments (both phases) ----
    uint32_t ah[8][4];
    {
        int row = 16 * wp + (grp & 1) * 8 + (lane & 7);
        uint32_t rb = (uint32_t)row * 256u, rx = (uint32_t)(row & 7);
#pragma unroll
        for (int kt = 0; kt < 8; kt++) {
            uint32_t cq = (uint32_t)(kt * 2 + (grp >> 1));
            ldsm4(ah[kt], sb + SQH + rb + ((cq ^ rx) << 4));
        }
    }

    unsigned selm_a, selm_b;
    const __half* khbase = g_kh16 + (size_t)kh * T_LEN * DDIM;
    const __half* vhbase = g_vh16 + (size_t)kh * T_LEN * DDIM;

    // ================= PHASE 1 =================
    {
        float s[16][4];
#pragma unroll
        for (int i = 0; i < 16; i++)
#pragma unroll
            for (int c = 0; c < 4; c++) s[i][c] = 0.f;

        // QK — only 16-col tiles containing valid windows (masked cols stay 0 -> exact)
#pragma unroll
        for (int np = 0; np < 8; np++) {
            if (np * 16 < nvb) {
                int keyq = np * 16 + (grp >> 1) * 8 + (lane & 7);
                uint32_t kb = (uint32_t)keyq * 256u, rxk = (uint32_t)(keyq & 7);
                int rowq = 16 * wp + (grp & 1) * 8 + (lane & 7);
                uint32_t rq = (uint32_t)rowq * 256u, rxq = (uint32_t)(rowq & 7);
#pragma unroll
                for (int kt = 0; kt < 8; kt++) {
                    uint32_t ck = (uint32_t)(kt * 2 + (grp & 1));
                    uint32_t bo = kb + ((ck ^ rxk) << 4);
                    uint32_t cq = (uint32_t)(kt * 2 + (grp >> 1));
                    uint32_t bh[4], bl[4], al[4];
                    ldsm4(bh, sb + SCKH + bo);
                    ldsm4(bl, sb + SCKL + bo);
                    ldsm4(al, sb + SQL + rq + ((cq ^ rxq) << 4));
                    mma16816h(s[2*np],   ah[kt], bh[0], bh[1]);
                    mma16816h(s[2*np+1], ah[kt], bh[2], bh[3]);
                    mma16816h(s[2*np],   ah[kt], bl[0], bl[1]);
                    mma16816h(s[2*np+1], ah[kt], bl[2], bl[3]);
                    mma16816h(s[2*np],   al,     bh[0], bh[1]);
                    mma16816h(s[2*np+1], al,     bh[2], bh[3]);
                }
            }
        }
        __syncthreads();   // QL/CKH/CKL reads done

        // stage cmp_v-hi + chunk-0 K/V (block 0 ALWAYS selected)
        for (int i = tid; i < 128 * 16; i += 256) {
            int row = i >> 4, c16 = i & 15;
            uint32_t off = (uint32_t)row * 256u + (uint32_t)((c16 ^ (row & 7)) << 4);
            CP_ASYNC16(sb + SCKH + off, &g_cvhi[kh][row][c16 * 8]);
        }
        for (int i = tid; i < 1024; i += 256) {
            int row = i >> 4, c16 = i & 15;
            size_t src = (size_t)row * DDIM + c16 * 8;
            uint32_t dst = sb + SBUF + ((uint32_t)row * 256u + (uint32_t)((c16 ^ (row & 7)) << 4));
            CP_ASYNC16(dst, khbase + src);
            CP_ASYNC16(dst + VHIO, vhbase + src);
        }
        CP_COMMIT();

        // softmax — SAME tile granularity as QK/pack: (nt>>1)*16 < nvb
        float ma = NEG_INF, mb = NEG_INF;
#pragma unroll
        for (int nt = 0; nt < 16; nt++) {
            if ((nt >> 1) * 16 < nvb) {
                int j0 = nt * 8 + jcl;
                if (j0 < nva)     ma = fmaxf(ma, s[nt][0] * SCALE_F);
                if (j0 + 1 < nva) ma = fmaxf(ma, s[nt][1] * SCALE_F);
                if (j0 < nvb)     mb = fmaxf(mb, s[nt][2] * SCALE_F);
                if (j0 + 1 < nvb) mb = fmaxf(mb, s[nt][3] * SCALE_F);
            }
        }
#pragma unroll
        for (int o = 1; o <= 2; o <<= 1) {
            ma = fmaxf(ma, __shfl_xor_sync(0xffffffffu, ma, o));
            mb = fmaxf(mb, __shfl_xor_sync(0xffffffffu, mb, o));
        }
        float la = 0.f, lb = 0.f;
#pragma unroll
        for (int nt = 0; nt < 16; nt++) {
            if ((nt >> 1) * 16 < nvb) {
                int j0 = nt * 8 + jcl;
                float e0 = (j0 < nva)     ? __expf(s[nt][0] * SCALE_F - ma) : 0.f;
                float e1 = (j0 + 1 < nva) ? __expf(s[nt][1] * SCALE_F - ma) : 0.f;
                float e2 = (j0 < nvb)     ? __expf(s[nt][2] * SCALE_F - mb) : 0.f;
                float e3 = (j0 + 1 < nvb) ? __expf(s[nt][3] * SCALE_F - mb) : 0.f;
                s[nt][0] = e0; s[nt][1] = e1; s[nt][2] = e2; s[nt][3] = e3;
                la += e0 + e1; lb += e2 + e3;
            }
        }
#pragma unroll
        for (int o = 1; o <= 2; o <<= 1) {
            la += __shfl_xor_sync(0xffffffffu, la, o);
            lb += __shfl_xor_sync(0xffffffffu, lb, o);
        }
        float inva = (nva > 0) ? 1.f / la : 0.f;
        float invb = (nvb > 0) ? 1.f / lb : 0.f;
#pragma unroll
        for (int nt = 0; nt < 16; nt++) {
            if ((nt >> 1) * 16 < nvb) {
                s[nt][0] *= inva; s[nt][1] *= inva;
                s[nt][2] *= invb; s[nt][3] *= invb;
            }
        }

        // psum — same tile granularity (covers every j < nvb the selection can read)
#pragma unroll
        for (int nt = 0; nt < 16; nt++) {
            if ((nt >> 1) * 16 < nvb) {
                float a0 = s[nt][0], a1 = s[nt][1], b0 = s[nt][2], b1 = s[nt][3];
#pragma unroll
                for (int o = 4; o <= 16; o <<= 1) {
                    a0 += __shfl_xor_sync(0xffffffffu, a0, o);
                    a1 += __shfl_xor_sync(0xffffffffu, a1, o);
                    b0 += __shfl_xor_sync(0xffffffffu, b0, o);
                    b1 += __shfl_xor_sync(0xffffffffu, b1, o);
                }
                if (lane < 4) {
                    int j = nt * 8 + lane * 2;
                    psum_sh[(2 * wp) * 128 + j] = a0;
                    psum_sh[(2 * wp) * 128 + j + 1] = a1;
                    psum_sh[(2 * wp + 1) * 128 + j] = b0;
                    psum_sh[(2 * wp + 1) * 128 + j + 1] = b1;
                }
            }
        }
        __syncthreads();

        unsigned selres[2];
#pragma unroll
        for (int rep = 0; rep < 2; rep++) {
            int t = t0 + 2 * wp + rep;
            int qi = 2 * wp + rep;
            int nv = (t >= 31) ? ((t - 31) / 16 + 1) : 0;
            int b = lane;
            int tb = t >> 6;
            bool forced = (b < 1) || ((b <= tb) && (b >= tb - 1));
            bool valid = (b * 64 <= t);
            float sc;
            if (!valid) sc = -1e30f;
            else if (forced) sc = 1e30f;
            else {
                int jlo = 4 * b - 1; if (jlo < 0) jlo = 0;
                int jhi = 4 * b + 3; if (jhi > nv - 1) jhi = nv - 1;
                float ss = 0.f;
                for (int j = jlo; j <= jhi; j++) ss += psum_sh[qi * 128 + j];
                sc = ss;
            }
            unsigned u = __float_as_uint(sc);
            u = ((int)u < 0) ? ~u : (u | 0x80000000u);
            unsigned sel = 0u;
            for (int it = 0; it < 16; it++) {
                unsigned cur = ((sel >> b) & 1u) ? 0u : u;
                unsigned m = __reduce_max_sync(0xffffffffu, cur);
                unsigned ball = __ballot_sync(0xffffffffu, cur == m);
                sel |= (1u << (__ffs(ball) - 1));
            }
            selres[rep] = sel;
        }
        selm_a = selres[0];
        selm_b = selres[1];
        if (lane == 0) atomicOr(&s_union, selm_a | selm_b);

        uint32_t ph[8][4];
#pragma unroll
        for (int kp = 0; kp < 8; kp++) {
            if (kp * 16 < nvb) {
                ph[kp][0] = packh2(s[2*kp][0],   s[2*kp][1]);
                ph[kp][1] = packh2(s[2*kp][2],   s[2*kp][3]);
                ph[kp][2] = packh2(s[2*kp+1][0], s[2*kp+1][1]);
                ph[kp][3] = packh2(s[2*kp+1][2], s[2*kp+1][3]);
            }
        }

        CP_WAIT0();
        __syncthreads();

        float Oc[16][4];
#pragma unroll
        for (int i = 0; i < 16; i++)
#pragma unroll
            for (int c = 0; c < 4; c++) Oc[i][c] = 0.f;
#pragma unroll
        for (int kp = 0; kp < 8; kp++) {
            if (kp * 16 < nvb) {
                int keyv = kp * 16 + (grp & 1) * 8 + (lane & 7);
                uint32_t kb = (uint32_t)keyv * 256u, rxv = (uint32_t)(keyv & 7);
#pragma unroll
                for (int dp = 0; dp < 8; dp++) {
                    uint32_t c16 = (uint32_t)(dp * 2 + (grp >> 1));
                    uint32_t off = kb + ((c16 ^ rxv) << 4);
                    uint32_t vh[4];
                    ldsm4t(vh, sb + SCKH + off);
                    mma16816h(Oc[2*dp],   ph[kp], vh[0], vh[1]);
                    mma16816h(Oc[2*dp+1], ph[kp], vh[2], vh[3]);
                }
            }
        }
        __syncthreads();

#pragma unroll
        for (int nt = 0; nt < 16; nt++)
#pragma unroll
            for (int c = 0; c < 4; c++)
                oc_sh[(nt * 4 + c) * 256 + tid] = Oc[nt][c];
    }

    // ================= PHASE 2 =================
    __syncthreads();
    unsigned selu = s_union;
    int t_blk = t0 >> 6;

    if (tid == 0) {
        int n = 0;
        for (int b = 0; b <= t_blk; b++) {
            bool need = ((selu >> b) & 1u) || (b * 64 + 63 >= t0 - 511);
            if (need) s_list[n++] = b;
        }
        s_n = n;
    }
    __syncthreads();
    int nch = s_n;

    float Os[16][4], Ow[16][4];
#pragma unroll
    for (int i = 0; i < 16; i++)
#pragma unroll
        for (int c = 0; c < 4; c++) { Os[i][c] = 0.f; Ow[i][c] = 0.f; }
    float sum_sa = 0.f, sum_sb = 0.f, sum_wa = 0.f, sum_wb = 0.f;
    unsigned selw = selm_a | selm_b;

    for (int ci = 0; ci < nch; ci++) {
        int b = s_list[ci];
        uint32_t KB = sb + SBUF + (uint32_t)(ci & 1) * BUFSZ;

        if (ci > 0) {
            CP_WAIT0();
            __syncthreads();
        }
        if (ci + 1 < nch) {
            int bn = s_list[ci + 1];
            uint32_t NB = sb + SBUF + (uint32_t)((ci + 1) & 1) * BUFSZ;
            for (int i = tid; i < 1024; i += 256) {
                int row = i >> 4, c16 = i & 15;
                size_t src = (size_t)(bn * 64 + row) * DDIM + c16 * 8;
                uint32_t dst = NB + ((uint32_t)row * 256u + (uint32_t)((c16 ^ (row & 7)) << 4));
                CP_ASYNC16(dst, khbase + src);
                CP_ASYNC16(dst + VHIO, vhbase + src);
            }
            CP_COMMIT();
        }

        bool sel_w = (selw >> b) & 1u;
        bool win_w = (b * 64 + 63 >= t_a - 511);
        if (!sel_w && !win_w) continue;
        bool sa = (selm_a >> b) & 1u, sb2 = (selm_b >> b) & 1u;
        bool needs_causal = (b == t_blk);
        bool needs_wm = win_w && (b * 64 < t_b - 511);
        bool fast = !needs_causal && !needs_wm;

#pragma unroll
        for (int npp = 0; npp < 2; npp++) {
            int npA = npp * 2;
            float sA0[4] = {0.f,0.f,0.f,0.f}, sA1[4] = {0.f,0.f,0.f,0.f};
            float sB0[4] = {0.f,0.f,0.f,0.f}, sB1[4] = {0.f,0.f,0.f,0.f};
            {
                int keyqA = npA * 16 + (grp >> 1) * 8 + (lane & 7);
                int keyqB = keyqA + 16;
                uint32_t kbA = (uint32_t)keyqA * 256u, rxA = (uint32_t)(keyqA & 7);
                uint32_t kbB = (uint32_t)keyqB * 256u, rxB = (uint32_t)(keyqB & 7);
#pragma unroll
                for (int kt = 0; kt < 8; kt++) {
                    uint32_t ck = (uint32_t)(kt * 2 + (grp & 1));
                    uint32_t bhA[4], bhB[4];
                    ldsm4(bhA, KB + kbA + ((ck ^ rxA) << 4));
                    ldsm4(bhB, KB + kbB + ((ck ^ rxB) << 4));
                    mma16816h(sA0, ah[kt], bhA[0], bhA[1]);
                    mma16816h(sB0, ah[kt], bhB[0], bhB[1]);
                    mma16816h(sA1, ah[kt], bhA[2], bhA[3]);
                    mma16816h(sB1, ah[kt], bhB[2], bhB[3]);
                }
            }
            float eaA0 = __expf(sA0[0] * SCALE_F - Ua);
            float eaA1 = __expf(sA0[1] * SCALE_F - Ua);
            float ebA0 = __expf(sA0[2] * SCALE_F - Ub);
            float ebA1 = __expf(sA0[3] * SCALE_F - Ub);
            float faA0 = __expf(sA1[0] * SCALE_F - Ua);
            float faA1 = __expf(sA1[1] * SCALE_F - Ua);
            float fbA0 = __expf(sA1[2] * SCALE_F - Ub);
            float fbA1 = __expf(sA1[3] * SCALE_F - Ub);
            float eaB0 = __expf(sB0[0] * SCALE_F - Ua);
            float eaB1 = __expf(sB0[1] * SCALE_F - Ua);
            float ebB0 = __expf(sB0[2] * SCALE_F - Ub);
            float ebB1 = __expf(sB0[3] * SCALE_F - Ub);
            float faB0 = __expf(sB1[0] * SCALE_F - Ua);
            float faB1 = __expf(sB1[1] * SCALE_F - Ua);
            float fbB0 = __expf(sB1[2] * SCALE_F - Ub);
            float fbB1 = __expf(sB1[3] * SCALE_F - Ub);

            uint32_t psA[4], pwA[4], psB[4], pwB[4];
            if (fast) {
                if (sel_w) {
                    float v0 = sa ? eaA0 : 0.f, v1 = sa ? eaA1 : 0.f;
                    float v2 = sb2 ? ebA0 : 0.f, v3 = sb2 ? ebA1 : 0.f;
                    float v4 = sa ? faA0 : 0.f, v5 = sa ? faA1 : 0.f;
                    float v6 = sb2 ? fbA0 : 0.f, v7 = sb2 ? fbA1 : 0.f;
                    float u0 = sa ? eaB0 : 0.f, u1 = sa ? eaB1 : 0.f;
                    float u2 = sb2 ? ebB0 : 0.f, u3 = sb2 ? ebB1 : 0.f;
                    float u4 = sa ? faB0 : 0.f, u5 = sa ? faB1 : 0.f;
                    float u6 = sb2 ? fbB0 : 0.f, u7 = sb2 ? fbB1 : 0.f;
                    sum_sa += v0 + v1 + v4 + v5 + u0 + u1 + u4 + u5;
                    sum_sb += v2 + v3 + v6 + v7 + u2 + u3 + u6 + u7;
                    psA[0] = packh2(v0, v1); psA[1] = packh2(v2, v3);
                    psA[2] = packh2(v4, v5); psA[3] = packh2(v6, v7);
                    psB[0] = packh2(u0, u1); psB[1] = packh2(u2, u3);
                    psB[2] = packh2(u4, u5); psB[3] = packh2(u6, u7);
                }
                if (win_w) {
                    sum_wa += eaA0 + eaA1 + faA0 + faA1 + eaB0 + eaB1 + faB0 + faB1;
                    sum_wb += ebA0 + ebA1 + fbA0 + fbA1 + ebB0 + ebB1 + fbB0 + fbB1;
                    pwA[0] = packh2(eaA0, eaA1); pwA[1] = packh2(ebA0, ebA1);
                    pwA[2] = packh2(faA0, faA1); pwA[3] = packh2(fbA0, fbA1);
                    pwB[0] = packh2(eaB0, eaB1); pwB[1] = packh2(ebB0, ebB1);
                    pwB[2] = packh2(faB0, faB1); pwB[3] = packh2(fbB0, fbB1);
                }
            } else {
                int j0A = b * 64 + npA * 16 + jcl;
                int j0B = j0A + 16;
                if (sel_w) {
                    float v0 = (sa  && j0A     <= t_a) ? eaA0 : 0.f;
                    float v1 = (sa  && j0A + 1 <= t_a) ? eaA1 : 0.f;
                    float v2 = (sb2 && j0A     <= t_b) ? ebA0 : 0.f;
                    float v3 = (sb2 && j0A + 1 <= t_b) ? ebA1 : 0.f;
                    float v4 = (sa  && j0A + 8 <= t_a) ? faA0 : 0.f;
                    float v5 = (sa  && j0A + 9 <= t_a) ? faA1 : 0.f;
                    float v6 = (sb2 && j0A + 8 <= t_b) ? fbA0 : 0.f;
                    float v7 = (sb2 && j0A + 9 <= t_b) ? fbA1 : 0.f;
                    float u0 = (sa  && j0B     <= t_a) ? eaB0 : 0.f;
                    float u1 = (sa  && j0B + 1 <= t_a) ? eaB1 : 0.f;
                    float u2 = (sb2 && j0B     <= t_b) ? ebB0 : 0.f;
                    float u3 = (sb2 && j0B + 1 <= t_b) ? ebB1 : 0.f;
                    float u4 = (sa  && j0B + 8 <= t_a) ? faB0 : 0.f;
                    float u5 = (sa  && j0B + 9 <= t_a) ? faB1 : 0.f;
                    float u6 = (sb2 && j0B + 8 <= t_b) ? fbB0 : 0.f;
                    float u7 = (sb2 && j0B + 9 <= t_b) ? fbB1 : 0.f;
                    sum_sa += v0 + v1 + v4 + v5 + u0 + u1 + u4 + u5;
                    sum_sb += v2 + v3 + v6 + v7 + u2 + u3 + u6 + u7;
                    psA[0] = packh2(v0, v1); psA[1] = packh2(v2, v3);
                    psA[2] = packh2(v4, v5); psA[3] = packh2(v6, v7);
                    psB[0] = packh2(u0, u1); psB[1] = packh2(u2, u3);
                    psB[2] = packh2(u4, u5); psB[3] = packh2(u6, u7);
                }
                if (win_w) {
                    float v0 = (j0A     <= t_a && t_a - j0A < 512)       ? eaA0 : 0.f;
                    float v1 = (j0A + 1 <= t_a && t_a - (j0A + 1) < 512) ? eaA1 : 0.f;
                    float v2 = (j0A     <= t_b && t_b - j0A < 512)       ? ebA0 : 0.f;
                    float v3 = (j0A + 1 <= t_b && t_b - (j0A + 1) < 512) ? ebA1 : 0.f;
                    float v4 = (j0A + 8 <= t_a && t_a - (j0A + 8) < 512) ? faA0 : 0.f;
                    float v5 = (j0A + 9 <= t_a && t_a - (j0A + 9) < 512) ? faA1 : 0.f;
                    float v6 = (j0A + 8 <= t_b && t_b - (j0A + 8) < 512) ? fbA0 : 0.f;
                    float v7 = (j0A + 9 <= t_b && t_b - (j0A + 9) < 512) ? fbA1 : 0.f;
                    float u0 = (j0B     <= t_a && t_a - j0B < 512)       ? eaB0 : 0.f;
                    float u1 = (j0B + 1 <= t_a && t_a - (j0B + 1) < 512) ? eaB1 : 0.f;
                    float u2 = (j0B     <= t_b && t_b - j0B < 512)       ? ebB0 : 0.f;
                    float u3 = (j0B + 1 <= t_b && t_b - (j0B + 1) < 512) ? ebB1 : 0.f;
                    float u4 = (j0B + 8 <= t_a && t_a - (j0B + 8) < 512) ? faB0 : 0.f;
                    float u5 = (j0B + 9 <= t_a && t_a - (j0B + 9) < 512) ? faB1 : 0.f;
                    float u6 = (j0B + 8 <= t_b && t_b - (j0B + 8) < 512) ? fbB0 : 0.f;
                    float u7 = (j0B + 9 <= t_b && t_b - (j0B + 9) < 512) ? fbB1 : 0.f;
                    sum_wa += v0 + v1 + v4 + v5 + u0 + u1 + u4 + u5;
                    sum_wb += v2 + v3 + v6 + v7 + u2 + u3 + u6 + u7;
                    pwA[0] = packh2(v0, v1); pwA[1] = packh2(v2, v3);
                    pwA[2] = packh2(v4, v5); pwA[3] = packh2(v6, v7);
                    pwB[0] = packh2(u0, u1); pwB[1] = packh2(u2, u3);
                    pwB[2] = packh2(u4, u5); pwB[3] = packh2(u6, u7);
                }
            }

            {
                int keyvA = npA * 16 + (grp & 1) * 8 + (lane & 7);
                int keyvB = keyvA + 16;
                uint32_t kbA = (uint32_t)keyvA * 256u, rxA = (uint32_t)(keyvA & 7);
                uint32_t kbB = (uint32_t)keyvB * 256u, rxB = (uint32_t)(keyvB & 7);
#pragma unroll
                for (int dp = 0; dp < 8; dp++) {
                    uint32_t c16 = (uint32_t)(dp * 2 + (grp >> 1));
                    uint32_t vA[4], vB[4];
                    ldsm4t(vA, KB + VHIO + kbA + ((c16 ^ rxA) << 4));
                    ldsm4t(vB, KB + VHIO + kbB + ((c16 ^ rxB) << 4));
                    if (sel_w) {
                        mma16816h(Os[2 * dp],     psA, vA[0], vA[1]);
                        mma16816h(Os[2 * dp + 1], psA, vA[2], vA[3]);
                        mma16816h(Os[2 * dp],     psB, vB[0], vB[1]);
                        mma16816h(Os[2 * dp + 1], psB, vB[2], vB[3]);
                    }
                    if (win_w) {
                        mma16816h(Ow[2 * dp],     pwA, vA[0], vA[1]);
                        mma16816h(Ow[2 * dp + 1], pwA, vA[2], vA[3]);
                        mma16816h(Ow[2 * dp],     pwB, vB[0], vB[1]);
                        mma16816h(Ow[2 * dp + 1], pwB, vB[2], vB[3]);
                    }
                }
            }
        }
    }

    // ---- epilogue ----
#pragma unroll
    for (int o = 1; o <= 2; o <<= 1) {
        sum_sa += __shfl_xor_sync(0xffffffffu, sum_sa, o);
        sum_sb += __shfl_xor_sync(0xffffffffu, sum_sb, o);
        sum_wa += __shfl_xor_sync(0xffffffffu, sum_wa, o);
        sum_wb += __shfl_xor_sync(0xffffffffu, sum_wb, o);
    }
    float inv_sa = 1.f / sum_sa, inv_sb = 1.f / sum_sb;
    float inv_wa = 1.f / sum_wa, inv_wb = 1.f / sum_wb;

    const float* wa = w + ((size_t)(t_a * H_HEADS + h)) * 3;
    const float* wb = w + ((size_t)(t_b * H_HEADS + h)) * 3;
    float w0a = wa[0], w1a = wa[1], w2a = wa[2];
    float w0b = wb[0], w1b = wb[1], w2b = wb[2];

#pragma unroll
    for (int nt = 0; nt < 16; nt++) {
        int d0 = nt * 8 + jcl;
        float oca0 = oc_sh[(nt * 4 + 0) * 256 + tid];
        float oca1 = oc_sh[(nt * 4 + 1) * 256 + tid];
        float ocb0 = oc_sh[(nt * 4 + 2) * 256 + tid];
        float ocb1 = oc_sh[(nt * 4 + 3) * 256 + tid];
        float2 oa, ob;
        oa.x = w0a * oca0 + w1a * Os[nt][0] * inv_sa + w2a * Ow[nt][0] * inv_wa;
        oa.y = w0a * oca1 + w1a * Os[nt][1] * inv_sa + w2a * Ow[nt][1] * inv_wa;
        ob.x = w0b * ocb0 + w1b * Os[nt][2] * inv_sb + w2b * Ow[nt][2] * inv_wb;
        ob.y = w0b * ocb1 + w1b * Os[nt][3] * inv_sb + w2b * Ow[nt][3] * inv_wb;
        *reinterpret_cast<float2*>(out + ((size_t)(t_a * H_HEADS + h)) * DDIM + d0) = oa;
        *reinterpret_cast<float2*>(out + ((size_t)(t_b * H_HEADS + h)) * DDIM + d0) = ob;
    }
}

// ---------------- launch ----------------
extern "C" void kernel_launch(void* const* d_in, const int* in_sizes, int n_in,
                              void* d_out, int out_size) {
    const float* q = (const float*)d_in[0];
    const float* k = (const float*)d_in[1];
    const float* v = (const float*)d_in[2];
    const float* w = (const float*)d_in[3];
    float* out = (float*)d_out;

    cudaFuncSetAttribute(k23_fused, cudaFuncAttributeMaxDynamicSharedMemorySize, SMTOT);

    k0_split<<<1024, 256>>>(q, k, v);
    k1_compress<<<dim3(NCMP, KHN), DDIM>>>(k, v);
    k1b_knorm<<<dim3(T_LEN, KHN), 32>>>(k);
    k23_fused<<<dim3(T_LEN / TQ * KHN, 1), 256, SMTOT>>>(q, w, out);
}